// round 1
// baseline (speedup 1.0000x reference)
#include <cuda_runtime.h>
#include <math.h>

#define RESO 128
#define NS 8
#define MPTS 65536
#define ZD 64
#define TD 32

// ---------------- scratch (device globals; no allocation allowed) ----------
__device__ float g_fmap[NS * ZD * RESO * RESO];   // 33.5 MB (reused as h2)
__device__ float g_h1[NS * ZD * RESO * RESO];     // 33.5 MB
__device__ float g_tri[(size_t)NS * 3 * RESO * RESO * TD]; // 50.3 MB, channel-last
__device__ float g_zb[NS * ZD];
__device__ float g_A[ZD];
__device__ float g_B[ZD];

// ---------------- prep: z = z_slots + slot_pos[:, :2]@pos_w + pos_b (+pe_b) -
__global__ void prep_kernel(const float* __restrict__ zs, const float* __restrict__ sp,
                            const float* __restrict__ pw, const float* __restrict__ pb,
                            const float* __restrict__ pew, const float* __restrict__ peb) {
    int c = threadIdx.x;
    if (c < ZD) {
        g_A[c] = pew[0 * ZD + c] - pew[2 * ZD + c];
        g_B[c] = pew[1 * ZD + c] - pew[3 * ZD + c];
        for (int n = 0; n < NS; n++) {
            g_zb[n * ZD + c] = zs[n * ZD + c]
                + sp[n * 3 + 0] * pw[0 * ZD + c]
                + sp[n * 3 + 1] * pw[1 * ZD + c]
                + pb[c] + peb[c];
        }
    }
}

// ---------------- fmap: analytic (linear in x,y) ---------------------------
__global__ void fmap_kernel() {
    int idx = blockIdx.x * blockDim.x + threadIdx.x;
    if (idx >= NS * ZD * RESO * RESO) return;
    int x = idx & 127;
    int y = (idx >> 7) & 127;
    int c = (idx >> 14) & 63;
    int n = idx >> 20;
    float xx = -1.f + (2 * x + 1) * (1.f / RESO);
    float yy = -1.f + (2 * y + 1) * (1.f / RESO);
    g_fmap[idx] = g_zb[n * ZD + c] + g_A[c] * xx + g_B[c] * yy;
}

// ---------------- direct tiled 3x3 conv ------------------------------------
// Block: 32x8 pixel tile, 16 output channels. 256 threads.
// Thread: 4 pixels (x) x 4 oc register micro-tile.
template <int IC, int OCG, bool RELU, bool SAMPLE_OUT>
__global__ __launch_bounds__(256) void conv_kernel(const float* __restrict__ in,
                                                   const float* __restrict__ wt,
                                                   const float* __restrict__ bias,
                                                   float* __restrict__ out) {
    const int TW = 32, TH = 8, OCB = 16, ICB = 16;
    __shared__ float s_in[ICB][TH + 2][35];  // stride 35 -> conflict-free
    __shared__ float s_w[OCB][ICB][9];

    int x0 = blockIdx.x * TW;
    int y0 = blockIdx.y * TH;
    int n = blockIdx.z / OCG;
    int oc0 = (blockIdx.z % OCG) * OCB;
    int tid = threadIdx.x;
    int ocq = tid >> 6;        // 0..3
    int pxg = tid & 63;
    int xg = pxg & 7;          // x-group (4 px each)
    int yy = pxg >> 3;         // row in tile

    float acc[4][4];
#pragma unroll
    for (int j = 0; j < 4; j++)
#pragma unroll
        for (int px = 0; px < 4; px++) acc[j][px] = 0.f;

    for (int ic0 = 0; ic0 < IC; ic0 += ICB) {
        // stage input tile with halo
        for (int idx = tid; idx < ICB * (TH + 2) * 34; idx += 256) {
            int ici = idx / 340;
            int r = idx % 340;
            int ry = r / 34, rx = r % 34;
            int gy = y0 + ry - 1, gx = x0 + rx - 1;
            float v = 0.f;
            if (gy >= 0 && gy < RESO && gx >= 0 && gx < RESO)
                v = in[(((size_t)n * IC + ic0 + ici) * RESO + gy) * RESO + gx];
            s_in[ici][ry][rx] = v;
        }
        // stage weights
        for (int idx = tid; idx < OCB * ICB * 9; idx += 256) {
            int oci = idx / (ICB * 9);
            int r = idx % (ICB * 9);
            int ici = r / 9, t = r % 9;
            s_w[oci][ici][t] = wt[((size_t)(oc0 + oci) * IC + ic0 + ici) * 9 + t];
        }
        __syncthreads();

#pragma unroll 1
        for (int ici = 0; ici < ICB; ici++) {
            float v[3][6];
#pragma unroll
            for (int dy = 0; dy < 3; dy++)
#pragma unroll
                for (int dx = 0; dx < 6; dx++)
                    v[dy][dx] = s_in[ici][yy + dy][4 * xg + dx];
#pragma unroll
            for (int j = 0; j < 4; j++) {
#pragma unroll
                for (int ky = 0; ky < 3; ky++)
#pragma unroll
                    for (int kx = 0; kx < 3; kx++) {
                        float wv = s_w[ocq * 4 + j][ici][ky * 3 + kx];
#pragma unroll
                        for (int px = 0; px < 4; px++)
                            acc[j][px] += wv * v[ky][px + kx];
                    }
            }
        }
        __syncthreads();
    }

    int y = y0 + yy;
#pragma unroll
    for (int j = 0; j < 4; j++) {
        int oc = oc0 + ocq * 4 + j;
        float b = bias[oc];
#pragma unroll
        for (int px = 0; px < 4; px++) {
            float val = acc[j][px] + b;
            if (RELU) val = fmaxf(val, 0.f);
            int x = x0 + 4 * xg + px;
            if (SAMPLE_OUT) {
                int plane = oc >> 5, c = oc & 31;
                out[((((size_t)n * 3 + plane) * RESO + y) * RESO + x) * TD + c] = val;
            } else {
                out[(((size_t)n * (OCG * 16) + oc) * RESO + y) * RESO + x] = val;
            }
        }
    }
}

// ---------------- fused sample + decoder MLP -------------------------------
#define PTS 128
#define ASTRIDE 100
// smem layout (floats)
#define OFF_W0   0
#define OFF_W1   9216
#define OFF_CW0  18432
#define OFF_B0   20736
#define OFF_B1   20832
#define OFF_DW   20928
#define OFF_CB0  21024
#define OFF_CW1  21048
#define OFF_CB1  21120
#define OFF_DB   21123
#define OFF_ACTA 21124
#define OFF_ACTB (21124 + PTS * ASTRIDE)
#define OFF_FLAG (OFF_ACTB + PTS * ASTRIDE)
#define SMEM_FLOATS (OFF_FLAG + PTS)
#define SMEM_BYTES (SMEM_FLOATS * 4)

__global__ __launch_bounds__(512, 1) void decode_kernel(
    const float* __restrict__ coor, const float* __restrict__ spos,
    const float* __restrict__ w0, const float* __restrict__ b0,
    const float* __restrict__ w1, const float* __restrict__ b1,
    const float* __restrict__ dw, const float* __restrict__ db,
    const float* __restrict__ cw0, const float* __restrict__ cb0,
    const float* __restrict__ cw1, const float* __restrict__ cb1,
    float* __restrict__ out) {
    extern __shared__ float sm[];
    float* s_w0 = sm + OFF_W0;
    float* s_w1 = sm + OFF_W1;
    float* s_cw0 = sm + OFF_CW0;
    float* s_b0 = sm + OFF_B0;
    float* s_b1 = sm + OFF_B1;
    float* s_dw = sm + OFF_DW;
    float* s_cb0 = sm + OFF_CB0;
    float* s_cw1 = sm + OFF_CW1;
    float* s_cb1 = sm + OFF_CB1;
    float* s_db = sm + OFF_DB;
    float* actA = sm + OFF_ACTA;
    float* actB = sm + OFF_ACTB;
    float* s_flag = sm + OFF_FLAG;

    int tid = threadIdx.x;
    for (int i = tid; i < 9216; i += 512) { s_w0[i] = w0[i]; s_w1[i] = w1[i]; }
    for (int i = tid; i < 2304; i += 512) s_cw0[i] = cw0[i];
    if (tid < 96) { s_b0[tid] = b0[tid]; s_b1[tid] = b1[tid]; s_dw[tid] = dw[tid]; }
    if (tid < 24) s_cb0[tid] = cb0[tid];
    if (tid < 72) s_cw1[tid] = cw1[tid];
    if (tid < 3) s_cb1[tid] = cb1[tid];
    if (tid == 0) s_db[0] = db[0];

    int n = blockIdx.x / (MPTS / PTS);
    int m0 = (blockIdx.x % (MPTS / PTS)) * PTS;
    int p = tid >> 2, oq = tid & 3;
    int m = m0 + p;

    float rx = coor[((size_t)n * MPTS + m) * 3 + 0] - spos[n * 3 + 0];
    float ry = coor[((size_t)n * MPTS + m) * 3 + 1] - spos[n * 3 + 1];
    float rz = coor[((size_t)n * MPTS + m) * 3 + 2] - spos[n * 3 + 2];

    if (oq == 3) {
        s_flag[p] = (fabsf(rx) > 1.f || fabsf(ry) > 1.f || fabsf(rz) > 1.f) ? 1.f : 0.f;
    } else {
        // plane 0: (x,y); plane 1: (x,z); plane 2: (z,x)
        float cu, cv;
        if (oq == 0) { cu = rx; cv = ry; }
        else if (oq == 1) { cu = rx; cv = rz; }
        else { cu = rz; cv = rx; }
        float u = (cu + 1.f) * 64.f - 0.5f;
        float v = (cv + 1.f) * 64.f - 0.5f;
        float fx = floorf(u), fy = floorf(v);
        float wx = u - fx, wy = v - fy;
        int ix0 = (int)fx, iy0 = (int)fy;
        float wts[4] = {(1 - wx) * (1 - wy), wx * (1 - wy), (1 - wx) * wy, wx * wy};
        int xs[4] = {ix0, ix0 + 1, ix0, ix0 + 1};
        int ys[4] = {iy0, iy0, iy0 + 1, iy0 + 1};
        float4 f[8];
#pragma unroll
        for (int k = 0; k < 8; k++) f[k] = make_float4(0.f, 0.f, 0.f, 0.f);
        size_t pb = ((size_t)n * 3 + oq) * RESO * RESO;
#pragma unroll
        for (int t = 0; t < 4; t++) {
            if (xs[t] >= 0 && xs[t] < RESO && ys[t] >= 0 && ys[t] < RESO) {
                const float4* tp = (const float4*)&g_tri[(pb + (size_t)ys[t] * RESO + xs[t]) * TD];
                float wv = wts[t];
#pragma unroll
                for (int k = 0; k < 8; k++) {
                    float4 d = tp[k];
                    f[k].x += wv * d.x; f[k].y += wv * d.y;
                    f[k].z += wv * d.z; f[k].w += wv * d.w;
                }
            }
        }
        float4* dst = (float4*)&actA[p * ASTRIDE + oq * 32];
#pragma unroll
        for (int k = 0; k < 8; k++) dst[k] = f[k];
    }
    __syncthreads();

    int o0 = oq * 24;
    // layer 0: actA -> actB (relu)
    {
        float4 acc[6];
#pragma unroll
        for (int k = 0; k < 6; k++) acc[k] = ((const float4*)&s_b0[o0])[k];
#pragma unroll 4
        for (int i = 0; i < 96; i++) {
            float a = actA[p * ASTRIDE + i];
            const float4* wr = (const float4*)&s_w0[i * 96 + o0];
#pragma unroll
            for (int k = 0; k < 6; k++) {
                float4 w4 = wr[k];
                acc[k].x += a * w4.x; acc[k].y += a * w4.y;
                acc[k].z += a * w4.z; acc[k].w += a * w4.w;
            }
        }
        float* dst = &actB[p * ASTRIDE + o0];
#pragma unroll
        for (int k = 0; k < 6; k++) {
            dst[4 * k + 0] = fmaxf(acc[k].x, 0.f);
            dst[4 * k + 1] = fmaxf(acc[k].y, 0.f);
            dst[4 * k + 2] = fmaxf(acc[k].z, 0.f);
            dst[4 * k + 3] = fmaxf(acc[k].w, 0.f);
        }
    }
    __syncwarp();
    // layer 1: actB -> actA (relu)
    {
        float4 acc[6];
#pragma unroll
        for (int k = 0; k < 6; k++) acc[k] = ((const float4*)&s_b1[o0])[k];
#pragma unroll 4
        for (int i = 0; i < 96; i++) {
            float a = actB[p * ASTRIDE + i];
            const float4* wr = (const float4*)&s_w1[i * 96 + o0];
#pragma unroll
            for (int k = 0; k < 6; k++) {
                float4 w4 = wr[k];
                acc[k].x += a * w4.x; acc[k].y += a * w4.y;
                acc[k].z += a * w4.z; acc[k].w += a * w4.w;
            }
        }
        float* dst = &actA[p * ASTRIDE + o0];
#pragma unroll
        for (int k = 0; k < 6; k++) {
            dst[4 * k + 0] = fmaxf(acc[k].x, 0.f);
            dst[4 * k + 1] = fmaxf(acc[k].y, 0.f);
            dst[4 * k + 2] = fmaxf(acc[k].z, 0.f);
            dst[4 * k + 3] = fmaxf(acc[k].w, 0.f);
        }
    }
    __syncwarp();

    // density: 4-lane split dot product + shfl reduce
    float part = 0.f;
#pragma unroll 4
    for (int i = 0; i < 24; i++) part += actA[p * ASTRIDE + o0 + i] * s_dw[o0 + i];
    part += __shfl_xor_sync(0xffffffffu, part, 1);
    part += __shfl_xor_sync(0xffffffffu, part, 2);
    float dens = part + s_db[0];

    // color hidden: 96 -> 24 (relu), 6 outputs per lane
    {
        int oc0 = oq * 6;
        float ch[6];
#pragma unroll
        for (int j = 0; j < 6; j++) ch[j] = s_cb0[oc0 + j];
#pragma unroll 4
        for (int i = 0; i < 96; i++) {
            float a = actA[p * ASTRIDE + i];
#pragma unroll
            for (int j = 0; j < 6; j++) ch[j] += a * s_cw0[i * 24 + oc0 + j];
        }
#pragma unroll
        for (int j = 0; j < 6; j++) actB[p * ASTRIDE + oc0 + j] = fmaxf(ch[j], 0.f);
    }
    __syncwarp();

    const size_t B2 = (size_t)MPTS * 4 + (size_t)NS * MPTS * 4;  // unmasked_raws base
    size_t ub = B2 + ((size_t)n * MPTS + m) * 4;
    if (oq < 3) {
        float col = s_cb1[oq];
#pragma unroll
        for (int j = 0; j < 24; j++) col += actB[p * ASTRIDE + j] * s_cw1[j * 3 + oq];
        out[ub + oq] = (tanhf(col) + 1.f) * 0.5f;
    } else {
        float rawmask = (s_flag[p] != 0.f) ? 0.f : fmaxf(dens, 0.f);
        out[ub + 3] = rawmask;
    }
}

// ---------------- composition over slots -----------------------------------
__global__ void compose_kernel(float* __restrict__ out) {
    int m = blockIdx.x * blockDim.x + threadIdx.x;
    if (m >= MPTS) return;
    const size_t B1 = (size_t)MPTS * 4;                 // masked_raws
    const size_t B2 = B1 + (size_t)NS * MPTS * 4;       // unmasked_raws
    const size_t B3 = B2 + (size_t)NS * MPTS * 4;       // masks
    float4 um[NS];
    float s = 0.f;
#pragma unroll
    for (int n = 0; n < NS; n++) {
        um[n] = *(const float4*)&out[B2 + ((size_t)n * MPTS + m) * 4];
        s += um[n].w;
    }
    float denom = s + 1e-8f;
    float4 r = make_float4(0.f, 0.f, 0.f, 0.f);
#pragma unroll
    for (int n = 0; n < NS; n++) {
        float mk = um[n].w / denom;
        out[B3 + (size_t)n * MPTS + m] = mk;
        float4 md = make_float4(um[n].x * mk, um[n].y * mk, um[n].z * mk, um[n].w * mk);
        *(float4*)&out[B1 + ((size_t)n * MPTS + m) * 4] = md;
        r.x += md.x; r.y += md.y; r.z += md.z; r.w += md.w;
    }
    *(float4*)&out[(size_t)m * 4] = r;
}

// ---------------- launch ----------------------------------------------------
extern "C" void kernel_launch(void* const* d_in, const int* in_sizes, int n_in,
                              void* d_out, int out_size) {
    const float* coor = (const float*)d_in[0];
    const float* zs   = (const float*)d_in[1];
    const float* sp   = (const float*)d_in[2];
    const float* pos_w = (const float*)d_in[3];
    const float* pos_b = (const float*)d_in[4];
    const float* pe_w  = (const float*)d_in[5];
    const float* pe_b  = (const float*)d_in[6];
    const float* c1w = (const float*)d_in[7];
    const float* c1b = (const float*)d_in[8];
    const float* c2w = (const float*)d_in[9];
    const float* c2b = (const float*)d_in[10];
    const float* c3w = (const float*)d_in[11];
    const float* c3b = (const float*)d_in[12];
    const float* dw0 = (const float*)d_in[13];
    const float* db0 = (const float*)d_in[14];
    const float* dw1 = (const float*)d_in[15];
    const float* db1 = (const float*)d_in[16];
    const float* dnw = (const float*)d_in[17];
    const float* dnb = (const float*)d_in[18];
    const float* cw0 = (const float*)d_in[19];
    const float* cb0 = (const float*)d_in[20];
    const float* cw1 = (const float*)d_in[21];
    const float* cb1 = (const float*)d_in[22];
    float* out = (float*)d_out;

    float *fmap, *h1, *tri;
    cudaGetSymbolAddress((void**)&fmap, g_fmap);
    cudaGetSymbolAddress((void**)&h1, g_h1);
    cudaGetSymbolAddress((void**)&tri, g_tri);

    prep_kernel<<<1, 64>>>(zs, sp, pos_w, pos_b, pe_w, pe_b);
    fmap_kernel<<<(NS * ZD * RESO * RESO + 255) / 256, 256>>>();

    dim3 cg1(4, 16, NS * 4);
    conv_kernel<64, 4, true, false><<<cg1, 256>>>(fmap, c1w, c1b, h1);
    conv_kernel<64, 4, true, false><<<cg1, 256>>>(h1, c2w, c2b, fmap);
    dim3 cg3(4, 16, NS * 6);
    conv_kernel<64, 6, false, true><<<cg3, 256>>>(fmap, c3w, c3b, tri);

    cudaFuncSetAttribute(decode_kernel, cudaFuncAttributeMaxDynamicSharedMemorySize, SMEM_BYTES);
    decode_kernel<<<NS * (MPTS / PTS), 512, SMEM_BYTES>>>(
        coor, sp, dw0, db0, dw1, db1, dnw, dnb, cw0, cb0, cw1, cb1, out);

    compose_kernel<<<MPTS / 256, 256>>>(out);
}

// round 2
// speedup vs baseline: 1.1730x; 1.1730x over previous
#include <cuda_runtime.h>
#include <math.h>

#define RESO 128
#define NS 8
#define MPTS 65536
#define ZD 64
#define TD 32

typedef unsigned long long ull;

// ---------------- packed f32x2 helpers -------------------------------------
__device__ __forceinline__ ull fma2(ull a, ull b, ull c) {
    ull d;
    asm("fma.rn.f32x2 %0, %1, %2, %3;" : "=l"(d) : "l"(a), "l"(b), "l"(c));
    return d;
}
__device__ __forceinline__ ull pk2(float v) {
    ull r;
    asm("mov.b64 %0, {%1, %1};" : "=l"(r) : "f"(v));
    return r;
}
__device__ __forceinline__ float2 upk2(ull a) {
    float2 r;
    asm("mov.b64 {%0, %1}, %2;" : "=f"(r.x), "=f"(r.y) : "l"(a));
    return r;
}

// ---------------- scratch (device globals; no allocation allowed) ----------
__device__ float g_fmap[NS * ZD * RESO * RESO];   // conv2 output
__device__ float g_h1[NS * ZD * RESO * RESO];     // conv1 (analytic) output
__device__ float g_tri[(size_t)NS * 3 * RESO * RESO * TD]; // channel-last triplane
__device__ float g_zb[NS * ZD];
__device__ float g_A[ZD];
__device__ float g_B[ZD];
// conv1 analytic coefficients
__device__ float g_Wz[NS * ZD * 9];
__device__ float g_Wa[ZD * 9];
__device__ float g_Wb[ZD * 9];
__device__ float g_K0[NS * ZD];
__device__ float g_K1[ZD];
__device__ float g_K2[ZD];

// ---------------- prep: z = z_slots + slot_pos[:, :2]@pos_w + pos_b (+pe_b) -
__global__ void prep_kernel(const float* __restrict__ zs, const float* __restrict__ sp,
                            const float* __restrict__ pw, const float* __restrict__ pb,
                            const float* __restrict__ pew, const float* __restrict__ peb) {
    int c = threadIdx.x;
    if (c < ZD) {
        g_A[c] = pew[0 * ZD + c] - pew[2 * ZD + c];
        g_B[c] = pew[1 * ZD + c] - pew[3 * ZD + c];
        for (int n = 0; n < NS; n++) {
            g_zb[n * ZD + c] = zs[n * ZD + c]
                + sp[n * 3 + 0] * pw[0 * ZD + c]
                + sp[n * 3 + 1] * pw[1 * ZD + c]
                + pb[c] + peb[c];
        }
    }
}

// ---------------- prep2: reduce conv1 weights over ic ----------------------
// Wz[n,oc,t] = sum_ic w1[oc,ic,t]*zb[n,ic]; Wa = sum w1*A; Wb = sum w1*B.
// K0/K1/K2: interior closed form.
__global__ void prep2_kernel(const float* __restrict__ w1, const float* __restrict__ b1) {
    int id = threadIdx.x;
    const float s = 2.0f / RESO;
    if (id < ZD * 9) {
        int oc = id / 9, t = id % 9;
        float wa = 0.f, wb = 0.f;
        float wz[NS];
#pragma unroll
        for (int n = 0; n < NS; n++) wz[n] = 0.f;
        for (int ic = 0; ic < ZD; ic++) {
            float w = w1[((size_t)oc * ZD + ic) * 9 + t];
            wa += w * g_A[ic];
            wb += w * g_B[ic];
#pragma unroll
            for (int n = 0; n < NS; n++) wz[n] += w * g_zb[n * ZD + ic];
        }
        g_Wa[oc * 9 + t] = wa;
        g_Wb[oc * 9 + t] = wb;
        for (int n = 0; n < NS; n++) g_Wz[(n * ZD + oc) * 9 + t] = wz[n];
    }
    __syncthreads();
    if (id < ZD) {
        int oc = id;
        float k1 = 0.f, k2 = 0.f;
        float k0[NS];
        for (int n = 0; n < NS; n++) k0[n] = b1[oc];
        for (int t = 0; t < 9; t++) {
            float dx = (float)(t % 3 - 1), dy = (float)(t / 3 - 1);
            float wa = g_Wa[oc * 9 + t], wb = g_Wb[oc * 9 + t];
            k1 += wa;
            k2 += wb;
            for (int n = 0; n < NS; n++)
                k0[n] += g_Wz[(n * ZD + oc) * 9 + t] + s * dx * wa + s * dy * wb;
        }
        g_K1[oc] = k1;
        g_K2[oc] = k2;
        for (int n = 0; n < NS; n++) g_K0[n * ZD + oc] = k0[n];
    }
}

// ---------------- conv1: analytic fill (interior 2 FMA/px, borders 9-tap) --
__global__ __launch_bounds__(512) void conv1fill_kernel(const float* __restrict__ b1) {
    int noc = blockIdx.x;        // n*64 + oc
    int n = noc >> 6, oc = noc & 63;
    int tid = threadIdx.x;
    int x = tid & 127, rb = tid >> 7;   // 4 rows per pass
    const float s = 2.0f / RESO;

    float Wz9[9], Wa9[9], Wb9[9];
#pragma unroll
    for (int t = 0; t < 9; t++) {
        Wz9[t] = g_Wz[(size_t)noc * 9 + t];
        Wa9[t] = g_Wa[oc * 9 + t];
        Wb9[t] = g_Wb[oc * 9 + t];
    }
    float k0 = g_K0[noc], k1 = g_K1[oc], k2 = g_K2[oc], bias = b1[oc];

    float X = (2 * x - 127) * (1.0f / RESO);
    bool xin = (x >= 1) && (x <= 126);
    float* outb = g_h1 + (size_t)noc * RESO * RESO;

    for (int yi = 0; yi < 32; yi++) {
        int y = yi * 4 + rb;
        float Y = (2 * y - 127) * (1.0f / RESO);
        float val;
        if (xin && y >= 1 && y <= 126) {
            val = k0 + k1 * X + k2 * Y;
        } else {
            val = bias;
#pragma unroll
            for (int t = 0; t < 9; t++) {
                int dy = t / 3 - 1, dx = t % 3 - 1;
                int gy = y + dy, gx = x + dx;
                if (gy >= 0 && gy < RESO && gx >= 0 && gx < RESO)
                    val += Wz9[t] + Wa9[t] * (X + dx * s) + Wb9[t] * (Y + dy * s);
            }
        }
        outb[y * RESO + x] = fmaxf(val, 0.f);
    }
}

// ---------------- direct tiled 3x3 conv, packed f32x2 over oc ---------------
// Block: 32x8 pixel tile, 16 output channels. 256 threads.
// Thread: 4 px (x) x 4 oc (2 packed pairs).
template <int IC, int OCG, bool RELU, bool SAMPLE_OUT>
__global__ __launch_bounds__(256, 2) void conv_p_kernel(const float* __restrict__ in,
                                                        const float* __restrict__ wt,
                                                        const float* __restrict__ bias,
                                                        float* __restrict__ out) {
    const int TW = 32, TH = 8, OCB = 16, ICB = 16;
    __shared__ float s_in[ICB][TH + 2][36];     // stride 36: float4-aligned rows
    __shared__ float s_w[ICB][9][OCB];          // oc contiguous -> 64-bit pairs

    int x0 = blockIdx.x * TW;
    int y0 = blockIdx.y * TH;
    int n = blockIdx.z / OCG;
    int oc0 = (blockIdx.z % OCG) * OCB;
    int tid = threadIdx.x;
    int ocq = tid >> 6;        // 0..3
    int pxg = tid & 63;
    int xg = pxg & 7;          // x-group (4 px each)
    int yy = pxg >> 3;         // row in tile

    ull acc[2][4];
#pragma unroll
    for (int jp = 0; jp < 2; jp++)
#pragma unroll
        for (int px = 0; px < 4; px++) acc[jp][px] = 0ULL;

    for (int ic0 = 0; ic0 < IC; ic0 += ICB) {
        // stage input tile with halo (34 valid cols)
        for (int idx = tid; idx < ICB * (TH + 2) * 34; idx += 256) {
            int ici = idx / 340;
            int r = idx % 340;
            int ry = r / 34, rx = r % 34;
            int gy = y0 + ry - 1, gx = x0 + rx - 1;
            float v = 0.f;
            if (gy >= 0 && gy < RESO && gx >= 0 && gx < RESO)
                v = in[(((size_t)n * IC + ic0 + ici) * RESO + gy) * RESO + gx];
            s_in[ici][ry][rx] = v;
        }
        // stage weights, oc-contiguous
        for (int idx = tid; idx < ICB * 9 * OCB; idx += 256) {
            int ici = idx / 144;
            int r = idx % 144;
            int k = r / 16, oci = r % 16;
            s_w[ici][k][oci] = wt[((size_t)(oc0 + oci) * IC + ic0 + ici) * 9 + k];
        }
        __syncthreads();

#pragma unroll 1
        for (int ici = 0; ici < ICB; ici++) {
            ull vv[3][6];
#pragma unroll
            for (int dy = 0; dy < 3; dy++) {
                float4 a = *(const float4*)&s_in[ici][yy + dy][4 * xg];
                float4 b = *(const float4*)&s_in[ici][yy + dy][4 * xg + 4];
                vv[dy][0] = pk2(a.x); vv[dy][1] = pk2(a.y); vv[dy][2] = pk2(a.z);
                vv[dy][3] = pk2(a.w); vv[dy][4] = pk2(b.x); vv[dy][5] = pk2(b.y);
            }
#pragma unroll
            for (int ky = 0; ky < 3; ky++)
#pragma unroll
                for (int kx = 0; kx < 3; kx++) {
                    ulonglong2 w2 = *(const ulonglong2*)&s_w[ici][ky * 3 + kx][ocq * 4];
#pragma unroll
                    for (int px = 0; px < 4; px++) {
                        acc[0][px] = fma2(w2.x, vv[ky][px + kx], acc[0][px]);
                        acc[1][px] = fma2(w2.y, vv[ky][px + kx], acc[1][px]);
                    }
                }
        }
        __syncthreads();
    }

    int y = y0 + yy;
#pragma unroll
    for (int jp = 0; jp < 2; jp++) {
        int ocA = oc0 + ocq * 4 + jp * 2;
        float bA = bias[ocA], bB = bias[ocA + 1];
#pragma unroll
        for (int px = 0; px < 4; px++) {
            float2 v = upk2(acc[jp][px]);
            float vA = v.x + bA, vB = v.y + bB;
            if (RELU) { vA = fmaxf(vA, 0.f); vB = fmaxf(vB, 0.f); }
            int x = x0 + 4 * xg + px;
            if (SAMPLE_OUT) {
                int plA = ocA >> 5, cA = ocA & 31;
                int plB = (ocA + 1) >> 5, cB = (ocA + 1) & 31;
                out[((((size_t)n * 3 + plA) * RESO + y) * RESO + x) * TD + cA] = vA;
                out[((((size_t)n * 3 + plB) * RESO + y) * RESO + x) * TD + cB] = vB;
            } else {
                out[(((size_t)n * (OCG * 16) + ocA) * RESO + y) * RESO + x] = vA;
                out[(((size_t)n * (OCG * 16) + ocA + 1) * RESO + y) * RESO + x] = vB;
            }
        }
    }
}

// ---------------- fused sample + decoder MLP (packed f32x2) ----------------
#define PTS 128
#define ASTRIDE 100
#define OFF_W0   0
#define OFF_W1   9216
#define OFF_CW0  18432
#define OFF_B0   20736
#define OFF_B1   20832
#define OFF_DW   20928
#define OFF_CB0  21024
#define OFF_CW1  21048
#define OFF_CB1  21120
#define OFF_DB   21123
#define OFF_ACTA 21124
#define OFF_ACTB (21124 + PTS * ASTRIDE)
#define OFF_FLAG (OFF_ACTB + PTS * ASTRIDE)
#define SMEM_FLOATS (OFF_FLAG + PTS)
#define SMEM_BYTES (SMEM_FLOATS * 4)

__global__ __launch_bounds__(512, 1) void decode_kernel(
    const float* __restrict__ coor, const float* __restrict__ spos,
    const float* __restrict__ w0, const float* __restrict__ b0,
    const float* __restrict__ w1, const float* __restrict__ b1,
    const float* __restrict__ dw, const float* __restrict__ db,
    const float* __restrict__ cw0, const float* __restrict__ cb0,
    const float* __restrict__ cw1, const float* __restrict__ cb1,
    float* __restrict__ out) {
    extern __shared__ float sm[];
    float* s_w0 = sm + OFF_W0;
    float* s_w1 = sm + OFF_W1;
    float* s_cw0 = sm + OFF_CW0;
    float* s_b0 = sm + OFF_B0;
    float* s_b1 = sm + OFF_B1;
    float* s_dw = sm + OFF_DW;
    float* s_cb0 = sm + OFF_CB0;
    float* s_cw1 = sm + OFF_CW1;
    float* s_cb1 = sm + OFF_CB1;
    float* s_db = sm + OFF_DB;
    float* actA = sm + OFF_ACTA;
    float* actB = sm + OFF_ACTB;
    float* s_flag = sm + OFF_FLAG;

    int tid = threadIdx.x;
    for (int i = tid; i < 9216; i += 512) { s_w0[i] = w0[i]; s_w1[i] = w1[i]; }
    for (int i = tid; i < 2304; i += 512) s_cw0[i] = cw0[i];
    if (tid < 96) { s_b0[tid] = b0[tid]; s_b1[tid] = b1[tid]; s_dw[tid] = dw[tid]; }
    if (tid < 24) s_cb0[tid] = cb0[tid];
    if (tid < 72) s_cw1[tid] = cw1[tid];
    if (tid < 3) s_cb1[tid] = cb1[tid];
    if (tid == 0) s_db[0] = db[0];

    int n = blockIdx.x / (MPTS / PTS);
    int m0 = (blockIdx.x % (MPTS / PTS)) * PTS;
    int p = tid >> 2, oq = tid & 3;
    int m = m0 + p;

    float rx = coor[((size_t)n * MPTS + m) * 3 + 0] - spos[n * 3 + 0];
    float ry = coor[((size_t)n * MPTS + m) * 3 + 1] - spos[n * 3 + 1];
    float rz = coor[((size_t)n * MPTS + m) * 3 + 2] - spos[n * 3 + 2];

    if (oq == 3) {
        s_flag[p] = (fabsf(rx) > 1.f || fabsf(ry) > 1.f || fabsf(rz) > 1.f) ? 1.f : 0.f;
    } else {
        // plane 0: (x,y); plane 1: (x,z); plane 2: (z,x)
        float cu, cv;
        if (oq == 0) { cu = rx; cv = ry; }
        else if (oq == 1) { cu = rx; cv = rz; }
        else { cu = rz; cv = rx; }
        float u = (cu + 1.f) * 64.f - 0.5f;
        float v = (cv + 1.f) * 64.f - 0.5f;
        float fx = floorf(u), fy = floorf(v);
        float wx = u - fx, wy = v - fy;
        int ix0 = (int)fx, iy0 = (int)fy;
        float wts[4] = {(1 - wx) * (1 - wy), wx * (1 - wy), (1 - wx) * wy, wx * wy};
        int xs[4] = {ix0, ix0 + 1, ix0, ix0 + 1};
        int ys[4] = {iy0, iy0, iy0 + 1, iy0 + 1};
        float4 f[8];
#pragma unroll
        for (int k = 0; k < 8; k++) f[k] = make_float4(0.f, 0.f, 0.f, 0.f);
        size_t pb = ((size_t)n * 3 + oq) * RESO * RESO;
#pragma unroll
        for (int t = 0; t < 4; t++) {
            if (xs[t] >= 0 && xs[t] < RESO && ys[t] >= 0 && ys[t] < RESO) {
                const float4* tp = (const float4*)&g_tri[(pb + (size_t)ys[t] * RESO + xs[t]) * TD];
                float wv = wts[t];
#pragma unroll
                for (int k = 0; k < 8; k++) {
                    float4 d = tp[k];
                    f[k].x += wv * d.x; f[k].y += wv * d.y;
                    f[k].z += wv * d.z; f[k].w += wv * d.w;
                }
            }
        }
        float4* dst = (float4*)&actA[p * ASTRIDE + oq * 32];
#pragma unroll
        for (int k = 0; k < 8; k++) dst[k] = f[k];
    }
    __syncthreads();

    int o0 = oq * 24;
    // layer 0: actA -> actB (relu), packed pairs over outputs
    {
        ull acc[12];
        const ulonglong2* bb = (const ulonglong2*)&s_b0[o0];
#pragma unroll
        for (int k = 0; k < 6; k++) { ulonglong2 q = bb[k]; acc[2 * k] = q.x; acc[2 * k + 1] = q.y; }
        const float* ap = &actA[p * ASTRIDE];
#pragma unroll 4
        for (int i = 0; i < 96; i++) {
            ull aa = pk2(ap[i]);
            const ulonglong2* wr = (const ulonglong2*)&s_w0[i * 96 + o0];
#pragma unroll
            for (int k = 0; k < 6; k++) {
                ulonglong2 q = wr[k];
                acc[2 * k] = fma2(q.x, aa, acc[2 * k]);
                acc[2 * k + 1] = fma2(q.y, aa, acc[2 * k + 1]);
            }
        }
        float* dst = &actB[p * ASTRIDE + o0];
#pragma unroll
        for (int k = 0; k < 12; k++) {
            float2 v = upk2(acc[k]);
            dst[2 * k] = fmaxf(v.x, 0.f);
            dst[2 * k + 1] = fmaxf(v.y, 0.f);
        }
    }
    __syncwarp();
    // layer 1: actB -> actA (relu)
    {
        ull acc[12];
        const ulonglong2* bb = (const ulonglong2*)&s_b1[o0];
#pragma unroll
        for (int k = 0; k < 6; k++) { ulonglong2 q = bb[k]; acc[2 * k] = q.x; acc[2 * k + 1] = q.y; }
        const float* ap = &actB[p * ASTRIDE];
#pragma unroll 4
        for (int i = 0; i < 96; i++) {
            ull aa = pk2(ap[i]);
            const ulonglong2* wr = (const ulonglong2*)&s_w1[i * 96 + o0];
#pragma unroll
            for (int k = 0; k < 6; k++) {
                ulonglong2 q = wr[k];
                acc[2 * k] = fma2(q.x, aa, acc[2 * k]);
                acc[2 * k + 1] = fma2(q.y, aa, acc[2 * k + 1]);
            }
        }
        float* dst = &actA[p * ASTRIDE + o0];
#pragma unroll
        for (int k = 0; k < 12; k++) {
            float2 v = upk2(acc[k]);
            dst[2 * k] = fmaxf(v.x, 0.f);
            dst[2 * k + 1] = fmaxf(v.y, 0.f);
        }
    }
    __syncwarp();

    // density: 4-lane split dot product + shfl reduce
    float part = 0.f;
#pragma unroll 4
    for (int i = 0; i < 24; i++) part += actA[p * ASTRIDE + o0 + i] * s_dw[o0 + i];
    part += __shfl_xor_sync(0xffffffffu, part, 1);
    part += __shfl_xor_sync(0xffffffffu, part, 2);
    float dens = part + s_db[0];

    // color hidden: 96 -> 24 (relu), 6 outputs (3 pairs) per lane
    {
        int oc0c = oq * 6;
        ull ch[3];
#pragma unroll
        for (int k = 0; k < 3; k++) ch[k] = *(const ull*)&s_cb0[oc0c + 2 * k];
        const float* ap = &actA[p * ASTRIDE];
#pragma unroll 4
        for (int i = 0; i < 96; i++) {
            ull aa = pk2(ap[i]);
#pragma unroll
            for (int k = 0; k < 3; k++)
                ch[k] = fma2(*(const ull*)&s_cw0[i * 24 + oc0c + 2 * k], aa, ch[k]);
        }
#pragma unroll
        for (int k = 0; k < 3; k++) {
            float2 v = upk2(ch[k]);
            actB[p * ASTRIDE + oc0c + 2 * k] = fmaxf(v.x, 0.f);
            actB[p * ASTRIDE + oc0c + 2 * k + 1] = fmaxf(v.y, 0.f);
        }
    }
    __syncwarp();

    const size_t B2 = (size_t)MPTS * 4 + (size_t)NS * MPTS * 4;  // unmasked_raws base
    size_t ub = B2 + ((size_t)n * MPTS + m) * 4;
    if (oq < 3) {
        float col = s_cb1[oq];
#pragma unroll
        for (int j = 0; j < 24; j++) col += actB[p * ASTRIDE + j] * s_cw1[j * 3 + oq];
        out[ub + oq] = (tanhf(col) + 1.f) * 0.5f;
    } else {
        float rawmask = (s_flag[p] != 0.f) ? 0.f : fmaxf(dens, 0.f);
        out[ub + 3] = rawmask;
    }
}

// ---------------- composition over slots -----------------------------------
__global__ void compose_kernel(float* __restrict__ out) {
    int m = blockIdx.x * blockDim.x + threadIdx.x;
    if (m >= MPTS) return;
    const size_t B1 = (size_t)MPTS * 4;                 // masked_raws
    const size_t B2 = B1 + (size_t)NS * MPTS * 4;       // unmasked_raws
    const size_t B3 = B2 + (size_t)NS * MPTS * 4;       // masks
    float4 um[NS];
    float s = 0.f;
#pragma unroll
    for (int n = 0; n < NS; n++) {
        um[n] = *(const float4*)&out[B2 + ((size_t)n * MPTS + m) * 4];
        s += um[n].w;
    }
    float denom = s + 1e-8f;
    float4 r = make_float4(0.f, 0.f, 0.f, 0.f);
#pragma unroll
    for (int n = 0; n < NS; n++) {
        float mk = um[n].w / denom;
        out[B3 + (size_t)n * MPTS + m] = mk;
        float4 md = make_float4(um[n].x * mk, um[n].y * mk, um[n].z * mk, um[n].w * mk);
        *(float4*)&out[B1 + ((size_t)n * MPTS + m) * 4] = md;
        r.x += md.x; r.y += md.y; r.z += md.z; r.w += md.w;
    }
    *(float4*)&out[(size_t)m * 4] = r;
}

// ---------------- launch ----------------------------------------------------
extern "C" void kernel_launch(void* const* d_in, const int* in_sizes, int n_in,
                              void* d_out, int out_size) {
    const float* coor = (const float*)d_in[0];
    const float* zs   = (const float*)d_in[1];
    const float* sp   = (const float*)d_in[2];
    const float* pos_w = (const float*)d_in[3];
    const float* pos_b = (const float*)d_in[4];
    const float* pe_w  = (const float*)d_in[5];
    const float* pe_b  = (const float*)d_in[6];
    const float* c1w = (const float*)d_in[7];
    const float* c1b = (const float*)d_in[8];
    const float* c2w = (const float*)d_in[9];
    const float* c2b = (const float*)d_in[10];
    const float* c3w = (const float*)d_in[11];
    const float* c3b = (const float*)d_in[12];
    const float* dw0 = (const float*)d_in[13];
    const float* db0 = (const float*)d_in[14];
    const float* dw1 = (const float*)d_in[15];
    const float* db1 = (const float*)d_in[16];
    const float* dnw = (const float*)d_in[17];
    const float* dnb = (const float*)d_in[18];
    const float* cw0 = (const float*)d_in[19];
    const float* cb0 = (const float*)d_in[20];
    const float* cw1 = (const float*)d_in[21];
    const float* cb1 = (const float*)d_in[22];
    float* out = (float*)d_out;

    float *fmap, *h1, *tri;
    cudaGetSymbolAddress((void**)&fmap, g_fmap);
    cudaGetSymbolAddress((void**)&h1, g_h1);
    cudaGetSymbolAddress((void**)&tri, g_tri);

    prep_kernel<<<1, 64>>>(zs, sp, pos_w, pos_b, pe_w, pe_b);
    prep2_kernel<<<1, 576>>>(c1w, c1b);
    conv1fill_kernel<<<NS * ZD, 512>>>(c1b);

    dim3 cg1(4, 16, NS * 4);
    conv_p_kernel<64, 4, true, false><<<cg1, 256>>>(h1, c2w, c2b, fmap);
    dim3 cg3(4, 16, NS * 6);
    conv_p_kernel<64, 6, false, true><<<cg3, 256>>>(fmap, c3w, c3b, tri);

    cudaFuncSetAttribute(decode_kernel, cudaFuncAttributeMaxDynamicSharedMemorySize, SMEM_BYTES);
    decode_kernel<<<NS * (MPTS / PTS), 512, SMEM_BYTES>>>(
        coor, sp, dw0, db0, dw1, db1, dnw, dnb, cw0, cb0, cw1, cb1, out);

    compose_kernel<<<MPTS / 256, 256>>>(out);
}

// round 3
// speedup vs baseline: 1.2406x; 1.0577x over previous
#include <cuda_runtime.h>
#include <math.h>

#define RESO 128
#define NS 8
#define MPTS 65536
#define ZD 64
#define TD 32

typedef unsigned long long ull;

// ---------------- packed f32x2 helpers -------------------------------------
__device__ __forceinline__ ull fma2(ull a, ull b, ull c) {
    ull d;
    asm("fma.rn.f32x2 %0, %1, %2, %3;" : "=l"(d) : "l"(a), "l"(b), "l"(c));
    return d;
}
__device__ __forceinline__ ull pk2(float v) {
    ull r;
    asm("mov.b64 %0, {%1, %1};" : "=l"(r) : "f"(v));
    return r;
}
__device__ __forceinline__ float2 upk2(ull a) {
    float2 r;
    asm("mov.b64 {%0, %1}, %2;" : "=f"(r.x), "=f"(r.y) : "l"(a));
    return r;
}

// ---------------- scratch (device globals; no allocation allowed) ----------
__device__ float g_fmap[NS * ZD * RESO * RESO];   // conv2 output
__device__ float g_h1[NS * ZD * RESO * RESO];     // conv1 (analytic) output
__device__ float g_tri[(size_t)NS * 3 * RESO * RESO * TD]; // channel-last triplane
__device__ float g_zb[NS * ZD];
__device__ float g_A[ZD];
__device__ float g_B[ZD];
// conv1 analytic coefficients
__device__ float g_Wz[NS * ZD * 9];
__device__ float g_Wa[ZD * 9];
__device__ float g_Wb[ZD * 9];
__device__ float g_K0[NS * ZD];
__device__ float g_K1[ZD];
__device__ float g_K2[ZD];

// ---------------- prep --------------------------------------------------
__global__ void prep_kernel(const float* __restrict__ zs, const float* __restrict__ sp,
                            const float* __restrict__ pw, const float* __restrict__ pb,
                            const float* __restrict__ pew, const float* __restrict__ peb) {
    int c = threadIdx.x;
    if (c < ZD) {
        g_A[c] = pew[0 * ZD + c] - pew[2 * ZD + c];
        g_B[c] = pew[1 * ZD + c] - pew[3 * ZD + c];
        for (int n = 0; n < NS; n++) {
            g_zb[n * ZD + c] = zs[n * ZD + c]
                + sp[n * 3 + 0] * pw[0 * ZD + c]
                + sp[n * 3 + 1] * pw[1 * ZD + c]
                + pb[c] + peb[c];
        }
    }
}

__global__ void prep2_kernel(const float* __restrict__ w1, const float* __restrict__ b1) {
    int id = threadIdx.x;
    const float s = 2.0f / RESO;
    if (id < ZD * 9) {
        int oc = id / 9, t = id % 9;
        float wa = 0.f, wb = 0.f;
        float wz[NS];
#pragma unroll
        for (int n = 0; n < NS; n++) wz[n] = 0.f;
        for (int ic = 0; ic < ZD; ic++) {
            float w = w1[((size_t)oc * ZD + ic) * 9 + t];
            wa += w * g_A[ic];
            wb += w * g_B[ic];
#pragma unroll
            for (int n = 0; n < NS; n++) wz[n] += w * g_zb[n * ZD + ic];
        }
        g_Wa[oc * 9 + t] = wa;
        g_Wb[oc * 9 + t] = wb;
        for (int n = 0; n < NS; n++) g_Wz[(n * ZD + oc) * 9 + t] = wz[n];
    }
    __syncthreads();
    if (id < ZD) {
        int oc = id;
        float k1 = 0.f, k2 = 0.f;
        float k0[NS];
        for (int n = 0; n < NS; n++) k0[n] = b1[oc];
        for (int t = 0; t < 9; t++) {
            float dx = (float)(t % 3 - 1), dy = (float)(t / 3 - 1);
            float wa = g_Wa[oc * 9 + t], wb = g_Wb[oc * 9 + t];
            k1 += wa;
            k2 += wb;
            for (int n = 0; n < NS; n++)
                k0[n] += g_Wz[(n * ZD + oc) * 9 + t] + s * dx * wa + s * dy * wb;
        }
        g_K1[oc] = k1;
        g_K2[oc] = k2;
        for (int n = 0; n < NS; n++) g_K0[n * ZD + oc] = k0[n];
    }
}

// ---------------- conv1: analytic fill -------------------------------------
__global__ __launch_bounds__(512) void conv1fill_kernel(const float* __restrict__ b1) {
    int noc = blockIdx.x;        // n*64 + oc
    int n = noc >> 6, oc = noc & 63;
    int tid = threadIdx.x;
    int x = tid & 127, rb = tid >> 7;
    const float s = 2.0f / RESO;

    float Wz9[9], Wa9[9], Wb9[9];
#pragma unroll
    for (int t = 0; t < 9; t++) {
        Wz9[t] = g_Wz[(size_t)noc * 9 + t];
        Wa9[t] = g_Wa[oc * 9 + t];
        Wb9[t] = g_Wb[oc * 9 + t];
    }
    float k0 = g_K0[noc], k1 = g_K1[oc], k2 = g_K2[oc], bias = b1[oc];

    float X = (2 * x - 127) * (1.0f / RESO);
    bool xin = (x >= 1) && (x <= 126);
    float* outb = g_h1 + (size_t)noc * RESO * RESO;

    for (int yi = 0; yi < 32; yi++) {
        int y = yi * 4 + rb;
        float Y = (2 * y - 127) * (1.0f / RESO);
        float val;
        if (xin && y >= 1 && y <= 126) {
            val = k0 + k1 * X + k2 * Y;
        } else {
            val = bias;
#pragma unroll
            for (int t = 0; t < 9; t++) {
                int dy = t / 3 - 1, dx = t % 3 - 1;
                int gy = y + dy, gx = x + dx;
                if (gy >= 0 && gy < RESO && gx >= 0 && gx < RESO)
                    val += Wz9[t] + Wa9[t] * (X + dx * s) + Wb9[t] * (Y + dy * s);
            }
        }
        outb[y * RESO + x] = fmaxf(val, 0.f);
    }
}

// ---------------- direct tiled 3x3 conv, packed f32x2 over oc ---------------
template <int IC, int OCG, bool RELU, bool SAMPLE_OUT>
__global__ __launch_bounds__(256, 3) void conv_p_kernel(const float* __restrict__ in,
                                                        const float* __restrict__ wt,
                                                        const float* __restrict__ bias,
                                                        float* __restrict__ out) {
    const int TW = 32, TH = 8, OCB = 16, ICB = 16;
    __shared__ float s_in[ICB][TH + 2][36];
    __shared__ float s_w[ICB][9][OCB];

    int x0 = blockIdx.x * TW;
    int y0 = blockIdx.y * TH;
    int n = blockIdx.z / OCG;
    int oc0 = (blockIdx.z % OCG) * OCB;
    int tid = threadIdx.x;
    int ocq = tid >> 6;
    int pxg = tid & 63;
    int xg = pxg & 7;
    int yy = pxg >> 3;

    ull acc[2][4];
#pragma unroll
    for (int jp = 0; jp < 2; jp++)
#pragma unroll
        for (int px = 0; px < 4; px++) acc[jp][px] = 0ULL;

    for (int ic0 = 0; ic0 < IC; ic0 += ICB) {
        for (int idx = tid; idx < ICB * (TH + 2) * 34; idx += 256) {
            int ici = idx / 340;
            int r = idx % 340;
            int ry = r / 34, rx = r % 34;
            int gy = y0 + ry - 1, gx = x0 + rx - 1;
            float v = 0.f;
            if (gy >= 0 && gy < RESO && gx >= 0 && gx < RESO)
                v = in[(((size_t)n * IC + ic0 + ici) * RESO + gy) * RESO + gx];
            s_in[ici][ry][rx] = v;
        }
        for (int idx = tid; idx < ICB * 9 * OCB; idx += 256) {
            int ici = idx / 144;
            int r = idx % 144;
            int k = r / 16, oci = r % 16;
            s_w[ici][k][oci] = wt[((size_t)(oc0 + oci) * IC + ic0 + ici) * 9 + k];
        }
        __syncthreads();

#pragma unroll 1
        for (int ici = 0; ici < ICB; ici++) {
            ull vv[3][6];
#pragma unroll
            for (int dy = 0; dy < 3; dy++) {
                float4 a = *(const float4*)&s_in[ici][yy + dy][4 * xg];
                float4 b = *(const float4*)&s_in[ici][yy + dy][4 * xg + 4];
                vv[dy][0] = pk2(a.x); vv[dy][1] = pk2(a.y); vv[dy][2] = pk2(a.z);
                vv[dy][3] = pk2(a.w); vv[dy][4] = pk2(b.x); vv[dy][5] = pk2(b.y);
            }
#pragma unroll
            for (int ky = 0; ky < 3; ky++)
#pragma unroll
                for (int kx = 0; kx < 3; kx++) {
                    ulonglong2 w2 = *(const ulonglong2*)&s_w[ici][ky * 3 + kx][ocq * 4];
#pragma unroll
                    for (int px = 0; px < 4; px++) {
                        acc[0][px] = fma2(w2.x, vv[ky][px + kx], acc[0][px]);
                        acc[1][px] = fma2(w2.y, vv[ky][px + kx], acc[1][px]);
                    }
                }
        }
        __syncthreads();
    }

    int y = y0 + yy;
#pragma unroll
    for (int jp = 0; jp < 2; jp++) {
        int ocA = oc0 + ocq * 4 + jp * 2;
        float bA = bias[ocA], bB = bias[ocA + 1];
#pragma unroll
        for (int px = 0; px < 4; px++) {
            float2 v = upk2(acc[jp][px]);
            float vA = v.x + bA, vB = v.y + bB;
            if (RELU) { vA = fmaxf(vA, 0.f); vB = fmaxf(vB, 0.f); }
            int x = x0 + 4 * xg + px;
            if (SAMPLE_OUT) {
                int plA = ocA >> 5, cA = ocA & 31;
                int plB = (ocA + 1) >> 5, cB = (ocA + 1) & 31;
                out[((((size_t)n * 3 + plA) * RESO + y) * RESO + x) * TD + cA] = vA;
                out[((((size_t)n * 3 + plB) * RESO + y) * RESO + x) * TD + cB] = vB;
            } else {
                out[(((size_t)n * (OCG * 16) + ocA) * RESO + y) * RESO + x] = vA;
                out[(((size_t)n * (OCG * 16) + ocA + 1) * RESO + y) * RESO + x] = vB;
            }
        }
    }
}

// ---------------- persistent fused sample + decoder MLP --------------------
#define ASTRIDE 100
#define OFF_W0   0
#define OFF_W1   9216
#define OFF_CW0  18432
#define OFF_B0   20736
#define OFF_B1   20832
#define OFF_DW   20928
#define OFF_CB0  21024
#define OFF_CW1  21048
#define OFF_CB1  21120
#define OFF_DB   21123
#define OFF_ACTA 21124
#define OFF_ACTB (OFF_ACTA + 128 * ASTRIDE)
#define SMEM_FLOATS (OFF_ACTB + 128 * ASTRIDE)
#define SMEM_BYTES (SMEM_FLOATS * 4)
#define NTILES (NS * MPTS / 8)   // 8-point warp tiles

// gather 3-plane features for one point into actA slot; lane3 returns flag
__device__ __forceinline__ float sample_point(
    const float* __restrict__ coor, const float* __restrict__ spos,
    int wt, int p8, int oq, float* actA_slot) {
    int n = wt >> 13;                 // wt / 8192
    int m = ((wt & 8191) << 3) + p8;  // 8 pts per warp-tile
    float rx = coor[((size_t)n * MPTS + m) * 3 + 0] - spos[n * 3 + 0];
    float ry = coor[((size_t)n * MPTS + m) * 3 + 1] - spos[n * 3 + 1];
    float rz = coor[((size_t)n * MPTS + m) * 3 + 2] - spos[n * 3 + 2];
    if (oq == 3)
        return (fabsf(rx) > 1.f || fabsf(ry) > 1.f || fabsf(rz) > 1.f) ? 1.f : 0.f;
    float cu, cv;
    if (oq == 0) { cu = rx; cv = ry; }
    else if (oq == 1) { cu = rx; cv = rz; }
    else { cu = rz; cv = rx; }
    float u = (cu + 1.f) * 64.f - 0.5f;
    float v = (cv + 1.f) * 64.f - 0.5f;
    float fx = floorf(u), fy = floorf(v);
    float wx = u - fx, wy = v - fy;
    int ix0 = (int)fx, iy0 = (int)fy;
    float wts[4] = {(1 - wx) * (1 - wy), wx * (1 - wy), (1 - wx) * wy, wx * wy};
    int xs[4] = {ix0, ix0 + 1, ix0, ix0 + 1};
    int ys[4] = {iy0, iy0, iy0 + 1, iy0 + 1};
    float4 f[8];
#pragma unroll
    for (int k = 0; k < 8; k++) f[k] = make_float4(0.f, 0.f, 0.f, 0.f);
    size_t pb = ((size_t)n * 3 + oq) * RESO * RESO;
#pragma unroll
    for (int t = 0; t < 4; t++) {
        if (xs[t] >= 0 && xs[t] < RESO && ys[t] >= 0 && ys[t] < RESO) {
            const float4* tp = (const float4*)&g_tri[(pb + (size_t)ys[t] * RESO + xs[t]) * TD];
            float wv = wts[t];
#pragma unroll
            for (int k = 0; k < 8; k++) {
                float4 d = tp[k];
                f[k].x += wv * d.x; f[k].y += wv * d.y;
                f[k].z += wv * d.z; f[k].w += wv * d.w;
            }
        }
    }
    float4* dst = (float4*)(actA_slot + oq * 32);
#pragma unroll
    for (int k = 0; k < 8; k++) dst[k] = f[k];
    return 0.f;
}

__device__ __forceinline__ void mlp96(const float* __restrict__ src,
                                      float* __restrict__ dst,
                                      const float* __restrict__ sw,
                                      const float* __restrict__ sb, int o0) {
    ull acc[12];
    const ulonglong2* bb = (const ulonglong2*)&sb[o0];
#pragma unroll
    for (int k = 0; k < 6; k++) { ulonglong2 q = bb[k]; acc[2 * k] = q.x; acc[2 * k + 1] = q.y; }
#pragma unroll 4
    for (int i = 0; i < 96; i++) {
        ull aa = pk2(src[i]);
        const ulonglong2* wr = (const ulonglong2*)&sw[i * 96 + o0];
#pragma unroll
        for (int k = 0; k < 6; k++) {
            ulonglong2 q = wr[k];
            acc[2 * k] = fma2(q.x, aa, acc[2 * k]);
            acc[2 * k + 1] = fma2(q.y, aa, acc[2 * k + 1]);
        }
    }
#pragma unroll
    for (int k = 0; k < 12; k++) {
        float2 v = upk2(acc[k]);
        dst[2 * k] = fmaxf(v.x, 0.f);
        dst[2 * k + 1] = fmaxf(v.y, 0.f);
    }
}

__global__ __launch_bounds__(512, 1) void decode_kernel(
    const float* __restrict__ coor, const float* __restrict__ spos,
    const float* __restrict__ w0, const float* __restrict__ b0,
    const float* __restrict__ w1, const float* __restrict__ b1,
    const float* __restrict__ dw, const float* __restrict__ db,
    const float* __restrict__ cw0, const float* __restrict__ cb0,
    const float* __restrict__ cw1, const float* __restrict__ cb1,
    float* __restrict__ out) {
    extern __shared__ float sm[];
    float* s_w0 = sm + OFF_W0;
    float* s_w1 = sm + OFF_W1;
    float* s_cw0 = sm + OFF_CW0;
    float* s_b0 = sm + OFF_B0;
    float* s_b1 = sm + OFF_B1;
    float* s_dw = sm + OFF_DW;
    float* s_cb0 = sm + OFF_CB0;
    float* s_cw1 = sm + OFF_CW1;
    float* s_cb1 = sm + OFF_CB1;
    float* s_db = sm + OFF_DB;
    float* actA = sm + OFF_ACTA;
    float* actB = sm + OFF_ACTB;

    int tid = threadIdx.x;
    // stage weights once (float4)
    for (int i = tid; i < 2304; i += 512) {
        ((float4*)s_w0)[i] = ((const float4*)w0)[i];
        ((float4*)s_w1)[i] = ((const float4*)w1)[i];
    }
    for (int i = tid; i < 576; i += 512) ((float4*)s_cw0)[i] = ((const float4*)cw0)[i];
    if (tid < 96) { s_b0[tid] = b0[tid]; s_b1[tid] = b1[tid]; s_dw[tid] = dw[tid]; }
    if (tid < 24) s_cb0[tid] = cb0[tid];
    if (tid < 72) s_cw1[tid] = cw1[tid];
    if (tid < 3) s_cb1[tid] = cb1[tid];
    if (tid == 0) s_db[0] = db[0];
    __syncthreads();

    const int slot = tid >> 2;           // 0..127
    const int oq = tid & 3;
    const int p8 = (tid >> 2) & 7;       // point within warp-tile
    float* aslotA = actA + slot * ASTRIDE;
    float* aslotB = actB + slot * ASTRIDE;
    const int o0 = oq * 24;
    const int WSTRIDE = gridDim.x * 16;
    const size_t B2 = (size_t)MPTS * 4 + (size_t)NS * MPTS * 4;

    int wt = blockIdx.x * 16 + (tid >> 5);
    if (wt >= NTILES) return;

    float flag_cur = sample_point(coor, spos, wt, p8, oq, aslotA);
    __syncwarp();

    while (true) {
        // layer 0: actA -> actB
        mlp96(aslotA, aslotB + o0, s_w0, s_b0, o0);
        __syncwarp();

        // prefetch/sample next tile into actA (overlaps with layer1 issue)
        int wt2 = wt + WSTRIDE;
        float flag_next = 0.f;
        if (wt2 < NTILES)
            flag_next = sample_point(coor, spos, wt2, p8, oq, aslotA);

        // layer 1: actB -> actB (in-place; warp-synchronous)
        mlp96(aslotB, aslotB + o0, s_w1, s_b1, o0);
        __syncwarp();

        // density partial (own 24-chunk)
        float part = 0.f;
#pragma unroll 4
        for (int i = 0; i < 24; i++) part += aslotB[o0 + i] * s_dw[o0 + i];
        part += __shfl_xor_sync(0xffffffffu, part, 1);
        part += __shfl_xor_sync(0xffffffffu, part, 2);
        float dens = part + s_db[0];

        // color hidden 96->24 (6 per lane, registers)
        float hid[6];
        {
            int oc0c = oq * 6;
            ull ch[3];
#pragma unroll
            for (int k = 0; k < 3; k++) ch[k] = *(const ull*)&s_cb0[oc0c + 2 * k];
#pragma unroll 4
            for (int i = 0; i < 96; i++) {
                ull aa = pk2(aslotB[i]);
#pragma unroll
                for (int k = 0; k < 3; k++)
                    ch[k] = fma2(*(const ull*)&s_cw0[i * 24 + oc0c + 2 * k], aa, ch[k]);
            }
#pragma unroll
            for (int k = 0; k < 3; k++) {
                float2 v = upk2(ch[k]);
                hid[2 * k] = fmaxf(v.x, 0.f);
                hid[2 * k + 1] = fmaxf(v.y, 0.f);
            }
        }
        // color output 24->3 via quad shuffle reduce
        float c0 = 0.f, c1 = 0.f, c2 = 0.f;
#pragma unroll
        for (int j = 0; j < 6; j++) {
            int k = oq * 6 + j;
            float h = hid[j];
            c0 += h * s_cw1[k * 3 + 0];
            c1 += h * s_cw1[k * 3 + 1];
            c2 += h * s_cw1[k * 3 + 2];
        }
        c0 += __shfl_xor_sync(0xffffffffu, c0, 1);
        c0 += __shfl_xor_sync(0xffffffffu, c0, 2);
        c1 += __shfl_xor_sync(0xffffffffu, c1, 1);
        c1 += __shfl_xor_sync(0xffffffffu, c1, 2);
        c2 += __shfl_xor_sync(0xffffffffu, c2, 1);
        c2 += __shfl_xor_sync(0xffffffffu, c2, 2);

        int n = wt >> 13;
        int m = ((wt & 8191) << 3) + p8;
        size_t ub = B2 + ((size_t)n * MPTS + m) * 4;
        if (oq == 0) out[ub + 0] = (tanhf(c0 + s_cb1[0]) + 1.f) * 0.5f;
        else if (oq == 1) out[ub + 1] = (tanhf(c1 + s_cb1[1]) + 1.f) * 0.5f;
        else if (oq == 2) out[ub + 2] = (tanhf(c2 + s_cb1[2]) + 1.f) * 0.5f;
        else out[ub + 3] = (flag_cur != 0.f) ? 0.f : fmaxf(dens, 0.f);

        if (wt2 >= NTILES) break;
        wt = wt2;
        flag_cur = flag_next;
        __syncwarp();   // actA sample writes visible before next layer0
    }
}

// ---------------- composition over slots -----------------------------------
__global__ void compose_kernel(float* __restrict__ out) {
    int m = blockIdx.x * blockDim.x + threadIdx.x;
    if (m >= MPTS) return;
    const size_t B1 = (size_t)MPTS * 4;
    const size_t B2 = B1 + (size_t)NS * MPTS * 4;
    const size_t B3 = B2 + (size_t)NS * MPTS * 4;
    float4 um[NS];
    float s = 0.f;
#pragma unroll
    for (int n = 0; n < NS; n++) {
        um[n] = *(const float4*)&out[B2 + ((size_t)n * MPTS + m) * 4];
        s += um[n].w;
    }
    float denom = s + 1e-8f;
    float4 r = make_float4(0.f, 0.f, 0.f, 0.f);
#pragma unroll
    for (int n = 0; n < NS; n++) {
        float mk = um[n].w / denom;
        out[B3 + (size_t)n * MPTS + m] = mk;
        float4 md = make_float4(um[n].x * mk, um[n].y * mk, um[n].z * mk, um[n].w * mk);
        *(float4*)&out[B1 + ((size_t)n * MPTS + m) * 4] = md;
        r.x += md.x; r.y += md.y; r.z += md.z; r.w += md.w;
    }
    *(float4*)&out[(size_t)m * 4] = r;
}

// ---------------- launch ----------------------------------------------------
extern "C" void kernel_launch(void* const* d_in, const int* in_sizes, int n_in,
                              void* d_out, int out_size) {
    const float* coor = (const float*)d_in[0];
    const float* zs   = (const float*)d_in[1];
    const float* sp   = (const float*)d_in[2];
    const float* pos_w = (const float*)d_in[3];
    const float* pos_b = (const float*)d_in[4];
    const float* pe_w  = (const float*)d_in[5];
    const float* pe_b  = (const float*)d_in[6];
    const float* c1w = (const float*)d_in[7];
    const float* c1b = (const float*)d_in[8];
    const float* c2w = (const float*)d_in[9];
    const float* c2b = (const float*)d_in[10];
    const float* c3w = (const float*)d_in[11];
    const float* c3b = (const float*)d_in[12];
    const float* dw0 = (const float*)d_in[13];
    const float* db0 = (const float*)d_in[14];
    const float* dw1 = (const float*)d_in[15];
    const float* db1 = (const float*)d_in[16];
    const float* dnw = (const float*)d_in[17];
    const float* dnb = (const float*)d_in[18];
    const float* cw0 = (const float*)d_in[19];
    const float* cb0 = (const float*)d_in[20];
    const float* cw1 = (const float*)d_in[21];
    const float* cb1 = (const float*)d_in[22];
    float* out = (float*)d_out;

    float *fmap, *h1, *tri;
    cudaGetSymbolAddress((void**)&fmap, g_fmap);
    cudaGetSymbolAddress((void**)&h1, g_h1);
    cudaGetSymbolAddress((void**)&tri, g_tri);

    prep_kernel<<<1, 64>>>(zs, sp, pos_w, pos_b, pe_w, pe_b);
    prep2_kernel<<<1, 576>>>(c1w, c1b);
    conv1fill_kernel<<<NS * ZD, 512>>>(c1b);

    dim3 cg1(4, 16, NS * 4);
    conv_p_kernel<64, 4, true, false><<<cg1, 256>>>(h1, c2w, c2b, fmap);
    dim3 cg3(4, 16, NS * 6);
    conv_p_kernel<64, 6, false, true><<<cg3, 256>>>(fmap, c3w, c3b, tri);

    cudaFuncSetAttribute(decode_kernel, cudaFuncAttributeMaxDynamicSharedMemorySize, SMEM_BYTES);
    decode_kernel<<<148, 512, SMEM_BYTES>>>(
        coor, sp, dw0, db0, dw1, db1, dnw, dnb, cw0, cb0, cw1, cb1, out);

    compose_kernel<<<MPTS / 256, 256>>>(out);
}

// round 5
// speedup vs baseline: 2.3688x; 1.9094x over previous
#include <cuda_runtime.h>
#include <math.h>
#include <stdint.h>

#define RESO 128
#define NS 8
#define MPTS 65536
#define ZD 64
#define TD 32

typedef unsigned long long ull;

// ---------------- packed f32x2 helpers (convs) -----------------------------
__device__ __forceinline__ ull fma2(ull a, ull b, ull c) {
    ull d;
    asm("fma.rn.f32x2 %0, %1, %2, %3;" : "=l"(d) : "l"(a), "l"(b), "l"(c));
    return d;
}
__device__ __forceinline__ ull pk2(float v) {
    ull r;
    asm("mov.b64 %0, {%1, %1};" : "=l"(r) : "f"(v));
    return r;
}
__device__ __forceinline__ float2 upk2(ull a) {
    float2 r;
    asm("mov.b64 {%0, %1}, %2;" : "=f"(r.x), "=f"(r.y) : "l"(a));
    return r;
}

// ---------------- tf32 helpers ---------------------------------------------
__device__ __forceinline__ uint32_t tf32_hi(float x) {
    uint32_t u;
    asm("cvt.rna.tf32.f32 %0, %1;" : "=r"(u) : "f"(x));
    return u;
}
__device__ __forceinline__ void mma_tf32(float* c, uint32_t a0, uint32_t a1,
                                         uint32_t a2, uint32_t a3,
                                         uint32_t b0, uint32_t b1) {
    asm volatile(
        "mma.sync.aligned.m16n8k8.row.col.f32.tf32.tf32.f32 "
        "{%0,%1,%2,%3}, {%4,%5,%6,%7}, {%8,%9}, {%0,%1,%2,%3};"
        : "+f"(c[0]), "+f"(c[1]), "+f"(c[2]), "+f"(c[3])
        : "r"(a0), "r"(a1), "r"(a2), "r"(a3), "r"(b0), "r"(b1));
}

// ---------------- scratch (device globals) ---------------------------------
__device__ float g_fmap[NS * ZD * RESO * RESO];
__device__ float g_h1[NS * ZD * RESO * RESO];
__device__ float g_tri[(size_t)NS * 3 * RESO * RESO * TD]; // channel-last
__device__ float g_zb[NS * ZD];
__device__ float g_A[ZD];
__device__ float g_B[ZD];
__device__ float g_Wz[NS * ZD * 9];
__device__ float g_Wa[ZD * 9];
__device__ float g_Wb[ZD * 9];
__device__ float g_K0[NS * ZD];
__device__ float g_K1[ZD];
__device__ float g_K2[ZD];

// ---------------- prep ------------------------------------------------------
__global__ void prep_kernel(const float* __restrict__ zs, const float* __restrict__ sp,
                            const float* __restrict__ pw, const float* __restrict__ pb,
                            const float* __restrict__ pew, const float* __restrict__ peb) {
    int c = threadIdx.x;
    if (c < ZD) {
        g_A[c] = pew[0 * ZD + c] - pew[2 * ZD + c];
        g_B[c] = pew[1 * ZD + c] - pew[3 * ZD + c];
        for (int n = 0; n < NS; n++) {
            g_zb[n * ZD + c] = zs[n * ZD + c]
                + sp[n * 3 + 0] * pw[0 * ZD + c]
                + sp[n * 3 + 1] * pw[1 * ZD + c]
                + pb[c] + peb[c];
        }
    }
}

__global__ void prep2_kernel(const float* __restrict__ w1, const float* __restrict__ b1) {
    int id = threadIdx.x;
    const float s = 2.0f / RESO;
    if (id < ZD * 9) {
        int oc = id / 9, t = id % 9;
        float wa = 0.f, wb = 0.f;
        float wz[NS];
#pragma unroll
        for (int n = 0; n < NS; n++) wz[n] = 0.f;
        for (int ic = 0; ic < ZD; ic++) {
            float w = w1[((size_t)oc * ZD + ic) * 9 + t];
            wa += w * g_A[ic];
            wb += w * g_B[ic];
#pragma unroll
            for (int n = 0; n < NS; n++) wz[n] += w * g_zb[n * ZD + ic];
        }
        g_Wa[oc * 9 + t] = wa;
        g_Wb[oc * 9 + t] = wb;
        for (int n = 0; n < NS; n++) g_Wz[(n * ZD + oc) * 9 + t] = wz[n];
    }
    __syncthreads();
    if (id < ZD) {
        int oc = id;
        float k1 = 0.f, k2 = 0.f;
        float k0[NS];
        for (int n = 0; n < NS; n++) k0[n] = b1[oc];
        for (int t = 0; t < 9; t++) {
            float dx = (float)(t % 3 - 1), dy = (float)(t / 3 - 1);
            float wa = g_Wa[oc * 9 + t], wb = g_Wb[oc * 9 + t];
            k1 += wa;
            k2 += wb;
            for (int n = 0; n < NS; n++)
                k0[n] += g_Wz[(n * ZD + oc) * 9 + t] + s * dx * wa + s * dy * wb;
        }
        g_K1[oc] = k1;
        g_K2[oc] = k2;
        for (int n = 0; n < NS; n++) g_K0[n * ZD + oc] = k0[n];
    }
}

// ---------------- conv1: analytic fill -------------------------------------
__global__ __launch_bounds__(512) void conv1fill_kernel(const float* __restrict__ b1) {
    int noc = blockIdx.x;
    int oc = noc & 63;
    int tid = threadIdx.x;
    int x = tid & 127, rb = tid >> 7;
    const float s = 2.0f / RESO;

    float Wz9[9], Wa9[9], Wb9[9];
#pragma unroll
    for (int t = 0; t < 9; t++) {
        Wz9[t] = g_Wz[(size_t)noc * 9 + t];
        Wa9[t] = g_Wa[oc * 9 + t];
        Wb9[t] = g_Wb[oc * 9 + t];
    }
    float k0 = g_K0[noc], k1 = g_K1[oc], k2 = g_K2[oc], bias = b1[oc];

    float X = (2 * x - 127) * (1.0f / RESO);
    bool xin = (x >= 1) && (x <= 126);
    float* outb = g_h1 + (size_t)noc * RESO * RESO;

    for (int yi = 0; yi < 32; yi++) {
        int y = yi * 4 + rb;
        float Y = (2 * y - 127) * (1.0f / RESO);
        float val;
        if (xin && y >= 1 && y <= 126) {
            val = k0 + k1 * X + k2 * Y;
        } else {
            val = bias;
#pragma unroll
            for (int t = 0; t < 9; t++) {
                int dy = t / 3 - 1, dx = t % 3 - 1;
                int gy = y + dy, gx = x + dx;
                if (gy >= 0 && gy < RESO && gx >= 0 && gx < RESO)
                    val += Wz9[t] + Wa9[t] * (X + dx * s) + Wb9[t] * (Y + dy * s);
            }
        }
        outb[y * RESO + x] = fmaxf(val, 0.f);
    }
}

// ---------------- direct tiled 3x3 conv (fp32, f32x2) ----------------------
template <int IC, int OCG, bool RELU, bool SAMPLE_OUT>
__global__ __launch_bounds__(256, 3) void conv_p_kernel(const float* __restrict__ in,
                                                        const float* __restrict__ wt,
                                                        const float* __restrict__ bias,
                                                        float* __restrict__ out) {
    const int TW = 32, TH = 8, OCB = 16, ICB = 16;
    __shared__ float s_in[ICB][TH + 2][36];
    __shared__ float s_w[ICB][9][OCB];

    int x0 = blockIdx.x * TW;
    int y0 = blockIdx.y * TH;
    int n = blockIdx.z / OCG;
    int oc0 = (blockIdx.z % OCG) * OCB;
    int tid = threadIdx.x;
    int ocq = tid >> 6;
    int pxg = tid & 63;
    int xg = pxg & 7;
    int yy = pxg >> 3;

    ull acc[2][4];
#pragma unroll
    for (int jp = 0; jp < 2; jp++)
#pragma unroll
        for (int px = 0; px < 4; px++) acc[jp][px] = 0ULL;

    for (int ic0 = 0; ic0 < IC; ic0 += ICB) {
        for (int idx = tid; idx < ICB * (TH + 2) * 34; idx += 256) {
            int ici = idx / 340;
            int r = idx % 340;
            int ry = r / 34, rx = r % 34;
            int gy = y0 + ry - 1, gx = x0 + rx - 1;
            float v = 0.f;
            if (gy >= 0 && gy < RESO && gx >= 0 && gx < RESO)
                v = in[(((size_t)n * IC + ic0 + ici) * RESO + gy) * RESO + gx];
            s_in[ici][ry][rx] = v;
        }
        for (int idx = tid; idx < ICB * 9 * OCB; idx += 256) {
            int ici = idx / 144;
            int r = idx % 144;
            int k = r / 16, oci = r % 16;
            s_w[ici][k][oci] = wt[((size_t)(oc0 + oci) * IC + ic0 + ici) * 9 + k];
        }
        __syncthreads();

#pragma unroll 1
        for (int ici = 0; ici < ICB; ici++) {
            ull vv[3][6];
#pragma unroll
            for (int dy = 0; dy < 3; dy++) {
                float4 a = *(const float4*)&s_in[ici][yy + dy][4 * xg];
                float4 b = *(const float4*)&s_in[ici][yy + dy][4 * xg + 4];
                vv[dy][0] = pk2(a.x); vv[dy][1] = pk2(a.y); vv[dy][2] = pk2(a.z);
                vv[dy][3] = pk2(a.w); vv[dy][4] = pk2(b.x); vv[dy][5] = pk2(b.y);
            }
#pragma unroll
            for (int ky = 0; ky < 3; ky++)
#pragma unroll
                for (int kx = 0; kx < 3; kx++) {
                    ulonglong2 w2 = *(const ulonglong2*)&s_w[ici][ky * 3 + kx][ocq * 4];
#pragma unroll
                    for (int px = 0; px < 4; px++) {
                        acc[0][px] = fma2(w2.x, vv[ky][px + kx], acc[0][px]);
                        acc[1][px] = fma2(w2.y, vv[ky][px + kx], acc[1][px]);
                    }
                }
        }
        __syncthreads();
    }

    int y = y0 + yy;
#pragma unroll
    for (int jp = 0; jp < 2; jp++) {
        int ocA = oc0 + ocq * 4 + jp * 2;
        float bA = bias[ocA], bB = bias[ocA + 1];
#pragma unroll
        for (int px = 0; px < 4; px++) {
            float2 v = upk2(acc[jp][px]);
            float vA = v.x + bA, vB = v.y + bB;
            if (RELU) { vA = fmaxf(vA, 0.f); vB = fmaxf(vB, 0.f); }
            int x = x0 + 4 * xg + px;
            if (SAMPLE_OUT) {
                int plA = ocA >> 5, cA = ocA & 31;
                int plB = (ocA + 1) >> 5, cB = (ocA + 1) & 31;
                out[((((size_t)n * 3 + plA) * RESO + y) * RESO + x) * TD + cA] = vA;
                out[((((size_t)n * 3 + plB) * RESO + y) * RESO + x) * TD + cB] = vB;
            } else {
                out[(((size_t)n * (OCG * 16) + ocA) * RESO + y) * RESO + x] = vA;
                out[(((size_t)n * (OCG * 16) + ocA + 1) * RESO + y) * RESO + x] = vB;
            }
        }
    }
}

// ---------------- tensor-core (mma.sync tf32) fused decoder ----------------
#define AST 100                // activation row stride (floats)
#define OFF_A    0             // 256 x 100
#define OFF_B0   25600         // frag layout, 9216
#define OFF_B1   34816         // 9216
#define OFF_B2   44032         // 3072
#define OFF_BI0  47104         // 96
#define OFF_BI1  47200         // 96
#define OFF_BI2  47296         // 32
#define OFF_CW1  47328         // 72
#define OFF_CB1  47400         // 4
#define DEC_FLOATS 47404
#define DEC_SMEM (DEC_FLOATS * 4)
#define DTILES 2048            // NS*MPTS/256

// one MLP layer on tensor cores: rows [rowbase, rowbase+32) of sA (in-place ok)
template <int NT, bool RELU>
__device__ __forceinline__ void mlp_layer(const float* sA, float* dA,
                                          const float* sB, const float* sbias,
                                          int rowbase, int lane) {
    const int cl = 2 * (lane & 3);
    float acc[2][NT][4];
#pragma unroll
    for (int nt = 0; nt < NT; nt++) {
        float bv0 = sbias[nt * 8 + cl], bv1 = sbias[nt * 8 + cl + 1];
#pragma unroll
        for (int mt = 0; mt < 2; mt++) {
            acc[mt][nt][0] = bv0; acc[mt][nt][1] = bv1;
            acc[mt][nt][2] = bv0; acc[mt][nt][3] = bv1;
        }
    }
#pragma unroll
    for (int ks = 0; ks < 12; ks++) {
        uint32_t bf[NT][2];
#pragma unroll
        for (int nt = 0; nt < NT; nt++) {
            float2 b2 = *(const float2*)&sB[((ks * NT + nt) * 32 + lane) * 2];
            bf[nt][0] = __float_as_uint(b2.x);
            bf[nt][1] = __float_as_uint(b2.y);
        }
#pragma unroll
        for (int mt = 0; mt < 2; mt++) {
            const float* ap = sA + (rowbase + mt * 16 + (lane >> 2)) * AST + ks * 8 + (lane & 3);
            float x0 = ap[0], x2 = ap[4], x1 = ap[8 * AST], x3 = ap[8 * AST + 4];
            uint32_t h0 = tf32_hi(x0), h1 = tf32_hi(x1), h2 = tf32_hi(x2), h3 = tf32_hi(x3);
            uint32_t l0 = tf32_hi(x0 - __uint_as_float(h0));
            uint32_t l1 = tf32_hi(x1 - __uint_as_float(h1));
            uint32_t l2 = tf32_hi(x2 - __uint_as_float(h2));
            uint32_t l3 = tf32_hi(x3 - __uint_as_float(h3));
#pragma unroll
            for (int nt = 0; nt < NT; nt++) {
                mma_tf32(acc[mt][nt], h0, h1, h2, h3, bf[nt][0], bf[nt][1]);
                mma_tf32(acc[mt][nt], l0, l1, l2, l3, bf[nt][0], bf[nt][1]);
            }
        }
    }
#pragma unroll
    for (int mt = 0; mt < 2; mt++) {
        int r0 = rowbase + mt * 16 + (lane >> 2);
#pragma unroll
        for (int nt = 0; nt < NT; nt++) {
            int col = nt * 8 + cl;
            float a0 = acc[mt][nt][0], a1 = acc[mt][nt][1];
            float a2 = acc[mt][nt][2], a3 = acc[mt][nt][3];
            if (RELU) {
                a0 = fmaxf(a0, 0.f); a1 = fmaxf(a1, 0.f);
                a2 = fmaxf(a2, 0.f); a3 = fmaxf(a3, 0.f);
            }
            *(float2*)&dA[r0 * AST + col] = make_float2(a0, a1);
            *(float2*)&dA[(r0 + 8) * AST + col] = make_float2(a2, a3);
        }
    }
}

__global__ __launch_bounds__(256, 1) void decode_kernel(
    const float* __restrict__ coor, const float* __restrict__ spos,
    const float* __restrict__ w0, const float* __restrict__ b0,
    const float* __restrict__ w1, const float* __restrict__ b1,
    const float* __restrict__ dw, const float* __restrict__ db,
    const float* __restrict__ cw0, const float* __restrict__ cb0,
    const float* __restrict__ cw1, const float* __restrict__ cb1,
    float* __restrict__ out) {
    extern __shared__ float sm[];
    float* sA = sm + OFF_A;
    float* sB0 = sm + OFF_B0;
    float* sB1 = sm + OFF_B1;
    float* sB2 = sm + OFF_B2;
    float* sbi0 = sm + OFF_BI0;
    float* sbi1 = sm + OFF_BI1;
    float* sbi2 = sm + OFF_BI2;
    float* scw1 = sm + OFF_CW1;
    float* scb1 = sm + OFF_CB1;

    int tid = threadIdx.x;
    int wid = tid >> 5, lane = tid & 31;

    // ---- stage weights in B-fragment layout (tf32-rounded) ----
    for (int idx = tid; idx < 96 * 96; idx += 256) {
        int k = idx / 96, n = idx % 96;
        int lfr = (n & 7) * 4 + (k & 3);
        int reg = (k & 7) >> 2;
        int off = (((k >> 3) * 12 + (n >> 3)) * 32 + lfr) * 2 + reg;
        sB0[off] = __uint_as_float(tf32_hi(w0[idx]));
        sB1[off] = __uint_as_float(tf32_hi(w1[idx]));
    }
    // layer2 fused [dens | cw0 | pad]: col0=dens, 1..24=cw0, 25..31=0
    for (int idx = tid; idx < 96 * 32; idx += 256) {
        int k = idx / 32, n = idx % 32;
        float v = (n == 0) ? dw[k] : ((n <= 24) ? cw0[k * 24 + n - 1] : 0.f);
        int lfr = (n & 7) * 4 + (k & 3);
        int reg = (k & 7) >> 2;
        int off = (((k >> 3) * 4 + (n >> 3)) * 32 + lfr) * 2 + reg;
        sB2[off] = __uint_as_float(tf32_hi(v));
    }
    if (tid < 96) { sbi0[tid] = b0[tid]; sbi1[tid] = b1[tid]; }
    if (tid < 32) sbi2[tid] = (tid == 0) ? db[0] : ((tid <= 24) ? cb0[tid - 1] : 0.f);
    if (tid < 72) scw1[tid] = cw1[tid];
    if (tid < 3) scb1[tid] = cb1[tid];
    __syncthreads();

    const int rowbase = wid * 32;
    const int myrow = rowbase + lane;
    const size_t B2o = (size_t)MPTS * 4 + (size_t)NS * MPTS * 4;

    for (int t = blockIdx.x; t < DTILES; t += gridDim.x) {
        int n = t >> 8;
        int m = ((t & 255) << 8) + myrow;

        // ---- sample 3 planes into own row of sA ----
        float rx = coor[((size_t)n * MPTS + m) * 3 + 0] - spos[n * 3 + 0];
        float ry = coor[((size_t)n * MPTS + m) * 3 + 1] - spos[n * 3 + 1];
        float rz = coor[((size_t)n * MPTS + m) * 3 + 2] - spos[n * 3 + 2];
        bool outsider = (fabsf(rx) > 1.f || fabsf(ry) > 1.f || fabsf(rz) > 1.f);

#pragma unroll
        for (int p = 0; p < 3; p++) {
            float cu, cv;
            if (p == 0) { cu = rx; cv = ry; }
            else if (p == 1) { cu = rx; cv = rz; }
            else { cu = rz; cv = rx; }
            float u = (cu + 1.f) * 64.f - 0.5f;
            float v = (cv + 1.f) * 64.f - 0.5f;
            float fx = floorf(u), fy = floorf(v);
            float wx = u - fx, wy = v - fy;
            int ix0 = (int)fx, iy0 = (int)fy;
            float wts[4] = {(1 - wx) * (1 - wy), wx * (1 - wy), (1 - wx) * wy, wx * wy};
            int xs[4] = {ix0, ix0 + 1, ix0, ix0 + 1};
            int ys[4] = {iy0, iy0, iy0 + 1, iy0 + 1};
            float4 f[8];
#pragma unroll
            for (int k = 0; k < 8; k++) f[k] = make_float4(0.f, 0.f, 0.f, 0.f);
            size_t pb = ((size_t)n * 3 + p) * RESO * RESO;
#pragma unroll
            for (int tt = 0; tt < 4; tt++) {
                if (xs[tt] >= 0 && xs[tt] < RESO && ys[tt] >= 0 && ys[tt] < RESO) {
                    const float4* tp = (const float4*)&g_tri[(pb + (size_t)ys[tt] * RESO + xs[tt]) * TD];
                    float wv = wts[tt];
#pragma unroll
                    for (int k = 0; k < 8; k++) {
                        float4 d = tp[k];
                        f[k].x += wv * d.x; f[k].y += wv * d.y;
                        f[k].z += wv * d.z; f[k].w += wv * d.w;
                    }
                }
            }
            float4* dst = (float4*)&sA[myrow * AST + p * 32];
#pragma unroll
            for (int k = 0; k < 8; k++) dst[k] = f[k];
        }
        __syncwarp();

        // ---- 3 tensor-core layers (warp-local) ----
        mlp_layer<12, true>(sA, sA, sB0, sbi0, rowbase, lane);
        __syncwarp();
        mlp_layer<12, true>(sA, sA, sB1, sbi1, rowbase, lane);
        __syncwarp();
        mlp_layer<4, false>(sA, sA, sB2, sbi2, rowbase, lane);
        __syncwarp();

        // ---- final epilogue: own row -> rgb + mask ----
        {
            const float* v = &sA[myrow * AST];
            float dens = v[0];
            float c0 = scb1[0], c1 = scb1[1], c2 = scb1[2];
#pragma unroll
            for (int j = 0; j < 24; j++) {
                float h = fmaxf(v[1 + j], 0.f);
                c0 += h * scw1[j * 3 + 0];
                c1 += h * scw1[j * 3 + 1];
                c2 += h * scw1[j * 3 + 2];
            }
            float rawmask = outsider ? 0.f : fmaxf(dens, 0.f);
            float4 o = make_float4((tanhf(c0) + 1.f) * 0.5f, (tanhf(c1) + 1.f) * 0.5f,
                                   (tanhf(c2) + 1.f) * 0.5f, rawmask);
            *(float4*)&out[B2o + ((size_t)n * MPTS + m) * 4] = o;
        }
        __syncwarp();
    }
}

// ---------------- composition over slots -----------------------------------
__global__ void compose_kernel(float* __restrict__ out) {
    int m = blockIdx.x * blockDim.x + threadIdx.x;
    if (m >= MPTS) return;
    const size_t B1 = (size_t)MPTS * 4;
    const size_t B2 = B1 + (size_t)NS * MPTS * 4;
    const size_t B3 = B2 + (size_t)NS * MPTS * 4;
    float4 um[NS];
    float s = 0.f;
#pragma unroll
    for (int n = 0; n < NS; n++) {
        um[n] = *(const float4*)&out[B2 + ((size_t)n * MPTS + m) * 4];
        s += um[n].w;
    }
    float denom = s + 1e-8f;
    float4 rr = make_float4(0.f, 0.f, 0.f, 0.f);
#pragma unroll
    for (int n = 0; n < NS; n++) {
        float mk = um[n].w / denom;
        out[B3 + (size_t)n * MPTS + m] = mk;
        float4 md = make_float4(um[n].x * mk, um[n].y * mk, um[n].z * mk, um[n].w * mk);
        *(float4*)&out[B1 + ((size_t)n * MPTS + m) * 4] = md;
        rr.x += md.x; rr.y += md.y; rr.z += md.z; rr.w += md.w;
    }
    *(float4*)&out[(size_t)m * 4] = rr;
}

// ---------------- launch ----------------------------------------------------
extern "C" void kernel_launch(void* const* d_in, const int* in_sizes, int n_in,
                              void* d_out, int out_size) {
    const float* coor = (const float*)d_in[0];
    const float* zs   = (const float*)d_in[1];
    const float* sp   = (const float*)d_in[2];
    const float* pos_w = (const float*)d_in[3];
    const float* pos_b = (const float*)d_in[4];
    const float* pe_w  = (const float*)d_in[5];
    const float* pe_b  = (const float*)d_in[6];
    const float* c1w = (const float*)d_in[7];
    const float* c1b = (const float*)d_in[8];
    const float* c2w = (const float*)d_in[9];
    const float* c2b = (const float*)d_in[10];
    const float* c3w = (const float*)d_in[11];
    const float* c3b = (const float*)d_in[12];
    const float* dw0 = (const float*)d_in[13];
    const float* db0 = (const float*)d_in[14];
    const float* dw1 = (const float*)d_in[15];
    const float* db1 = (const float*)d_in[16];
    const float* dnw = (const float*)d_in[17];
    const float* dnb = (const float*)d_in[18];
    const float* cw0 = (const float*)d_in[19];
    const float* cb0 = (const float*)d_in[20];
    const float* cw1 = (const float*)d_in[21];
    const float* cb1 = (const float*)d_in[22];
    float* out = (float*)d_out;

    float *fmap, *h1, *tri;
    cudaGetSymbolAddress((void**)&fmap, g_fmap);
    cudaGetSymbolAddress((void**)&h1, g_h1);
    cudaGetSymbolAddress((void**)&tri, g_tri);

    prep_kernel<<<1, 64>>>(zs, sp, pos_w, pos_b, pe_w, pe_b);
    prep2_kernel<<<1, 576>>>(c1w, c1b);
    conv1fill_kernel<<<NS * ZD, 512>>>(c1b);

    dim3 cg1(4, 16, NS * 4);
    conv_p_kernel<64, 4, true, false><<<cg1, 256>>>(h1, c2w, c2b, fmap);
    dim3 cg3(4, 16, NS * 6);
    conv_p_kernel<64, 6, false, true><<<cg3, 256>>>(fmap, c3w, c3b, tri);

    cudaFuncSetAttribute(decode_kernel, cudaFuncAttributeMaxDynamicSharedMemorySize, DEC_SMEM);
    decode_kernel<<<148, 256, DEC_SMEM>>>(
        coor, sp, dw0, db0, dw1, db1, dnw, dnb, cw0, cb0, cw1, cb1, out);

    compose_kernel<<<MPTS / 256, 256>>>(out);
}

// round 6
// speedup vs baseline: 3.9723x; 1.6769x over previous
#include <cuda_runtime.h>
#include <math.h>
#include <stdint.h>

#define RESO 128
#define NS 8
#define MPTS 65536
#define ZD 64
#define TD 32

typedef unsigned long long ull;

// ---------------- tf32 helpers ---------------------------------------------
__device__ __forceinline__ uint32_t tf32_hi(float x) {
    uint32_t u;
    asm("cvt.rna.tf32.f32 %0, %1;" : "=r"(u) : "f"(x));
    return u;
}
__device__ __forceinline__ void mma_tf32(float* c, uint32_t a0, uint32_t a1,
                                         uint32_t a2, uint32_t a3,
                                         uint32_t b0, uint32_t b1) {
    asm volatile(
        "mma.sync.aligned.m16n8k8.row.col.f32.tf32.tf32.f32 "
        "{%0,%1,%2,%3}, {%4,%5,%6,%7}, {%8,%9}, {%0,%1,%2,%3};"
        : "+f"(c[0]), "+f"(c[1]), "+f"(c[2]), "+f"(c[3])
        : "r"(a0), "r"(a1), "r"(a2), "r"(a3), "r"(b0), "r"(b1));
}

// ---------------- scratch (device globals) ---------------------------------
__device__ float g_fmap[NS * RESO * RESO * ZD];            // conv2 out, channel-last
__device__ float g_tri[(size_t)NS * 3 * RESO * RESO * TD]; // channel-last triplane
__device__ float g_zb[NS * ZD];
__device__ float g_A[ZD];
__device__ float g_B[ZD];
__device__ float g_Wz[NS * ZD * 9];
__device__ float g_Wa[ZD * 9];
__device__ float g_Wb[ZD * 9];
__device__ float g_K0[NS * ZD];
__device__ float g_K1[ZD];
__device__ float g_K2[ZD];
__device__ float g_wf2[9 * 64 * 64];   // conv2 weights, B-fragment layout per tap
__device__ float g_wf3[9 * 64 * 96];   // conv3 weights, B-fragment layout per tap

// ---------------- prep ------------------------------------------------------
__global__ void prep_kernel(const float* __restrict__ zs, const float* __restrict__ sp,
                            const float* __restrict__ pw, const float* __restrict__ pb,
                            const float* __restrict__ pew, const float* __restrict__ peb) {
    int c = threadIdx.x;
    if (c < ZD) {
        g_A[c] = pew[0 * ZD + c] - pew[2 * ZD + c];
        g_B[c] = pew[1 * ZD + c] - pew[3 * ZD + c];
        for (int n = 0; n < NS; n++) {
            g_zb[n * ZD + c] = zs[n * ZD + c]
                + sp[n * 3 + 0] * pw[0 * ZD + c]
                + sp[n * 3 + 1] * pw[1 * ZD + c]
                + pb[c] + peb[c];
        }
    }
}

__global__ void prep2_kernel(const float* __restrict__ w1, const float* __restrict__ b1) {
    int id = threadIdx.x;
    const float s = 2.0f / RESO;
    if (id < ZD * 9) {
        int oc = id / 9, t = id % 9;
        float wa = 0.f, wb = 0.f;
        float wz[NS];
#pragma unroll
        for (int n = 0; n < NS; n++) wz[n] = 0.f;
        for (int ic = 0; ic < ZD; ic++) {
            float w = w1[((size_t)oc * ZD + ic) * 9 + t];
            wa += w * g_A[ic];
            wb += w * g_B[ic];
#pragma unroll
            for (int n = 0; n < NS; n++) wz[n] += w * g_zb[n * ZD + ic];
        }
        g_Wa[oc * 9 + t] = wa;
        g_Wb[oc * 9 + t] = wb;
        for (int n = 0; n < NS; n++) g_Wz[(n * ZD + oc) * 9 + t] = wz[n];
    }
    __syncthreads();
    if (id < ZD) {
        int oc = id;
        float k1 = 0.f, k2 = 0.f;
        float k0[NS];
        for (int n = 0; n < NS; n++) k0[n] = b1[oc];
        for (int t = 0; t < 9; t++) {
            float dx = (float)(t % 3 - 1), dy = (float)(t / 3 - 1);
            float wa = g_Wa[oc * 9 + t], wb = g_Wb[oc * 9 + t];
            k1 += wa;
            k2 += wb;
            for (int n = 0; n < NS; n++)
                k0[n] += g_Wz[(n * ZD + oc) * 9 + t] + s * dx * wa + s * dy * wb;
        }
        g_K1[oc] = k1;
        g_K2[oc] = k2;
        for (int n = 0; n < NS; n++) g_K0[n * ZD + oc] = k0[n];
    }
}

// weights -> B-fragment layout (tf32-rounded). conv2: NT=8, conv3: NT=12.
__global__ void prep3_kernel(const float* __restrict__ c2w, const float* __restrict__ c3w) {
    int idx = blockIdx.x * blockDim.x + threadIdx.x;
    if (idx < 9 * 64 * 64) {
        int t = idx / 4096, r = idx % 4096;
        int k = r / 64, n = r % 64;
        int lfr = (n & 7) * 4 + (k & 3);
        int reg = (k & 7) >> 2;
        int off = (((k >> 3) * 8 + (n >> 3)) * 32 + lfr) * 2 + reg;
        g_wf2[t * 4096 + off] = __uint_as_float(tf32_hi(c2w[(size_t)n * 576 + k * 9 + t]));
    } else if (idx < 9 * 64 * 64 + 9 * 64 * 96) {
        int j = idx - 9 * 64 * 64;
        int t = j / 6144, r = j % 6144;
        int k = r / 96, n = r % 96;
        int lfr = (n & 7) * 4 + (k & 3);
        int reg = (k & 7) >> 2;
        int off = (((k >> 3) * 12 + (n >> 3)) * 32 + lfr) * 2 + reg;
        g_wf3[t * 6144 + off] = __uint_as_float(tf32_hi(c3w[(size_t)n * 576 + k * 9 + t]));
    }
}

// ---------------- tensor-core implicit-GEMM 3x3 conv -----------------------
// Block: 128 threads (4 warps). Tile: 32 (x) x 4 (y) pixels, all NOC outputs.
// Warp w owns y-row w; A rows = x. Input staged channel-last in smem.
#define XST 68
#define YST (34 * XST)
#define SIN_FLOATS (6 * YST)

template <int NOC, bool FUSED, bool TRI>
__global__ __launch_bounds__(128, 2) void conv_tc_kernel(
    const float* __restrict__ wf, const float* __restrict__ bias,
    const float* __restrict__ c1b, float* __restrict__ out) {
    constexpr int NT = NOC / 8;
    extern __shared__ float sh[];
    float* s_in = sh;                      // 6 x 34 x (64 + 4 pad)
    float* s_B = sh + SIN_FLOATS;          // NOC * 64 (one tap, frag layout)
    float* s_bias = s_B + NOC * 64;        // NOC

    const int tid = threadIdx.x;
    const int w = tid >> 5, lane = tid & 31;
    const int x0 = blockIdx.x * 32, y0 = blockIdx.y * 4;
    const int n = blockIdx.z;

    if (tid < NOC) s_bias[tid] = bias[tid];

    // ---- stage input tile (+halo), channel-last, fp32 exact ----
    const float sgrid = 2.0f / RESO;
    for (int idx = tid; idx < 6 * 34 * 16; idx += 128) {
        int yi = idx / (34 * 16);
        int rem = idx % (34 * 16);
        int xi = rem / 16, icq = rem % 16;
        int ic4 = icq * 4;
        int gy = y0 + yi - 1, gx = x0 + xi - 1;
        float4 v = make_float4(0.f, 0.f, 0.f, 0.f);
        if (gy >= 0 && gy < RESO && gx >= 0 && gx < RESO) {
            if (FUSED) {
                // conv1 output computed analytically
                float X = (2 * gx - 127) * (1.0f / RESO);
                float Y = (2 * gy - 127) * (1.0f / RESO);
                if (gx >= 1 && gx <= 126 && gy >= 1 && gy <= 126) {
                    float4 k0 = *(const float4*)&g_K0[n * ZD + ic4];
                    float4 k1 = *(const float4*)&g_K1[ic4];
                    float4 k2 = *(const float4*)&g_K2[ic4];
                    v.x = fmaxf(k0.x + k1.x * X + k2.x * Y, 0.f);
                    v.y = fmaxf(k0.y + k1.y * X + k2.y * Y, 0.f);
                    v.z = fmaxf(k0.z + k1.z * X + k2.z * Y, 0.f);
                    v.w = fmaxf(k0.w + k1.w * X + k2.w * Y, 0.f);
                } else {
                    float vv[4];
#pragma unroll
                    for (int c = 0; c < 4; c++) {
                        int ic = ic4 + c;
                        float val = c1b[ic];
#pragma unroll
                        for (int t9 = 0; t9 < 9; t9++) {
                            int dyb = t9 / 3 - 1, dxb = t9 % 3 - 1;
                            int gy2 = gy + dyb, gx2 = gx + dxb;
                            if (gy2 >= 0 && gy2 < RESO && gx2 >= 0 && gx2 < RESO)
                                val += g_Wz[((size_t)n * ZD + ic) * 9 + t9]
                                     + g_Wa[ic * 9 + t9] * (X + dxb * sgrid)
                                     + g_Wb[ic * 9 + t9] * (Y + dyb * sgrid);
                        }
                        vv[c] = fmaxf(val, 0.f);
                    }
                    v = make_float4(vv[0], vv[1], vv[2], vv[3]);
                }
            } else {
                v = *(const float4*)&g_fmap[(((size_t)n * RESO + gy) * RESO + gx) * ZD + ic4];
            }
        }
        *(float4*)&s_in[yi * YST + xi * XST + ic4] = v;
    }

    float acc[2][NT][4];
#pragma unroll
    for (int mt = 0; mt < 2; mt++)
#pragma unroll
        for (int nt = 0; nt < NT; nt++)
#pragma unroll
            for (int j = 0; j < 4; j++) acc[mt][nt][j] = 0.f;

    const int q = lane & 3, hr = lane >> 2;

#pragma unroll 1
    for (int t = 0; t < 9; t++) {
        int dy = t / 3, dx = t % 3;
        __syncthreads();
        // stage this tap's weights (already fragment-layout in gmem)
        const float4* src = (const float4*)(wf + t * (NOC * 64));
        for (int i = tid; i < NOC * 16; i += 128) ((float4*)s_B)[i] = src[i];
        __syncthreads();

#pragma unroll
        for (int icc = 0; icc < 8; icc++) {
            float2 bf[NT];
#pragma unroll
            for (int nt = 0; nt < NT; nt++)
                bf[nt] = *(const float2*)&s_B[(icc * NT + nt) * 64 + lane * 2];
#pragma unroll
            for (int mt = 0; mt < 2; mt++) {
                const float* ap = s_in + (w + dy) * YST + (mt * 16 + hr + dx) * XST + icc * 8 + q;
                float x0v = ap[0], x1v = ap[8 * XST], x2v = ap[4], x3v = ap[8 * XST + 4];
                uint32_t h0 = tf32_hi(x0v), h1 = tf32_hi(x1v);
                uint32_t h2 = tf32_hi(x2v), h3 = tf32_hi(x3v);
                uint32_t l0 = tf32_hi(x0v - __uint_as_float(h0));
                uint32_t l1 = tf32_hi(x1v - __uint_as_float(h1));
                uint32_t l2 = tf32_hi(x2v - __uint_as_float(h2));
                uint32_t l3 = tf32_hi(x3v - __uint_as_float(h3));
#pragma unroll
                for (int nt = 0; nt < NT; nt++) {
                    uint32_t b0 = __float_as_uint(bf[nt].x), b1 = __float_as_uint(bf[nt].y);
                    mma_tf32(acc[mt][nt], h0, h1, h2, h3, b0, b1);
                    mma_tf32(acc[mt][nt], l0, l1, l2, l3, b0, b1);
                }
            }
        }
    }

    // ---- epilogue ----
    const int y = y0 + w;
    const int cl = 2 * (lane & 3);
#pragma unroll
    for (int mt = 0; mt < 2; mt++) {
        int xa = x0 + mt * 16 + hr;
#pragma unroll
        for (int nt = 0; nt < NT; nt++) {
            int col = nt * 8 + cl;
            float bv0 = s_bias[col], bv1 = s_bias[col + 1];
            float v0 = acc[mt][nt][0] + bv0, v1 = acc[mt][nt][1] + bv1;
            float v2 = acc[mt][nt][2] + bv0, v3 = acc[mt][nt][3] + bv1;
            if (!TRI) {  // conv2: relu, channel-last fmap
                v0 = fmaxf(v0, 0.f); v1 = fmaxf(v1, 0.f);
                v2 = fmaxf(v2, 0.f); v3 = fmaxf(v3, 0.f);
                *(float2*)&out[(((size_t)n * RESO + y) * RESO + xa) * ZD + col] = make_float2(v0, v1);
                *(float2*)&out[(((size_t)n * RESO + y) * RESO + xa + 8) * ZD + col] = make_float2(v2, v3);
            } else {     // conv3: triplane channel-last
                int plane = col >> 5, c = col & 31;
                size_t pb = (((size_t)n * 3 + plane) * RESO * RESO);
                *(float2*)&out[(pb + (size_t)y * RESO + xa) * TD + c] = make_float2(v0, v1);
                *(float2*)&out[(pb + (size_t)y * RESO + xa + 8) * TD + c] = make_float2(v2, v3);
            }
        }
    }
}

// ---------------- tensor-core (mma.sync tf32) fused decoder ----------------
#define AST 100
#define OFF_A    0
#define OFF_B0   25600
#define OFF_B1   34816
#define OFF_B2   44032
#define OFF_BI0  47104
#define OFF_BI1  47200
#define OFF_BI2  47296
#define OFF_CW1  47328
#define OFF_CB1  47400
#define DEC_FLOATS 47404
#define DEC_SMEM (DEC_FLOATS * 4)
#define DTILES 2048

template <int NT, bool RELU>
__device__ __forceinline__ void mlp_layer(const float* sA, float* dA,
                                          const float* sB, const float* sbias,
                                          int rowbase, int lane) {
    const int cl = 2 * (lane & 3);
    float acc[2][NT][4];
#pragma unroll
    for (int nt = 0; nt < NT; nt++) {
        float bv0 = sbias[nt * 8 + cl], bv1 = sbias[nt * 8 + cl + 1];
#pragma unroll
        for (int mt = 0; mt < 2; mt++) {
            acc[mt][nt][0] = bv0; acc[mt][nt][1] = bv1;
            acc[mt][nt][2] = bv0; acc[mt][nt][3] = bv1;
        }
    }
#pragma unroll
    for (int ks = 0; ks < 12; ks++) {
        uint32_t bf[NT][2];
#pragma unroll
        for (int nt = 0; nt < NT; nt++) {
            float2 b2 = *(const float2*)&sB[((ks * NT + nt) * 32 + lane) * 2];
            bf[nt][0] = __float_as_uint(b2.x);
            bf[nt][1] = __float_as_uint(b2.y);
        }
#pragma unroll
        for (int mt = 0; mt < 2; mt++) {
            const float* ap = sA + (rowbase + mt * 16 + (lane >> 2)) * AST + ks * 8 + (lane & 3);
            float x0 = ap[0], x2 = ap[4], x1 = ap[8 * AST], x3 = ap[8 * AST + 4];
            uint32_t h0 = tf32_hi(x0), h1 = tf32_hi(x1), h2 = tf32_hi(x2), h3 = tf32_hi(x3);
            uint32_t l0 = tf32_hi(x0 - __uint_as_float(h0));
            uint32_t l1 = tf32_hi(x1 - __uint_as_float(h1));
            uint32_t l2 = tf32_hi(x2 - __uint_as_float(h2));
            uint32_t l3 = tf32_hi(x3 - __uint_as_float(h3));
#pragma unroll
            for (int nt = 0; nt < NT; nt++) {
                mma_tf32(acc[mt][nt], h0, h1, h2, h3, bf[nt][0], bf[nt][1]);
                mma_tf32(acc[mt][nt], l0, l1, l2, l3, bf[nt][0], bf[nt][1]);
            }
        }
    }
#pragma unroll
    for (int mt = 0; mt < 2; mt++) {
        int r0 = rowbase + mt * 16 + (lane >> 2);
#pragma unroll
        for (int nt = 0; nt < NT; nt++) {
            int col = nt * 8 + cl;
            float a0 = acc[mt][nt][0], a1 = acc[mt][nt][1];
            float a2 = acc[mt][nt][2], a3 = acc[mt][nt][3];
            if (RELU) {
                a0 = fmaxf(a0, 0.f); a1 = fmaxf(a1, 0.f);
                a2 = fmaxf(a2, 0.f); a3 = fmaxf(a3, 0.f);
            }
            *(float2*)&dA[r0 * AST + col] = make_float2(a0, a1);
            *(float2*)&dA[(r0 + 8) * AST + col] = make_float2(a2, a3);
        }
    }
}

__global__ __launch_bounds__(256, 1) void decode_kernel(
    const float* __restrict__ coor, const float* __restrict__ spos,
    const float* __restrict__ w0, const float* __restrict__ b0,
    const float* __restrict__ w1, const float* __restrict__ b1,
    const float* __restrict__ dw, const float* __restrict__ db,
    const float* __restrict__ cw0, const float* __restrict__ cb0,
    const float* __restrict__ cw1, const float* __restrict__ cb1,
    float* __restrict__ out) {
    extern __shared__ float sm[];
    float* sA = sm + OFF_A;
    float* sB0 = sm + OFF_B0;
    float* sB1 = sm + OFF_B1;
    float* sB2 = sm + OFF_B2;
    float* sbi0 = sm + OFF_BI0;
    float* sbi1 = sm + OFF_BI1;
    float* sbi2 = sm + OFF_BI2;
    float* scw1 = sm + OFF_CW1;
    float* scb1 = sm + OFF_CB1;

    int tid = threadIdx.x;
    int wid = tid >> 5, lane = tid & 31;

    for (int idx = tid; idx < 96 * 96; idx += 256) {
        int k = idx / 96, n = idx % 96;
        int lfr = (n & 7) * 4 + (k & 3);
        int reg = (k & 7) >> 2;
        int off = (((k >> 3) * 12 + (n >> 3)) * 32 + lfr) * 2 + reg;
        sB0[off] = __uint_as_float(tf32_hi(w0[idx]));
        sB1[off] = __uint_as_float(tf32_hi(w1[idx]));
    }
    for (int idx = tid; idx < 96 * 32; idx += 256) {
        int k = idx / 32, n = idx % 32;
        float v = (n == 0) ? dw[k] : ((n <= 24) ? cw0[k * 24 + n - 1] : 0.f);
        int lfr = (n & 7) * 4 + (k & 3);
        int reg = (k & 7) >> 2;
        int off = (((k >> 3) * 4 + (n >> 3)) * 32 + lfr) * 2 + reg;
        sB2[off] = __uint_as_float(tf32_hi(v));
    }
    if (tid < 96) { sbi0[tid] = b0[tid]; sbi1[tid] = b1[tid]; }
    if (tid < 32) sbi2[tid] = (tid == 0) ? db[0] : ((tid <= 24) ? cb0[tid - 1] : 0.f);
    if (tid < 72) scw1[tid] = cw1[tid];
    if (tid < 3) scb1[tid] = cb1[tid];
    __syncthreads();

    const int rowbase = wid * 32;
    const int myrow = rowbase + lane;
    const size_t B2o = (size_t)MPTS * 4 + (size_t)NS * MPTS * 4;

    for (int t = blockIdx.x; t < DTILES; t += gridDim.x) {
        int n = t >> 8;
        int m = ((t & 255) << 8) + myrow;

        float rx = coor[((size_t)n * MPTS + m) * 3 + 0] - spos[n * 3 + 0];
        float ry = coor[((size_t)n * MPTS + m) * 3 + 1] - spos[n * 3 + 1];
        float rz = coor[((size_t)n * MPTS + m) * 3 + 2] - spos[n * 3 + 2];
        bool outsider = (fabsf(rx) > 1.f || fabsf(ry) > 1.f || fabsf(rz) > 1.f);

#pragma unroll
        for (int p = 0; p < 3; p++) {
            float cu, cv;
            if (p == 0) { cu = rx; cv = ry; }
            else if (p == 1) { cu = rx; cv = rz; }
            else { cu = rz; cv = rx; }
            float u = (cu + 1.f) * 64.f - 0.5f;
            float v = (cv + 1.f) * 64.f - 0.5f;
            float fx = floorf(u), fy = floorf(v);
            float wx = u - fx, wy = v - fy;
            int ix0 = (int)fx, iy0 = (int)fy;
            float wts[4] = {(1 - wx) * (1 - wy), wx * (1 - wy), (1 - wx) * wy, wx * wy};
            int xs[4] = {ix0, ix0 + 1, ix0, ix0 + 1};
            int ys[4] = {iy0, iy0, iy0 + 1, iy0 + 1};
            float4 f[8];
#pragma unroll
            for (int k = 0; k < 8; k++) f[k] = make_float4(0.f, 0.f, 0.f, 0.f);
            size_t pb = ((size_t)n * 3 + p) * RESO * RESO;
#pragma unroll
            for (int tt = 0; tt < 4; tt++) {
                if (xs[tt] >= 0 && xs[tt] < RESO && ys[tt] >= 0 && ys[tt] < RESO) {
                    const float4* tp = (const float4*)&g_tri[(pb + (size_t)ys[tt] * RESO + xs[tt]) * TD];
                    float wv = wts[tt];
#pragma unroll
                    for (int k = 0; k < 8; k++) {
                        float4 d = tp[k];
                        f[k].x += wv * d.x; f[k].y += wv * d.y;
                        f[k].z += wv * d.z; f[k].w += wv * d.w;
                    }
                }
            }
            float4* dst = (float4*)&sA[myrow * AST + p * 32];
#pragma unroll
            for (int k = 0; k < 8; k++) dst[k] = f[k];
        }
        __syncwarp();

        mlp_layer<12, true>(sA, sA, sB0, sbi0, rowbase, lane);
        __syncwarp();
        mlp_layer<12, true>(sA, sA, sB1, sbi1, rowbase, lane);
        __syncwarp();
        mlp_layer<4, false>(sA, sA, sB2, sbi2, rowbase, lane);
        __syncwarp();

        {
            const float* v = &sA[myrow * AST];
            float dens = v[0];
            float c0 = scb1[0], c1 = scb1[1], c2 = scb1[2];
#pragma unroll
            for (int j = 0; j < 24; j++) {
                float h = fmaxf(v[1 + j], 0.f);
                c0 += h * scw1[j * 3 + 0];
                c1 += h * scw1[j * 3 + 1];
                c2 += h * scw1[j * 3 + 2];
            }
            float rawmask = outsider ? 0.f : fmaxf(dens, 0.f);
            float4 o = make_float4((tanhf(c0) + 1.f) * 0.5f, (tanhf(c1) + 1.f) * 0.5f,
                                   (tanhf(c2) + 1.f) * 0.5f, rawmask);
            *(float4*)&out[B2o + ((size_t)n * MPTS + m) * 4] = o;
        }
        __syncwarp();
    }
}

// ---------------- composition over slots -----------------------------------
__global__ void compose_kernel(float* __restrict__ out) {
    int m = blockIdx.x * blockDim.x + threadIdx.x;
    if (m >= MPTS) return;
    const size_t B1 = (size_t)MPTS * 4;
    const size_t B2 = B1 + (size_t)NS * MPTS * 4;
    const size_t B3 = B2 + (size_t)NS * MPTS * 4;
    float4 um[NS];
    float s = 0.f;
#pragma unroll
    for (int n = 0; n < NS; n++) {
        um[n] = *(const float4*)&out[B2 + ((size_t)n * MPTS + m) * 4];
        s += um[n].w;
    }
    float denom = s + 1e-8f;
    float4 rr = make_float4(0.f, 0.f, 0.f, 0.f);
#pragma unroll
    for (int n = 0; n < NS; n++) {
        float mk = um[n].w / denom;
        out[B3 + (size_t)n * MPTS + m] = mk;
        float4 md = make_float4(um[n].x * mk, um[n].y * mk, um[n].z * mk, um[n].w * mk);
        *(float4*)&out[B1 + ((size_t)n * MPTS + m) * 4] = md;
        rr.x += md.x; rr.y += md.y; rr.z += md.z; rr.w += md.w;
    }
    *(float4*)&out[(size_t)m * 4] = rr;
}

// ---------------- launch ----------------------------------------------------
extern "C" void kernel_launch(void* const* d_in, const int* in_sizes, int n_in,
                              void* d_out, int out_size) {
    const float* coor = (const float*)d_in[0];
    const float* zs   = (const float*)d_in[1];
    const float* sp   = (const float*)d_in[2];
    const float* pos_w = (const float*)d_in[3];
    const float* pos_b = (const float*)d_in[4];
    const float* pe_w  = (const float*)d_in[5];
    const float* pe_b  = (const float*)d_in[6];
    const float* c1w = (const float*)d_in[7];
    const float* c1b = (const float*)d_in[8];
    const float* c2w = (const float*)d_in[9];
    const float* c2b = (const float*)d_in[10];
    const float* c3w = (const float*)d_in[11];
    const float* c3b = (const float*)d_in[12];
    const float* dw0 = (const float*)d_in[13];
    const float* db0 = (const float*)d_in[14];
    const float* dw1 = (const float*)d_in[15];
    const float* db1 = (const float*)d_in[16];
    const float* dnw = (const float*)d_in[17];
    const float* dnb = (const float*)d_in[18];
    const float* cw0 = (const float*)d_in[19];
    const float* cb0 = (const float*)d_in[20];
    const float* cw1 = (const float*)d_in[21];
    const float* cb1 = (const float*)d_in[22];
    float* out = (float*)d_out;

    float *fmap, *tri, *wf2, *wf3;
    cudaGetSymbolAddress((void**)&fmap, g_fmap);
    cudaGetSymbolAddress((void**)&tri, g_tri);
    cudaGetSymbolAddress((void**)&wf2, g_wf2);
    cudaGetSymbolAddress((void**)&wf3, g_wf3);

    prep_kernel<<<1, 64>>>(zs, sp, pos_w, pos_b, pe_w, pe_b);
    prep2_kernel<<<1, 576>>>(c1w, c1b);
    prep3_kernel<<<(9 * 64 * 64 + 9 * 64 * 96 + 255) / 256, 256>>>(c2w, c3w);

    const int smem2 = (SIN_FLOATS + 64 * 64 + 64) * 4;
    const int smem3 = (SIN_FLOATS + 96 * 64 + 96) * 4;
    cudaFuncSetAttribute((const void*)conv_tc_kernel<64, true, false>,
                         cudaFuncAttributeMaxDynamicSharedMemorySize, smem2);
    cudaFuncSetAttribute((const void*)conv_tc_kernel<96, false, true>,
                         cudaFuncAttributeMaxDynamicSharedMemorySize, smem3);

    dim3 cg(4, 32, NS);
    conv_tc_kernel<64, true, false><<<cg, 128, smem2>>>(wf2, c2b, c1b, fmap);
    conv_tc_kernel<96, false, true><<<cg, 128, smem3>>>(wf3, c3b, c1b, tri);

    cudaFuncSetAttribute(decode_kernel, cudaFuncAttributeMaxDynamicSharedMemorySize, DEC_SMEM);
    decode_kernel<<<148, 256, DEC_SMEM>>>(
        coor, sp, dw0, db0, dw1, db1, dnw, dnb, cw0, cb0, cw1, cb1, out);

    compose_kernel<<<MPTS / 256, 256>>>(out);
}

// round 7
// speedup vs baseline: 5.1117x; 1.2868x over previous
#include <cuda_runtime.h>
#include <math.h>
#include <stdint.h>

#define RESO 128
#define NS 8
#define MPTS 65536
#define ZD 64
#define TD 32

// ---------------- tf32 helpers ---------------------------------------------
__device__ __forceinline__ uint32_t tf32_hi(float x) {
    uint32_t u;
    asm("cvt.rna.tf32.f32 %0, %1;" : "=r"(u) : "f"(x));
    return u;
}
__device__ __forceinline__ float tf32f(float x) {
    return __uint_as_float(tf32_hi(x));
}
__device__ __forceinline__ void mma_tf32(float* c, uint32_t a0, uint32_t a1,
                                         uint32_t a2, uint32_t a3,
                                         uint32_t b0, uint32_t b1) {
    asm volatile(
        "mma.sync.aligned.m16n8k8.row.col.f32.tf32.tf32.f32 "
        "{%0,%1,%2,%3}, {%4,%5,%6,%7}, {%8,%9}, {%0,%1,%2,%3};"
        : "+f"(c[0]), "+f"(c[1]), "+f"(c[2]), "+f"(c[3])
        : "r"(a0), "r"(a1), "r"(a2), "r"(a3), "r"(b0), "r"(b1));
}

// ---------------- scratch (device globals) ---------------------------------
__device__ float g_fmap[NS * RESO * RESO * ZD];            // conv2 out, channel-last
__device__ float g_tri[(size_t)NS * 3 * RESO * RESO * TD]; // channel-last triplane
__device__ float g_zb[NS * ZD];
__device__ float g_A[ZD];
__device__ float g_B[ZD];
__device__ float g_Wz[NS * ZD * 9];
__device__ float g_Wa[ZD * 9];
__device__ float g_Wb[ZD * 9];
__device__ float g_K0[NS * ZD];
__device__ float g_K1[ZD];
__device__ float g_K2[ZD];
__device__ float g_wf2[9 * 64 * 64];   // conv2 weights, B-fragment layout per tap
__device__ float g_wf3[9 * 64 * 96];   // conv3 weights, B-fragment layout per tap

// ---------------- prep ------------------------------------------------------
__global__ void prep_kernel(const float* __restrict__ zs, const float* __restrict__ sp,
                            const float* __restrict__ pw, const float* __restrict__ pb,
                            const float* __restrict__ pew, const float* __restrict__ peb) {
    int c = threadIdx.x;
    if (c < ZD) {
        g_A[c] = pew[0 * ZD + c] - pew[2 * ZD + c];
        g_B[c] = pew[1 * ZD + c] - pew[3 * ZD + c];
        for (int n = 0; n < NS; n++) {
            g_zb[n * ZD + c] = zs[n * ZD + c]
                + sp[n * 3 + 0] * pw[0 * ZD + c]
                + sp[n * 3 + 1] * pw[1 * ZD + c]
                + pb[c] + peb[c];
        }
    }
}

__global__ void prep2_kernel(const float* __restrict__ w1, const float* __restrict__ b1) {
    int id = threadIdx.x;
    const float s = 2.0f / RESO;
    if (id < ZD * 9) {
        int oc = id / 9, t = id % 9;
        float wa = 0.f, wb = 0.f;
        float wz[NS];
#pragma unroll
        for (int n = 0; n < NS; n++) wz[n] = 0.f;
        for (int ic = 0; ic < ZD; ic++) {
            float w = w1[((size_t)oc * ZD + ic) * 9 + t];
            wa += w * g_A[ic];
            wb += w * g_B[ic];
#pragma unroll
            for (int n = 0; n < NS; n++) wz[n] += w * g_zb[n * ZD + ic];
        }
        g_Wa[oc * 9 + t] = wa;
        g_Wb[oc * 9 + t] = wb;
        for (int n = 0; n < NS; n++) g_Wz[(n * ZD + oc) * 9 + t] = wz[n];
    }
    __syncthreads();
    if (id < ZD) {
        int oc = id;
        float k1 = 0.f, k2 = 0.f;
        float k0[NS];
        for (int n = 0; n < NS; n++) k0[n] = b1[oc];
        for (int t = 0; t < 9; t++) {
            float dx = (float)(t % 3 - 1), dy = (float)(t / 3 - 1);
            float wa = g_Wa[oc * 9 + t], wb = g_Wb[oc * 9 + t];
            k1 += wa;
            k2 += wb;
            for (int n = 0; n < NS; n++)
                k0[n] += g_Wz[(n * ZD + oc) * 9 + t] + s * dx * wa + s * dy * wb;
        }
        g_K1[oc] = k1;
        g_K2[oc] = k2;
        for (int n = 0; n < NS; n++) g_K0[n * ZD + oc] = k0[n];
    }
}

// weights -> B-fragment layout (tf32-rounded).
__global__ void prep3_kernel(const float* __restrict__ c2w, const float* __restrict__ c3w) {
    int idx = blockIdx.x * blockDim.x + threadIdx.x;
    if (idx < 9 * 64 * 64) {
        int t = idx / 4096, r = idx % 4096;
        int k = r / 64, n = r % 64;
        int lfr = (n & 7) * 4 + (k & 3);
        int reg = (k & 7) >> 2;
        int off = (((k >> 3) * 8 + (n >> 3)) * 32 + lfr) * 2 + reg;
        g_wf2[t * 4096 + off] = tf32f(c2w[(size_t)n * 576 + k * 9 + t]);
    } else if (idx < 9 * 64 * 64 + 9 * 64 * 96) {
        int j = idx - 9 * 64 * 64;
        int t = j / 6144, r = j % 6144;
        int k = r / 96, n = r % 96;
        int lfr = (n & 7) * 4 + (k & 3);
        int reg = (k & 7) >> 2;
        int off = (((k >> 3) * 12 + (n >> 3)) * 32 + lfr) * 2 + reg;
        g_wf3[t * 6144 + off] = tf32f(c3w[(size_t)n * 576 + k * 9 + t]);
    }
}

// ---------------- tensor-core implicit-GEMM 3x3 conv (single-pass tf32) ----
#define XST 68
#define YST (34 * XST)
#define SIN_FLOATS (6 * YST)

template <int NOC, bool FUSED, bool TRI>
__global__ __launch_bounds__(128, 2) void conv_tc_kernel(
    const float* __restrict__ wf, const float* __restrict__ bias,
    const float* __restrict__ c1b, float* __restrict__ out) {
    constexpr int NT = NOC / 8;
    extern __shared__ float sh[];
    float* s_in = sh;
    float* s_B = sh + SIN_FLOATS;
    float* s_bias = s_B + NOC * 64;

    const int tid = threadIdx.x;
    const int w = tid >> 5, lane = tid & 31;
    const int x0 = blockIdx.x * 32, y0 = blockIdx.y * 4;
    const int n = blockIdx.z;

    if (tid < NOC) s_bias[tid] = bias[tid];

    // ---- stage input tile (+halo), channel-last, tf32-pre-rounded ----
    const float sgrid = 2.0f / RESO;
    for (int idx = tid; idx < 6 * 34 * 16; idx += 128) {
        int yi = idx / (34 * 16);
        int rem = idx % (34 * 16);
        int xi = rem / 16, icq = rem % 16;
        int ic4 = icq * 4;
        int gy = y0 + yi - 1, gx = x0 + xi - 1;
        float4 v = make_float4(0.f, 0.f, 0.f, 0.f);
        if (gy >= 0 && gy < RESO && gx >= 0 && gx < RESO) {
            if (FUSED) {
                float X = (2 * gx - 127) * (1.0f / RESO);
                float Y = (2 * gy - 127) * (1.0f / RESO);
                if (gx >= 1 && gx <= 126 && gy >= 1 && gy <= 126) {
                    float4 k0 = *(const float4*)&g_K0[n * ZD + ic4];
                    float4 k1 = *(const float4*)&g_K1[ic4];
                    float4 k2 = *(const float4*)&g_K2[ic4];
                    v.x = fmaxf(k0.x + k1.x * X + k2.x * Y, 0.f);
                    v.y = fmaxf(k0.y + k1.y * X + k2.y * Y, 0.f);
                    v.z = fmaxf(k0.z + k1.z * X + k2.z * Y, 0.f);
                    v.w = fmaxf(k0.w + k1.w * X + k2.w * Y, 0.f);
                } else {
                    float vv[4];
#pragma unroll
                    for (int c = 0; c < 4; c++) {
                        int ic = ic4 + c;
                        float val = c1b[ic];
#pragma unroll
                        for (int t9 = 0; t9 < 9; t9++) {
                            int dyb = t9 / 3 - 1, dxb = t9 % 3 - 1;
                            int gy2 = gy + dyb, gx2 = gx + dxb;
                            if (gy2 >= 0 && gy2 < RESO && gx2 >= 0 && gx2 < RESO)
                                val += g_Wz[((size_t)n * ZD + ic) * 9 + t9]
                                     + g_Wa[ic * 9 + t9] * (X + dxb * sgrid)
                                     + g_Wb[ic * 9 + t9] * (Y + dyb * sgrid);
                        }
                        vv[c] = fmaxf(val, 0.f);
                    }
                    v = make_float4(vv[0], vv[1], vv[2], vv[3]);
                }
            } else {
                v = *(const float4*)&g_fmap[(((size_t)n * RESO + gy) * RESO + gx) * ZD + ic4];
            }
            v.x = tf32f(v.x); v.y = tf32f(v.y); v.z = tf32f(v.z); v.w = tf32f(v.w);
        }
        *(float4*)&s_in[yi * YST + xi * XST + ic4] = v;
    }

    float acc[2][NT][4];
#pragma unroll
    for (int mt = 0; mt < 2; mt++)
#pragma unroll
        for (int nt = 0; nt < NT; nt++)
#pragma unroll
            for (int j = 0; j < 4; j++) acc[mt][nt][j] = 0.f;

    const int q = lane & 3, hr = lane >> 2;

#pragma unroll 1
    for (int t = 0; t < 9; t++) {
        int dy = t / 3, dx = t % 3;
        __syncthreads();
        const float4* src = (const float4*)(wf + t * (NOC * 64));
        for (int i = tid; i < NOC * 16; i += 128) ((float4*)s_B)[i] = src[i];
        __syncthreads();

#pragma unroll
        for (int icc = 0; icc < 8; icc++) {
            float2 bf[NT];
#pragma unroll
            for (int nt = 0; nt < NT; nt++)
                bf[nt] = *(const float2*)&s_B[(icc * NT + nt) * 64 + lane * 2];
#pragma unroll
            for (int mt = 0; mt < 2; mt++) {
                const float* ap = s_in + (w + dy) * YST + (mt * 16 + hr + dx) * XST + icc * 8 + q;
                uint32_t h0 = __float_as_uint(ap[0]);
                uint32_t h1 = __float_as_uint(ap[8 * XST]);
                uint32_t h2 = __float_as_uint(ap[4]);
                uint32_t h3 = __float_as_uint(ap[8 * XST + 4]);
#pragma unroll
                for (int nt = 0; nt < NT; nt++)
                    mma_tf32(acc[mt][nt], h0, h1, h2, h3,
                             __float_as_uint(bf[nt].x), __float_as_uint(bf[nt].y));
            }
        }
    }

    // ---- epilogue ----
    const int y = y0 + w;
    const int cl = 2 * (lane & 3);
#pragma unroll
    for (int mt = 0; mt < 2; mt++) {
        int xa = x0 + mt * 16 + hr;
#pragma unroll
        for (int nt = 0; nt < NT; nt++) {
            int col = nt * 8 + cl;
            float bv0 = s_bias[col], bv1 = s_bias[col + 1];
            float v0 = acc[mt][nt][0] + bv0, v1 = acc[mt][nt][1] + bv1;
            float v2 = acc[mt][nt][2] + bv0, v3 = acc[mt][nt][3] + bv1;
            if (!TRI) {
                v0 = fmaxf(v0, 0.f); v1 = fmaxf(v1, 0.f);
                v2 = fmaxf(v2, 0.f); v3 = fmaxf(v3, 0.f);
                *(float2*)&out[(((size_t)n * RESO + y) * RESO + xa) * ZD + col] = make_float2(v0, v1);
                *(float2*)&out[(((size_t)n * RESO + y) * RESO + xa + 8) * ZD + col] = make_float2(v2, v3);
            } else {
                int plane = col >> 5, c = col & 31;
                size_t pb = (((size_t)n * 3 + plane) * RESO * RESO);
                *(float2*)&out[(pb + (size_t)y * RESO + xa) * TD + c] = make_float2(v0, v1);
                *(float2*)&out[(pb + (size_t)y * RESO + xa + 8) * TD + c] = make_float2(v2, v3);
            }
        }
    }
}

// ---------------- tensor-core (single-pass tf32) fused decoder -------------
#define AST 100
#define OFF_A    0
#define OFF_B0   25600
#define OFF_B1   34816
#define OFF_B2   44032
#define OFF_BI0  47104
#define OFF_BI1  47200
#define OFF_BI2  47296
#define OFF_CW1  47328
#define OFF_CB1  47400
#define DEC_FLOATS 47404
#define DEC_SMEM (DEC_FLOATS * 4)
#define DTILES 2048

// TF32OUT: round stored activations (they feed the next MMA layer)
template <int NT, bool RELU, bool TF32OUT>
__device__ __forceinline__ void mlp_layer(const float* sA, float* dA,
                                          const float* sB, const float* sbias,
                                          int rowbase, int lane) {
    const int cl = 2 * (lane & 3);
    float acc[2][NT][4];
#pragma unroll
    for (int nt = 0; nt < NT; nt++) {
        float bv0 = sbias[nt * 8 + cl], bv1 = sbias[nt * 8 + cl + 1];
#pragma unroll
        for (int mt = 0; mt < 2; mt++) {
            acc[mt][nt][0] = bv0; acc[mt][nt][1] = bv1;
            acc[mt][nt][2] = bv0; acc[mt][nt][3] = bv1;
        }
    }
#pragma unroll
    for (int ks = 0; ks < 12; ks++) {
        uint32_t bf[NT][2];
#pragma unroll
        for (int nt = 0; nt < NT; nt++) {
            float2 b2 = *(const float2*)&sB[((ks * NT + nt) * 32 + lane) * 2];
            bf[nt][0] = __float_as_uint(b2.x);
            bf[nt][1] = __float_as_uint(b2.y);
        }
#pragma unroll
        for (int mt = 0; mt < 2; mt++) {
            const float* ap = sA + (rowbase + mt * 16 + (lane >> 2)) * AST + ks * 8 + (lane & 3);
            uint32_t h0 = __float_as_uint(ap[0]);
            uint32_t h2 = __float_as_uint(ap[4]);
            uint32_t h1 = __float_as_uint(ap[8 * AST]);
            uint32_t h3 = __float_as_uint(ap[8 * AST + 4]);
#pragma unroll
            for (int nt = 0; nt < NT; nt++)
                mma_tf32(acc[mt][nt], h0, h1, h2, h3, bf[nt][0], bf[nt][1]);
        }
    }
#pragma unroll
    for (int mt = 0; mt < 2; mt++) {
        int r0 = rowbase + mt * 16 + (lane >> 2);
#pragma unroll
        for (int nt = 0; nt < NT; nt++) {
            int col = nt * 8 + cl;
            float a0 = acc[mt][nt][0], a1 = acc[mt][nt][1];
            float a2 = acc[mt][nt][2], a3 = acc[mt][nt][3];
            if (RELU) {
                a0 = fmaxf(a0, 0.f); a1 = fmaxf(a1, 0.f);
                a2 = fmaxf(a2, 0.f); a3 = fmaxf(a3, 0.f);
            }
            if (TF32OUT) {
                a0 = tf32f(a0); a1 = tf32f(a1); a2 = tf32f(a2); a3 = tf32f(a3);
            }
            *(float2*)&dA[r0 * AST + col] = make_float2(a0, a1);
            *(float2*)&dA[(r0 + 8) * AST + col] = make_float2(a2, a3);
        }
    }
}

__global__ __launch_bounds__(256, 1) void decode_kernel(
    const float* __restrict__ coor, const float* __restrict__ spos,
    const float* __restrict__ w0, const float* __restrict__ b0,
    const float* __restrict__ w1, const float* __restrict__ b1,
    const float* __restrict__ dw, const float* __restrict__ db,
    const float* __restrict__ cw0, const float* __restrict__ cb0,
    const float* __restrict__ cw1, const float* __restrict__ cb1,
    float* __restrict__ out) {
    extern __shared__ float sm[];
    float* sA = sm + OFF_A;
    float* sB0 = sm + OFF_B0;
    float* sB1 = sm + OFF_B1;
    float* sB2 = sm + OFF_B2;
    float* sbi0 = sm + OFF_BI0;
    float* sbi1 = sm + OFF_BI1;
    float* sbi2 = sm + OFF_BI2;
    float* scw1 = sm + OFF_CW1;
    float* scb1 = sm + OFF_CB1;

    int tid = threadIdx.x;
    int wid = tid >> 5, lane = tid & 31;

    for (int idx = tid; idx < 96 * 96; idx += 256) {
        int k = idx / 96, n = idx % 96;
        int lfr = (n & 7) * 4 + (k & 3);
        int reg = (k & 7) >> 2;
        int off = (((k >> 3) * 12 + (n >> 3)) * 32 + lfr) * 2 + reg;
        sB0[off] = tf32f(w0[idx]);
        sB1[off] = tf32f(w1[idx]);
    }
    for (int idx = tid; idx < 96 * 32; idx += 256) {
        int k = idx / 32, n = idx % 32;
        float v = (n == 0) ? dw[k] : ((n <= 24) ? cw0[k * 24 + n - 1] : 0.f);
        int lfr = (n & 7) * 4 + (k & 3);
        int reg = (k & 7) >> 2;
        int off = (((k >> 3) * 4 + (n >> 3)) * 32 + lfr) * 2 + reg;
        sB2[off] = tf32f(v);
    }
    if (tid < 96) { sbi0[tid] = b0[tid]; sbi1[tid] = b1[tid]; }
    if (tid < 32) sbi2[tid] = (tid == 0) ? db[0] : ((tid <= 24) ? cb0[tid - 1] : 0.f);
    if (tid < 72) scw1[tid] = cw1[tid];
    if (tid < 3) scb1[tid] = cb1[tid];
    __syncthreads();

    const int rowbase = wid * 32;
    const int myrow = rowbase + lane;
    const size_t B2o = (size_t)MPTS * 4 + (size_t)NS * MPTS * 4;

    for (int t = blockIdx.x; t < DTILES; t += gridDim.x) {
        int n = t >> 8;
        int m = ((t & 255) << 8) + myrow;

        float rx = coor[((size_t)n * MPTS + m) * 3 + 0] - spos[n * 3 + 0];
        float ry = coor[((size_t)n * MPTS + m) * 3 + 1] - spos[n * 3 + 1];
        float rz = coor[((size_t)n * MPTS + m) * 3 + 2] - spos[n * 3 + 2];
        bool outsider = (fabsf(rx) > 1.f || fabsf(ry) > 1.f || fabsf(rz) > 1.f);

#pragma unroll
        for (int p = 0; p < 3; p++) {
            float cu, cv;
            if (p == 0) { cu = rx; cv = ry; }
            else if (p == 1) { cu = rx; cv = rz; }
            else { cu = rz; cv = rx; }
            float u = (cu + 1.f) * 64.f - 0.5f;
            float v = (cv + 1.f) * 64.f - 0.5f;
            float fx = floorf(u), fy = floorf(v);
            float wx = u - fx, wy = v - fy;
            int ix0 = (int)fx, iy0 = (int)fy;
            float wts[4] = {(1 - wx) * (1 - wy), wx * (1 - wy), (1 - wx) * wy, wx * wy};
            int xs[4] = {ix0, ix0 + 1, ix0, ix0 + 1};
            int ys[4] = {iy0, iy0, iy0 + 1, iy0 + 1};
            float4 f[8];
#pragma unroll
            for (int k = 0; k < 8; k++) f[k] = make_float4(0.f, 0.f, 0.f, 0.f);
            size_t pb = ((size_t)n * 3 + p) * RESO * RESO;
#pragma unroll
            for (int tt = 0; tt < 4; tt++) {
                if (xs[tt] >= 0 && xs[tt] < RESO && ys[tt] >= 0 && ys[tt] < RESO) {
                    const float4* tp = (const float4*)&g_tri[(pb + (size_t)ys[tt] * RESO + xs[tt]) * TD];
                    float wv = wts[tt];
#pragma unroll
                    for (int k = 0; k < 8; k++) {
                        float4 d = tp[k];
                        f[k].x += wv * d.x; f[k].y += wv * d.y;
                        f[k].z += wv * d.z; f[k].w += wv * d.w;
                    }
                }
            }
            float4* dst = (float4*)&sA[myrow * AST + p * 32];
#pragma unroll
            for (int k = 0; k < 8; k++) {
                f[k].x = tf32f(f[k].x); f[k].y = tf32f(f[k].y);
                f[k].z = tf32f(f[k].z); f[k].w = tf32f(f[k].w);
                dst[k] = f[k];
            }
        }
        __syncwarp();

        mlp_layer<12, true, true>(sA, sA, sB0, sbi0, rowbase, lane);
        __syncwarp();
        mlp_layer<12, true, true>(sA, sA, sB1, sbi1, rowbase, lane);
        __syncwarp();
        mlp_layer<4, false, false>(sA, sA, sB2, sbi2, rowbase, lane);
        __syncwarp();

        {
            const float* v = &sA[myrow * AST];
            float dens = v[0];
            float c0 = scb1[0], c1 = scb1[1], c2 = scb1[2];
#pragma unroll
            for (int j = 0; j < 24; j++) {
                float h = fmaxf(v[1 + j], 0.f);
                c0 += h * scw1[j * 3 + 0];
                c1 += h * scw1[j * 3 + 1];
                c2 += h * scw1[j * 3 + 2];
            }
            float rawmask = outsider ? 0.f : fmaxf(dens, 0.f);
            float4 o = make_float4((tanhf(c0) + 1.f) * 0.5f, (tanhf(c1) + 1.f) * 0.5f,
                                   (tanhf(c2) + 1.f) * 0.5f, rawmask);
            *(float4*)&out[B2o + ((size_t)n * MPTS + m) * 4] = o;
        }
        __syncwarp();
    }
}

// ---------------- composition over slots -----------------------------------
__global__ void compose_kernel(float* __restrict__ out) {
    int m = blockIdx.x * blockDim.x + threadIdx.x;
    if (m >= MPTS) return;
    const size_t B1 = (size_t)MPTS * 4;
    const size_t B2 = B1 + (size_t)NS * MPTS * 4;
    const size_t B3 = B2 + (size_t)NS * MPTS * 4;
    float4 um[NS];
    float s = 0.f;
#pragma unroll
    for (int n = 0; n < NS; n++) {
        um[n] = *(const float4*)&out[B2 + ((size_t)n * MPTS + m) * 4];
        s += um[n].w;
    }
    float denom = s + 1e-8f;
    float4 rr = make_float4(0.f, 0.f, 0.f, 0.f);
#pragma unroll
    for (int n = 0; n < NS; n++) {
        float mk = um[n].w / denom;
        out[B3 + (size_t)n * MPTS + m] = mk;
        float4 md = make_float4(um[n].x * mk, um[n].y * mk, um[n].z * mk, um[n].w * mk);
        *(float4*)&out[B1 + ((size_t)n * MPTS + m) * 4] = md;
        rr.x += md.x; rr.y += md.y; rr.z += md.z; rr.w += md.w;
    }
    *(float4*)&out[(size_t)m * 4] = rr;
}

// ---------------- launch ----------------------------------------------------
extern "C" void kernel_launch(void* const* d_in, const int* in_sizes, int n_in,
                              void* d_out, int out_size) {
    const float* coor = (const float*)d_in[0];
    const float* zs   = (const float*)d_in[1];
    const float* sp   = (const float*)d_in[2];
    const float* pos_w = (const float*)d_in[3];
    const float* pos_b = (const float*)d_in[4];
    const float* pe_w  = (const float*)d_in[5];
    const float* pe_b  = (const float*)d_in[6];
    const float* c1w = (const float*)d_in[7];
    const float* c1b = (const float*)d_in[8];
    const float* c2w = (const float*)d_in[9];
    const float* c2b = (const float*)d_in[10];
    const float* c3w = (const float*)d_in[11];
    const float* c3b = (const float*)d_in[12];
    const float* dw0 = (const float*)d_in[13];
    const float* db0 = (const float*)d_in[14];
    const float* dw1 = (const float*)d_in[15];
    const float* db1 = (const float*)d_in[16];
    const float* dnw = (const float*)d_in[17];
    const float* dnb = (const float*)d_in[18];
    const float* cw0 = (const float*)d_in[19];
    const float* cb0 = (const float*)d_in[20];
    const float* cw1 = (const float*)d_in[21];
    const float* cb1 = (const float*)d_in[22];
    float* out = (float*)d_out;

    float *fmap, *tri, *wf2, *wf3;
    cudaGetSymbolAddress((void**)&fmap, g_fmap);
    cudaGetSymbolAddress((void**)&tri, g_tri);
    cudaGetSymbolAddress((void**)&wf2, g_wf2);
    cudaGetSymbolAddress((void**)&wf3, g_wf3);

    prep_kernel<<<1, 64>>>(zs, sp, pos_w, pos_b, pe_w, pe_b);
    prep2_kernel<<<1, 576>>>(c1w, c1b);
    prep3_kernel<<<(9 * 64 * 64 + 9 * 64 * 96 + 255) / 256, 256>>>(c2w, c3w);

    const int smem2 = (SIN_FLOATS + 64 * 64 + 64) * 4;
    const int smem3 = (SIN_FLOATS + 96 * 64 + 96) * 4;
    cudaFuncSetAttribute((const void*)conv_tc_kernel<64, true, false>,
                         cudaFuncAttributeMaxDynamicSharedMemorySize, smem2);
    cudaFuncSetAttribute((const void*)conv_tc_kernel<96, false, true>,
                         cudaFuncAttributeMaxDynamicSharedMemorySize, smem3);

    dim3 cg(4, 32, NS);
    conv_tc_kernel<64, true, false><<<cg, 128, smem2>>>(wf2, c2b, c1b, fmap);
    conv_tc_kernel<96, false, true><<<cg, 128, smem3>>>(wf3, c3b, c1b, tri);

    cudaFuncSetAttribute(decode_kernel, cudaFuncAttributeMaxDynamicSharedMemorySize, DEC_SMEM);
    decode_kernel<<<148, 256, DEC_SMEM>>>(
        coor, sp, dw0, db0, dw1, db1, dnw, dnb, cw0, cb0, cw1, cb1, out);

    compose_kernel<<<MPTS / 256, 256>>>(out);
}

// round 8
// speedup vs baseline: 8.4885x; 1.6606x over previous
#include <cuda_runtime.h>
#include <cuda_bf16.h>
#include <math.h>
#include <stdint.h>

#define RESO 128
#define NS 8
#define MPTS 65536
#define ZD 64
#define TD 32

typedef __nv_bfloat16 bf16;
typedef __nv_bfloat162 bf162;

// ---------------- helpers ---------------------------------------------------
__device__ __forceinline__ void mma_bf16(float* c, uint32_t a0, uint32_t a1,
                                         uint32_t a2, uint32_t a3,
                                         uint32_t b0, uint32_t b1) {
    asm volatile(
        "mma.sync.aligned.m16n8k16.row.col.f32.bf16.bf16.f32 "
        "{%0,%1,%2,%3}, {%4,%5,%6,%7}, {%8,%9}, {%0,%1,%2,%3};"
        : "+f"(c[0]), "+f"(c[1]), "+f"(c[2]), "+f"(c[3])
        : "r"(a0), "r"(a1), "r"(a2), "r"(a3), "r"(b0), "r"(b1));
}
__device__ __forceinline__ uint32_t packbf(float a, float b) {
    bf162 h = __float22bfloat162_rn(make_float2(a, b));
    return *reinterpret_cast<uint32_t*>(&h);
}

// ---------------- scratch (device globals) ---------------------------------
__device__ bf16 g_fmap_h[NS * RESO * RESO * ZD];            // conv2 out, ch-last
__device__ bf16 g_tri_h[(size_t)NS * 3 * RESO * RESO * TD]; // triplane, ch-last
__device__ float g_zb[NS * ZD];
__device__ float g_A[ZD];
__device__ float g_B[ZD];
__device__ float g_Wz[NS * ZD * 9];
__device__ float g_Wa[ZD * 9];
__device__ float g_Wb[ZD * 9];
__device__ float g_K0[NS * ZD];
__device__ float g_K1[ZD];
__device__ float g_K2[ZD];
__device__ bf16 g_wf2h[9 * 4 * 8 * 128];    // conv2 w frag: per tap 4kb x 8nt x 64 u32
__device__ bf16 g_wf3h[9 * 4 * 12 * 128];   // conv3 w frag

// ---------------- prep ------------------------------------------------------
__global__ void prep_kernel(const float* __restrict__ zs, const float* __restrict__ sp,
                            const float* __restrict__ pw, const float* __restrict__ pb,
                            const float* __restrict__ pew, const float* __restrict__ peb) {
    int c = threadIdx.x;
    if (c < ZD) {
        g_A[c] = pew[0 * ZD + c] - pew[2 * ZD + c];
        g_B[c] = pew[1 * ZD + c] - pew[3 * ZD + c];
        for (int n = 0; n < NS; n++) {
            g_zb[n * ZD + c] = zs[n * ZD + c]
                + sp[n * 3 + 0] * pw[0 * ZD + c]
                + sp[n * 3 + 1] * pw[1 * ZD + c]
                + pb[c] + peb[c];
        }
    }
}

__global__ void prep2_kernel(const float* __restrict__ w1, const float* __restrict__ b1) {
    int id = threadIdx.x;
    const float s = 2.0f / RESO;
    if (id < ZD * 9) {
        int oc = id / 9, t = id % 9;
        float wa = 0.f, wb = 0.f;
        float wz[NS];
#pragma unroll
        for (int n = 0; n < NS; n++) wz[n] = 0.f;
        for (int ic = 0; ic < ZD; ic++) {
            float w = w1[((size_t)oc * ZD + ic) * 9 + t];
            wa += w * g_A[ic];
            wb += w * g_B[ic];
#pragma unroll
            for (int n = 0; n < NS; n++) wz[n] += w * g_zb[n * ZD + ic];
        }
        g_Wa[oc * 9 + t] = wa;
        g_Wb[oc * 9 + t] = wb;
        for (int n = 0; n < NS; n++) g_Wz[(n * ZD + oc) * 9 + t] = wz[n];
    }
    __syncthreads();
    if (id < ZD) {
        int oc = id;
        float k1 = 0.f, k2 = 0.f;
        float k0[NS];
        for (int n = 0; n < NS; n++) k0[n] = b1[oc];
        for (int t = 0; t < 9; t++) {
            float dx = (float)(t % 3 - 1), dy = (float)(t / 3 - 1);
            float wa = g_Wa[oc * 9 + t], wb = g_Wb[oc * 9 + t];
            k1 += wa;
            k2 += wb;
            for (int n = 0; n < NS; n++)
                k0[n] += g_Wz[(n * ZD + oc) * 9 + t] + s * dx * wa + s * dy * wb;
        }
        g_K1[oc] = k1;
        g_K2[oc] = k2;
        for (int n = 0; n < NS; n++) g_K0[n * ZD + oc] = k0[n];
    }
}

// weights -> bf16 B-fragment layout (m16n8k16)
__global__ void prep3_kernel(const float* __restrict__ c2w, const float* __restrict__ c3w) {
    int idx = blockIdx.x * blockDim.x + threadIdx.x;
    if (idx < 9 * 64 * 64) {
        int t = idx / 4096, r2 = idx % 4096;
        int k = r2 / 64, n = r2 % 64;
        int kb = k >> 4, rr = (k >> 3) & 1, half = k & 1;
        int lane = (n & 7) * 4 + ((k & 7) >> 1), nt = n >> 3;
        int word = (t * 32 + kb * 8 + nt) * 64 + lane * 2 + rr;
        g_wf2h[word * 2 + half] = __float2bfloat16(c2w[(size_t)n * 576 + k * 9 + t]);
    } else if (idx < 9 * 64 * 64 + 9 * 64 * 96) {
        int j = idx - 9 * 64 * 64;
        int t = j / 6144, r2 = j % 6144;
        int k = r2 / 96, n = r2 % 96;
        int kb = k >> 4, rr = (k >> 3) & 1, half = k & 1;
        int lane = (n & 7) * 4 + ((k & 7) >> 1), nt = n >> 3;
        int word = (t * 48 + kb * 12 + nt) * 64 + lane * 2 + rr;
        g_wf3h[word * 2 + half] = __float2bfloat16(c3w[(size_t)n * 576 + k * 9 + t]);
    }
}

// ---------------- bf16 tensor-core implicit-GEMM 3x3 conv ------------------
#define X2 72
#define Y2 (34 * X2)
#define SIN_H (6 * Y2)   // bf16 elements

template <int NOC, bool FUSED, bool TRI>
__global__ __launch_bounds__(128, 3) void conv_tc_kernel(
    const uint32_t* __restrict__ wf, const float* __restrict__ bias,
    const float* __restrict__ c1b, bf16* __restrict__ outh) {
    constexpr int NT = NOC / 8;
    extern __shared__ char shraw[];
    bf16* s_in = (bf16*)shraw;
    uint32_t* s_B = (uint32_t*)(shraw + SIN_H * 2);
    float* s_bias = (float*)(shraw + SIN_H * 2 + 4 * NT * 64 * 4);

    const int tid = threadIdx.x;
    const int w = tid >> 5, lane = tid & 31;
    const int x0 = blockIdx.x * 32, y0 = blockIdx.y * 4;
    const int n = blockIdx.z;

    if (tid < NOC) s_bias[tid] = bias[tid];

    const float sgrid = 2.0f / RESO;
    if (FUSED) {
        for (int idx = tid; idx < 6 * 34 * 16; idx += 128) {
            int yi = idx / (34 * 16);
            int rem = idx % (34 * 16);
            int xi = rem / 16, icq = rem % 16;
            int ic4 = icq * 4;
            int gy = y0 + yi - 1, gx = x0 + xi - 1;
            float4 v = make_float4(0.f, 0.f, 0.f, 0.f);
            if (gy >= 0 && gy < RESO && gx >= 0 && gx < RESO) {
                float X = (2 * gx - 127) * (1.0f / RESO);
                float Y = (2 * gy - 127) * (1.0f / RESO);
                if (gx >= 1 && gx <= 126 && gy >= 1 && gy <= 126) {
                    float4 k0 = *(const float4*)&g_K0[n * ZD + ic4];
                    float4 k1 = *(const float4*)&g_K1[ic4];
                    float4 k2 = *(const float4*)&g_K2[ic4];
                    v.x = fmaxf(k0.x + k1.x * X + k2.x * Y, 0.f);
                    v.y = fmaxf(k0.y + k1.y * X + k2.y * Y, 0.f);
                    v.z = fmaxf(k0.z + k1.z * X + k2.z * Y, 0.f);
                    v.w = fmaxf(k0.w + k1.w * X + k2.w * Y, 0.f);
                } else {
                    float vv[4];
#pragma unroll
                    for (int c = 0; c < 4; c++) {
                        int ic = ic4 + c;
                        float val = c1b[ic];
#pragma unroll
                        for (int t9 = 0; t9 < 9; t9++) {
                            int dyb = t9 / 3 - 1, dxb = t9 % 3 - 1;
                            int gy2 = gy + dyb, gx2 = gx + dxb;
                            if (gy2 >= 0 && gy2 < RESO && gx2 >= 0 && gx2 < RESO)
                                val += g_Wz[((size_t)n * ZD + ic) * 9 + t9]
                                     + g_Wa[ic * 9 + t9] * (X + dxb * sgrid)
                                     + g_Wb[ic * 9 + t9] * (Y + dyb * sgrid);
                        }
                        vv[c] = fmaxf(val, 0.f);
                    }
                    v = make_float4(vv[0], vv[1], vv[2], vv[3]);
                }
            }
            uint2 pk;
            pk.x = packbf(v.x, v.y);
            pk.y = packbf(v.z, v.w);
            *(uint2*)&s_in[yi * Y2 + xi * X2 + ic4] = pk;
        }
    } else {
        for (int idx = tid; idx < 6 * 34 * 8; idx += 128) {
            int yi = idx / (34 * 8);
            int rem = idx % (34 * 8);
            int xi = rem / 8, ic8 = (rem % 8) * 8;
            int gy = y0 + yi - 1, gx = x0 + xi - 1;
            uint4 v = make_uint4(0u, 0u, 0u, 0u);
            if (gy >= 0 && gy < RESO && gx >= 0 && gx < RESO)
                v = *(const uint4*)&g_fmap_h[(((size_t)n * RESO + gy) * RESO + gx) * ZD + ic8];
            *(uint4*)&s_in[yi * Y2 + xi * X2 + ic8] = v;
        }
    }

    float acc[2][NT][4];
#pragma unroll
    for (int mt = 0; mt < 2; mt++)
#pragma unroll
        for (int nt = 0; nt < NT; nt++)
#pragma unroll
            for (int j = 0; j < 4; j++) acc[mt][nt][j] = 0.f;

    const int q = lane & 3, hr = lane >> 2;

#pragma unroll 1
    for (int tt = 0; tt < 9; tt++) {
        int dy = tt / 3, dx = tt % 3;
        __syncthreads();
        const uint4* src = (const uint4*)(wf + tt * (4 * NT * 64));
        for (int i = tid; i < NT * 64; i += 128) ((uint4*)s_B)[i] = src[i];
        __syncthreads();

#pragma unroll
        for (int kb = 0; kb < 4; kb++) {
            uint2 bb[NT];
#pragma unroll
            for (int nt = 0; nt < NT; nt++)
                bb[nt] = *(const uint2*)&s_B[(kb * NT + nt) * 64 + lane * 2];
#pragma unroll
            for (int mt = 0; mt < 2; mt++) {
                const bf16* ap = s_in + (w + dy) * Y2 + (mt * 16 + hr + dx) * X2 + kb * 16;
                uint32_t a0 = *(const uint32_t*)&ap[2 * q];
                uint32_t a1 = *(const uint32_t*)&ap[8 * X2 + 2 * q];
                uint32_t a2 = *(const uint32_t*)&ap[2 * q + 8];
                uint32_t a3 = *(const uint32_t*)&ap[8 * X2 + 2 * q + 8];
#pragma unroll
                for (int nt = 0; nt < NT; nt++)
                    mma_bf16(acc[mt][nt], a0, a1, a2, a3, bb[nt].x, bb[nt].y);
            }
        }
    }

    // ---- epilogue: pack bf16 pairs ----
    const int y = y0 + w;
#pragma unroll
    for (int mt = 0; mt < 2; mt++) {
        int xa = x0 + mt * 16 + hr;
#pragma unroll
        for (int nt = 0; nt < NT; nt++) {
            int col = nt * 8 + 2 * q;
            float bv0 = s_bias[col], bv1 = s_bias[col + 1];
            float v0 = acc[mt][nt][0] + bv0, v1 = acc[mt][nt][1] + bv1;
            float v2 = acc[mt][nt][2] + bv0, v3 = acc[mt][nt][3] + bv1;
            if (!TRI) {
                v0 = fmaxf(v0, 0.f); v1 = fmaxf(v1, 0.f);
                v2 = fmaxf(v2, 0.f); v3 = fmaxf(v3, 0.f);
                *(uint32_t*)&outh[(((size_t)n * RESO + y) * RESO + xa) * ZD + col] = packbf(v0, v1);
                *(uint32_t*)&outh[(((size_t)n * RESO + y) * RESO + xa + 8) * ZD + col] = packbf(v2, v3);
            } else {
                int plane = col >> 5, c = col & 31;
                size_t pb = (((size_t)n * 3 + plane) * RESO * RESO);
                *(uint32_t*)&outh[(pb + (size_t)y * RESO + xa) * TD + c] = packbf(v0, v1);
                *(uint32_t*)&outh[(pb + (size_t)y * RESO + xa + 8) * TD + c] = packbf(v2, v3);
            }
        }
    }
}

// ---------------- bf16 tensor-core fused decoder ---------------------------
#define AST2 104
#define D_SA    0
#define D_B0    53248
#define D_B1    71680
#define D_B2    90112
#define D_BI0   96256
#define D_BI1   96640
#define D_BI2   97024
#define D_CW1   97152
#define D_CB1   97440
#define DEC_SMEM 97456
#define DTILES 2048

template <int NT, bool RELU>
__device__ __forceinline__ void mlp_layer(bf16* sA, const uint32_t* sB,
                                          const float* sbias, int rowbase, int lane) {
    const int g = lane >> 2, q = lane & 3;
    const int cl = 2 * q;
    float acc[2][NT][4];
#pragma unroll
    for (int nt = 0; nt < NT; nt++) {
        float bv0 = sbias[nt * 8 + cl], bv1 = sbias[nt * 8 + cl + 1];
#pragma unroll
        for (int mt = 0; mt < 2; mt++) {
            acc[mt][nt][0] = bv0; acc[mt][nt][1] = bv1;
            acc[mt][nt][2] = bv0; acc[mt][nt][3] = bv1;
        }
    }
#pragma unroll
    for (int kb = 0; kb < 6; kb++) {
        uint2 bb[NT];
#pragma unroll
        for (int nt = 0; nt < NT; nt++)
            bb[nt] = *(const uint2*)&sB[(kb * NT + nt) * 64 + lane * 2];
#pragma unroll
        for (int mt = 0; mt < 2; mt++) {
            const bf16* ap = sA + (rowbase + mt * 16 + g) * AST2 + kb * 16;
            uint32_t a0 = *(const uint32_t*)&ap[2 * q];
            uint32_t a1 = *(const uint32_t*)&ap[8 * AST2 + 2 * q];
            uint32_t a2 = *(const uint32_t*)&ap[2 * q + 8];
            uint32_t a3 = *(const uint32_t*)&ap[8 * AST2 + 2 * q + 8];
#pragma unroll
            for (int nt = 0; nt < NT; nt++)
                mma_bf16(acc[mt][nt], a0, a1, a2, a3, bb[nt].x, bb[nt].y);
        }
    }
#pragma unroll
    for (int mt = 0; mt < 2; mt++) {
        int r0 = rowbase + mt * 16 + g;
#pragma unroll
        for (int nt = 0; nt < NT; nt++) {
            int col = nt * 8 + cl;
            float a0 = acc[mt][nt][0], a1 = acc[mt][nt][1];
            float a2 = acc[mt][nt][2], a3 = acc[mt][nt][3];
            if (RELU) {
                a0 = fmaxf(a0, 0.f); a1 = fmaxf(a1, 0.f);
                a2 = fmaxf(a2, 0.f); a3 = fmaxf(a3, 0.f);
            }
            *(uint32_t*)&sA[r0 * AST2 + col] = packbf(a0, a1);
            *(uint32_t*)&sA[(r0 + 8) * AST2 + col] = packbf(a2, a3);
        }
    }
}

__global__ __launch_bounds__(256, 2) void decode_kernel(
    const float* __restrict__ coor, const float* __restrict__ spos,
    const float* __restrict__ w0, const float* __restrict__ b0,
    const float* __restrict__ w1, const float* __restrict__ b1,
    const float* __restrict__ dw, const float* __restrict__ db,
    const float* __restrict__ cw0, const float* __restrict__ cb0,
    const float* __restrict__ cw1, const float* __restrict__ cb1,
    float* __restrict__ out) {
    extern __shared__ char smraw[];
    bf16* sA = (bf16*)(smraw + D_SA);
    uint32_t* sB0 = (uint32_t*)(smraw + D_B0);
    uint32_t* sB1 = (uint32_t*)(smraw + D_B1);
    uint32_t* sB2 = (uint32_t*)(smraw + D_B2);
    float* sbi0 = (float*)(smraw + D_BI0);
    float* sbi1 = (float*)(smraw + D_BI1);
    float* sbi2 = (float*)(smraw + D_BI2);
    float* scw1 = (float*)(smraw + D_CW1);
    float* scb1 = (float*)(smraw + D_CB1);

    int tid = threadIdx.x;
    int wid = tid >> 5, lane = tid & 31;

    // stage weights (bf16 fragment layout)
    for (int idx = tid; idx < 96 * 96; idx += 256) {
        int k = idx / 96, n = idx % 96;
        int kb = k >> 4, rr = (k >> 3) & 1, half = k & 1;
        int lane2 = (n & 7) * 4 + ((k & 7) >> 1), nt = n >> 3;
        int hoff = ((kb * 12 + nt) * 64 + lane2 * 2 + rr) * 2 + half;
        ((bf16*)sB0)[hoff] = __float2bfloat16(w0[idx]);
        ((bf16*)sB1)[hoff] = __float2bfloat16(w1[idx]);
    }
    for (int idx = tid; idx < 96 * 32; idx += 256) {
        int k = idx / 32, n = idx % 32;
        float v = (n == 0) ? dw[k] : ((n <= 24) ? cw0[k * 24 + n - 1] : 0.f);
        int kb = k >> 4, rr = (k >> 3) & 1, half = k & 1;
        int lane2 = (n & 7) * 4 + ((k & 7) >> 1), nt = n >> 3;
        int hoff = ((kb * 4 + nt) * 64 + lane2 * 2 + rr) * 2 + half;
        ((bf16*)sB2)[hoff] = __float2bfloat16(v);
    }
    if (tid < 96) { sbi0[tid] = b0[tid]; sbi1[tid] = b1[tid]; }
    if (tid < 32) sbi2[tid] = (tid == 0) ? db[0] : ((tid <= 24) ? cb0[tid - 1] : 0.f);
    if (tid < 72) scw1[tid] = cw1[tid];
    if (tid < 3) scb1[tid] = cb1[tid];
    __syncthreads();

    const int rowbase = wid * 32;
    const int myrow = rowbase + lane;
    const size_t B2o = (size_t)MPTS * 4 + (size_t)NS * MPTS * 4;

    for (int t = blockIdx.x; t < DTILES; t += gridDim.x) {
        int n = t >> 8;
        int m = ((t & 255) << 8) + myrow;

        float rx = coor[((size_t)n * MPTS + m) * 3 + 0] - spos[n * 3 + 0];
        float ry = coor[((size_t)n * MPTS + m) * 3 + 1] - spos[n * 3 + 1];
        float rz = coor[((size_t)n * MPTS + m) * 3 + 2] - spos[n * 3 + 2];
        bool outsider = (fabsf(rx) > 1.f || fabsf(ry) > 1.f || fabsf(rz) > 1.f);

#pragma unroll
        for (int p = 0; p < 3; p++) {
            float cu, cv;
            if (p == 0) { cu = rx; cv = ry; }
            else if (p == 1) { cu = rx; cv = rz; }
            else { cu = rz; cv = rx; }
            float u = (cu + 1.f) * 64.f - 0.5f;
            float v = (cv + 1.f) * 64.f - 0.5f;
            float fx = floorf(u), fy = floorf(v);
            float wx = u - fx, wy = v - fy;
            int ix0 = (int)fx, iy0 = (int)fy;
            float wts[4] = {(1 - wx) * (1 - wy), wx * (1 - wy), (1 - wx) * wy, wx * wy};
            int xs[4] = {ix0, ix0 + 1, ix0, ix0 + 1};
            int ys[4] = {iy0, iy0, iy0 + 1, iy0 + 1};
            bf162 hacc[16];
#pragma unroll
            for (int k = 0; k < 16; k++) hacc[k] = __float2bfloat162_rn(0.f);
            size_t pb = ((size_t)n * 3 + p) * RESO * RESO;
#pragma unroll
            for (int tt = 0; tt < 4; tt++) {
                if (xs[tt] >= 0 && xs[tt] < RESO && ys[tt] >= 0 && ys[tt] < RESO) {
                    const uint4* tq = (const uint4*)&g_tri_h[(pb + (size_t)ys[tt] * RESO + xs[tt]) * TD];
                    bf162 w2 = __float2bfloat162_rn(wts[tt]);
#pragma unroll
                    for (int j = 0; j < 4; j++) {
                        uint4 qv = tq[j];
                        hacc[j * 4 + 0] = __hfma2(*(bf162*)&qv.x, w2, hacc[j * 4 + 0]);
                        hacc[j * 4 + 1] = __hfma2(*(bf162*)&qv.y, w2, hacc[j * 4 + 1]);
                        hacc[j * 4 + 2] = __hfma2(*(bf162*)&qv.z, w2, hacc[j * 4 + 2]);
                        hacc[j * 4 + 3] = __hfma2(*(bf162*)&qv.w, w2, hacc[j * 4 + 3]);
                    }
                }
            }
            uint4* dst = (uint4*)&sA[myrow * AST2 + p * 32];
#pragma unroll
            for (int j = 0; j < 4; j++) {
                uint4 o;
                o.x = *(uint32_t*)&hacc[j * 4 + 0];
                o.y = *(uint32_t*)&hacc[j * 4 + 1];
                o.z = *(uint32_t*)&hacc[j * 4 + 2];
                o.w = *(uint32_t*)&hacc[j * 4 + 3];
                dst[j] = o;
            }
        }
        __syncwarp();

        mlp_layer<12, true>(sA, sB0, sbi0, rowbase, lane);
        __syncwarp();
        mlp_layer<12, true>(sA, sB1, sbi1, rowbase, lane);
        __syncwarp();
        mlp_layer<4, false>(sA, sB2, sbi2, rowbase, lane);
        __syncwarp();

        {
            const bf16* vh = &sA[myrow * AST2];
            float vv[26];
#pragma unroll
            for (int i = 0; i < 13; i++) {
                float2 f2 = __bfloat1622float2(*(const bf162*)&vh[2 * i]);
                vv[2 * i] = f2.x;
                vv[2 * i + 1] = f2.y;
            }
            float dens = vv[0];
            float c0 = scb1[0], c1 = scb1[1], c2 = scb1[2];
#pragma unroll
            for (int j = 0; j < 24; j++) {
                float h = fmaxf(vv[1 + j], 0.f);
                c0 += h * scw1[j * 3 + 0];
                c1 += h * scw1[j * 3 + 1];
                c2 += h * scw1[j * 3 + 2];
            }
            float rawmask = outsider ? 0.f : fmaxf(dens, 0.f);
            float4 o = make_float4((tanhf(c0) + 1.f) * 0.5f, (tanhf(c1) + 1.f) * 0.5f,
                                   (tanhf(c2) + 1.f) * 0.5f, rawmask);
            *(float4*)&out[B2o + ((size_t)n * MPTS + m) * 4] = o;
        }
        __syncwarp();
    }
}

// ---------------- composition over slots -----------------------------------
__global__ void compose_kernel(float* __restrict__ out) {
    int m = blockIdx.x * blockDim.x + threadIdx.x;
    if (m >= MPTS) return;
    const size_t B1 = (size_t)MPTS * 4;
    const size_t B2 = B1 + (size_t)NS * MPTS * 4;
    const size_t B3 = B2 + (size_t)NS * MPTS * 4;
    float4 um[NS];
    float s = 0.f;
#pragma unroll
    for (int n = 0; n < NS; n++) {
        um[n] = *(const float4*)&out[B2 + ((size_t)n * MPTS + m) * 4];
        s += um[n].w;
    }
    float denom = s + 1e-8f;
    float4 rr = make_float4(0.f, 0.f, 0.f, 0.f);
#pragma unroll
    for (int n = 0; n < NS; n++) {
        float mk = um[n].w / denom;
        out[B3 + (size_t)n * MPTS + m] = mk;
        float4 md = make_float4(um[n].x * mk, um[n].y * mk, um[n].z * mk, um[n].w * mk);
        *(float4*)&out[B1 + ((size_t)n * MPTS + m) * 4] = md;
        rr.x += md.x; rr.y += md.y; rr.z += md.z; rr.w += md.w;
    }
    *(float4*)&out[(size_t)m * 4] = rr;
}

// ---------------- launch ----------------------------------------------------
extern "C" void kernel_launch(void* const* d_in, const int* in_sizes, int n_in,
                              void* d_out, int out_size) {
    const float* coor = (const float*)d_in[0];
    const float* zs   = (const float*)d_in[1];
    const float* sp   = (const float*)d_in[2];
    const float* pos_w = (const float*)d_in[3];
    const float* pos_b = (const float*)d_in[4];
    const float* pe_w  = (const float*)d_in[5];
    const float* pe_b  = (const float*)d_in[6];
    const float* c1w = (const float*)d_in[7];
    const float* c1b = (const float*)d_in[8];
    const float* c2w = (const float*)d_in[9];
    const float* c2b = (const float*)d_in[10];
    const float* c3w = (const float*)d_in[11];
    const float* c3b = (const float*)d_in[12];
    const float* dw0 = (const float*)d_in[13];
    const float* db0 = (const float*)d_in[14];
    const float* dw1 = (const float*)d_in[15];
    const float* db1 = (const float*)d_in[16];
    const float* dnw = (const float*)d_in[17];
    const float* dnb = (const float*)d_in[18];
    const float* cw0 = (const float*)d_in[19];
    const float* cb0 = (const float*)d_in[20];
    const float* cw1 = (const float*)d_in[21];
    const float* cb1 = (const float*)d_in[22];
    float* out = (float*)d_out;

    bf16 *fmap, *tri, *wf2, *wf3;
    cudaGetSymbolAddress((void**)&fmap, g_fmap_h);
    cudaGetSymbolAddress((void**)&tri, g_tri_h);
    cudaGetSymbolAddress((void**)&wf2, g_wf2h);
    cudaGetSymbolAddress((void**)&wf3, g_wf3h);

    prep_kernel<<<1, 64>>>(zs, sp, pos_w, pos_b, pe_w, pe_b);
    prep2_kernel<<<1, 576>>>(c1w, c1b);
    prep3_kernel<<<(9 * 64 * 64 + 9 * 64 * 96 + 255) / 256, 256>>>(c2w, c3w);

    const int smem2 = SIN_H * 2 + 4 * 8 * 64 * 4 + 64 * 4;
    const int smem3 = SIN_H * 2 + 4 * 12 * 64 * 4 + 96 * 4;
    cudaFuncSetAttribute((const void*)conv_tc_kernel<64, true, false>,
                         cudaFuncAttributeMaxDynamicSharedMemorySize, smem2);
    cudaFuncSetAttribute((const void*)conv_tc_kernel<96, false, true>,
                         cudaFuncAttributeMaxDynamicSharedMemorySize, smem3);

    dim3 cg(4, 32, NS);
    conv_tc_kernel<64, true, false><<<cg, 128, smem2>>>((const uint32_t*)wf2, c2b, c1b, fmap);
    conv_tc_kernel<96, false, true><<<cg, 128, smem3>>>((const uint32_t*)wf3, c3b, c1b, tri);

    cudaFuncSetAttribute(decode_kernel, cudaFuncAttributeMaxDynamicSharedMemorySize, DEC_SMEM);
    decode_kernel<<<296, 256, DEC_SMEM>>>(
        coor, sp, dw0, db0, dw1, db1, dnw, dnb, cw0, cb0, cw1, cb1, out);

    compose_kernel<<<MPTS / 256, 256>>>(out);
}

// round 9
// speedup vs baseline: 9.0894x; 1.0708x over previous
#include <cuda_runtime.h>
#include <cuda_bf16.h>
#include <math.h>
#include <stdint.h>

#define RESO 128
#define NS 8
#define MPTS 65536
#define ZD 64
#define TD 32

typedef __nv_bfloat16 bf16;
typedef __nv_bfloat162 bf162;

// ---------------- helpers ---------------------------------------------------
__device__ __forceinline__ void mma_bf16(float* c, uint32_t a0, uint32_t a1,
                                         uint32_t a2, uint32_t a3,
                                         uint32_t b0, uint32_t b1) {
    asm volatile(
        "mma.sync.aligned.m16n8k16.row.col.f32.bf16.bf16.f32 "
        "{%0,%1,%2,%3}, {%4,%5,%6,%7}, {%8,%9}, {%0,%1,%2,%3};"
        : "+f"(c[0]), "+f"(c[1]), "+f"(c[2]), "+f"(c[3])
        : "r"(a0), "r"(a1), "r"(a2), "r"(a3), "r"(b0), "r"(b1));
}
__device__ __forceinline__ uint32_t packbf(float a, float b) {
    bf162 h = __float22bfloat162_rn(make_float2(a, b));
    return *reinterpret_cast<uint32_t*>(&h);
}

// ---------------- scratch (device globals) ---------------------------------
__device__ bf16 g_fmap_h[NS * RESO * RESO * ZD];            // conv2 out, ch-last
__device__ bf16 g_tri_h[(size_t)NS * 3 * RESO * RESO * TD]; // triplane, ch-last
__device__ float g_zb[NS * ZD];
__device__ float g_A[ZD];
__device__ float g_B[ZD];
__device__ float g_Wz[NS * ZD * 9];
__device__ float g_Wa[ZD * 9];
__device__ float g_Wb[ZD * 9];
__device__ float g_K0[NS * ZD];
__device__ float g_K1[ZD];
__device__ float g_K2[ZD];
__device__ bf16 g_wf2h[9 * 4 * 8 * 128];    // conv2 w frag
__device__ bf16 g_wf3h[9 * 4 * 12 * 128];   // conv3 w frag

// ---------------- prep ------------------------------------------------------
__global__ void prep_kernel(const float* __restrict__ zs, const float* __restrict__ sp,
                            const float* __restrict__ pw, const float* __restrict__ pb,
                            const float* __restrict__ pew, const float* __restrict__ peb) {
    int c = threadIdx.x;
    if (c < ZD) {
        g_A[c] = pew[0 * ZD + c] - pew[2 * ZD + c];
        g_B[c] = pew[1 * ZD + c] - pew[3 * ZD + c];
        for (int n = 0; n < NS; n++) {
            g_zb[n * ZD + c] = zs[n * ZD + c]
                + sp[n * 3 + 0] * pw[0 * ZD + c]
                + sp[n * 3 + 1] * pw[1 * ZD + c]
                + pb[c] + peb[c];
        }
    }
}

__global__ void prep2_kernel(const float* __restrict__ w1, const float* __restrict__ b1) {
    int id = threadIdx.x;
    const float s = 2.0f / RESO;
    if (id < ZD * 9) {
        int oc = id / 9, t = id % 9;
        float wa = 0.f, wb = 0.f;
        float wz[NS];
#pragma unroll
        for (int n = 0; n < NS; n++) wz[n] = 0.f;
        for (int ic = 0; ic < ZD; ic++) {
            float w = w1[((size_t)oc * ZD + ic) * 9 + t];
            wa += w * g_A[ic];
            wb += w * g_B[ic];
#pragma unroll
            for (int n = 0; n < NS; n++) wz[n] += w * g_zb[n * ZD + ic];
        }
        g_Wa[oc * 9 + t] = wa;
        g_Wb[oc * 9 + t] = wb;
        for (int n = 0; n < NS; n++) g_Wz[(n * ZD + oc) * 9 + t] = wz[n];
    }
    __syncthreads();
    if (id < ZD) {
        int oc = id;
        float k1 = 0.f, k2 = 0.f;
        float k0[NS];
        for (int n = 0; n < NS; n++) k0[n] = b1[oc];
        for (int t = 0; t < 9; t++) {
            float dx = (float)(t % 3 - 1), dy = (float)(t / 3 - 1);
            float wa = g_Wa[oc * 9 + t], wb = g_Wb[oc * 9 + t];
            k1 += wa;
            k2 += wb;
            for (int n = 0; n < NS; n++)
                k0[n] += g_Wz[(n * ZD + oc) * 9 + t] + s * dx * wa + s * dy * wb;
        }
        g_K1[oc] = k1;
        g_K2[oc] = k2;
        for (int n = 0; n < NS; n++) g_K0[n * ZD + oc] = k0[n];
    }
}

// weights -> bf16 B-fragment layout (m16n8k16)
__global__ void prep3_kernel(const float* __restrict__ c2w, const float* __restrict__ c3w) {
    int idx = blockIdx.x * blockDim.x + threadIdx.x;
    if (idx < 9 * 64 * 64) {
        int t = idx / 4096, r2 = idx % 4096;
        int k = r2 / 64, n = r2 % 64;
        int kb = k >> 4, rr = (k >> 3) & 1, half = k & 1;
        int lane = (n & 7) * 4 + ((k & 7) >> 1), nt = n >> 3;
        int word = (t * 32 + kb * 8 + nt) * 64 + lane * 2 + rr;
        g_wf2h[word * 2 + half] = __float2bfloat16(c2w[(size_t)n * 576 + k * 9 + t]);
    } else if (idx < 9 * 64 * 64 + 9 * 64 * 96) {
        int j = idx - 9 * 64 * 64;
        int t = j / 6144, r2 = j % 6144;
        int k = r2 / 96, n = r2 % 96;
        int kb = k >> 4, rr = (k >> 3) & 1, half = k & 1;
        int lane = (n & 7) * 4 + ((k & 7) >> 1), nt = n >> 3;
        int word = (t * 48 + kb * 12 + nt) * 64 + lane * 2 + rr;
        g_wf3h[word * 2 + half] = __float2bfloat16(c3w[(size_t)n * 576 + k * 9 + t]);
    }
}

// ---------------- bf16 tensor-core implicit-GEMM 3x3 conv ------------------
// weights read straight from gmem (L1-resident) -> ONE barrier per block
#define X2 72
#define Y2 (34 * X2)
#define SIN_H (6 * Y2)   // bf16 elements

template <int NOC, bool FUSED, bool TRI>
__global__ __launch_bounds__(128, 3) void conv_tc_kernel(
    const uint2* __restrict__ wf, const float* __restrict__ bias,
    const float* __restrict__ c1b, bf16* __restrict__ outh) {
    constexpr int NT = NOC / 8;
    extern __shared__ char shraw[];
    bf16* s_in = (bf16*)shraw;
    float* s_bias = (float*)(shraw + SIN_H * 2);

    const int tid = threadIdx.x;
    const int w = tid >> 5, lane = tid & 31;
    const int x0 = blockIdx.x * 32, y0 = blockIdx.y * 4;
    const int n = blockIdx.z;

    if (tid < NOC) s_bias[tid] = bias[tid];

    const float sgrid = 2.0f / RESO;
    if (FUSED) {
        for (int idx = tid; idx < 6 * 34 * 16; idx += 128) {
            int yi = idx / (34 * 16);
            int rem = idx % (34 * 16);
            int xi = rem / 16, icq = rem % 16;
            int ic4 = icq * 4;
            int gy = y0 + yi - 1, gx = x0 + xi - 1;
            float4 v = make_float4(0.f, 0.f, 0.f, 0.f);
            if (gy >= 0 && gy < RESO && gx >= 0 && gx < RESO) {
                float X = (2 * gx - 127) * (1.0f / RESO);
                float Y = (2 * gy - 127) * (1.0f / RESO);
                if (gx >= 1 && gx <= 126 && gy >= 1 && gy <= 126) {
                    float4 k0 = *(const float4*)&g_K0[n * ZD + ic4];
                    float4 k1 = *(const float4*)&g_K1[ic4];
                    float4 k2 = *(const float4*)&g_K2[ic4];
                    v.x = fmaxf(k0.x + k1.x * X + k2.x * Y, 0.f);
                    v.y = fmaxf(k0.y + k1.y * X + k2.y * Y, 0.f);
                    v.z = fmaxf(k0.z + k1.z * X + k2.z * Y, 0.f);
                    v.w = fmaxf(k0.w + k1.w * X + k2.w * Y, 0.f);
                } else {
                    float vv[4];
#pragma unroll
                    for (int c = 0; c < 4; c++) {
                        int ic = ic4 + c;
                        float val = c1b[ic];
#pragma unroll
                        for (int t9 = 0; t9 < 9; t9++) {
                            int dyb = t9 / 3 - 1, dxb = t9 % 3 - 1;
                            int gy2 = gy + dyb, gx2 = gx + dxb;
                            if (gy2 >= 0 && gy2 < RESO && gx2 >= 0 && gx2 < RESO)
                                val += g_Wz[((size_t)n * ZD + ic) * 9 + t9]
                                     + g_Wa[ic * 9 + t9] * (X + dxb * sgrid)
                                     + g_Wb[ic * 9 + t9] * (Y + dyb * sgrid);
                        }
                        vv[c] = fmaxf(val, 0.f);
                    }
                    v = make_float4(vv[0], vv[1], vv[2], vv[3]);
                }
            }
            uint2 pk;
            pk.x = packbf(v.x, v.y);
            pk.y = packbf(v.z, v.w);
            *(uint2*)&s_in[yi * Y2 + xi * X2 + ic4] = pk;
        }
    } else {
        for (int idx = tid; idx < 6 * 34 * 8; idx += 128) {
            int yi = idx / (34 * 8);
            int rem = idx % (34 * 8);
            int xi = rem / 8, ic8 = (rem % 8) * 8;
            int gy = y0 + yi - 1, gx = x0 + xi - 1;
            uint4 v = make_uint4(0u, 0u, 0u, 0u);
            if (gy >= 0 && gy < RESO && gx >= 0 && gx < RESO)
                v = *(const uint4*)&g_fmap_h[(((size_t)n * RESO + gy) * RESO + gx) * ZD + ic8];
            *(uint4*)&s_in[yi * Y2 + xi * X2 + ic8] = v;
        }
    }
    __syncthreads();   // the ONLY block barrier

    float acc[2][NT][4];
#pragma unroll
    for (int mt = 0; mt < 2; mt++)
#pragma unroll
        for (int nt = 0; nt < NT; nt++)
#pragma unroll
            for (int j = 0; j < 4; j++) acc[mt][nt][j] = 0.f;

    const int q = lane & 3, hr = lane >> 2;

#pragma unroll 1
    for (int tt = 0; tt < 9; tt++) {
        int dy = tt / 3, dx = tt % 3;
#pragma unroll
        for (int kb = 0; kb < 4; kb++) {
            uint2 bb[NT];
#pragma unroll
            for (int nt = 0; nt < NT; nt++)
                bb[nt] = __ldg(&wf[((tt * 4 + kb) * NT + nt) * 32 + lane]);
#pragma unroll
            for (int mt = 0; mt < 2; mt++) {
                const bf16* ap = s_in + (w + dy) * Y2 + (mt * 16 + hr + dx) * X2 + kb * 16;
                uint32_t a0 = *(const uint32_t*)&ap[2 * q];
                uint32_t a1 = *(const uint32_t*)&ap[8 * X2 + 2 * q];
                uint32_t a2 = *(const uint32_t*)&ap[2 * q + 8];
                uint32_t a3 = *(const uint32_t*)&ap[8 * X2 + 2 * q + 8];
#pragma unroll
                for (int nt = 0; nt < NT; nt++)
                    mma_bf16(acc[mt][nt], a0, a1, a2, a3, bb[nt].x, bb[nt].y);
            }
        }
    }

    // ---- epilogue ----
    const int y = y0 + w;
#pragma unroll
    for (int mt = 0; mt < 2; mt++) {
        int xa = x0 + mt * 16 + hr;
#pragma unroll
        for (int nt = 0; nt < NT; nt++) {
            int col = nt * 8 + 2 * q;
            float bv0 = s_bias[col], bv1 = s_bias[col + 1];
            float v0 = acc[mt][nt][0] + bv0, v1 = acc[mt][nt][1] + bv1;
            float v2 = acc[mt][nt][2] + bv0, v3 = acc[mt][nt][3] + bv1;
            if (!TRI) {
                v0 = fmaxf(v0, 0.f); v1 = fmaxf(v1, 0.f);
                v2 = fmaxf(v2, 0.f); v3 = fmaxf(v3, 0.f);
                *(uint32_t*)&outh[(((size_t)n * RESO + y) * RESO + xa) * ZD + col] = packbf(v0, v1);
                *(uint32_t*)&outh[(((size_t)n * RESO + y) * RESO + xa + 8) * ZD + col] = packbf(v2, v3);
            } else {
                int plane = col >> 5, c = col & 31;
                size_t pb = (((size_t)n * 3 + plane) * RESO * RESO);
                *(uint32_t*)&outh[(pb + (size_t)y * RESO + xa) * TD + c] = packbf(v0, v1);
                *(uint32_t*)&outh[(pb + (size_t)y * RESO + xa + 8) * TD + c] = packbf(v2, v3);
            }
        }
    }
}

// ---------------- bf16 decoder + fused composition -------------------------
// Tile = 32 points x 8 slots (warp = slot). M=256 rows, warp-local MMA rows.
#define AST2 104
#define D_SA    0
#define D_B0    53248
#define D_B1    71680
#define D_B2    90112
#define D_BI0   96256
#define D_BI1   96640
#define D_BI2   97024
#define D_CW1   97152
#define D_CB1   97440
#define D_UM    97456
#define DEC_SMEM (97456 + 4096)
#define DTILES (MPTS / 32)

template <int NT, bool RELU>
__device__ __forceinline__ void mlp_layer(bf16* sA, const uint32_t* sB,
                                          const float* sbias, int rowbase, int lane) {
    const int g = lane >> 2, q = lane & 3;
    const int cl = 2 * q;
    float acc[2][NT][4];
#pragma unroll
    for (int nt = 0; nt < NT; nt++) {
        float bv0 = sbias[nt * 8 + cl], bv1 = sbias[nt * 8 + cl + 1];
#pragma unroll
        for (int mt = 0; mt < 2; mt++) {
            acc[mt][nt][0] = bv0; acc[mt][nt][1] = bv1;
            acc[mt][nt][2] = bv0; acc[mt][nt][3] = bv1;
        }
    }
#pragma unroll
    for (int kb = 0; kb < 6; kb++) {
        uint2 bb[NT];
#pragma unroll
        for (int nt = 0; nt < NT; nt++)
            bb[nt] = *(const uint2*)&sB[(kb * NT + nt) * 64 + lane * 2];
#pragma unroll
        for (int mt = 0; mt < 2; mt++) {
            const bf16* ap = sA + (rowbase + mt * 16 + g) * AST2 + kb * 16;
            uint32_t a0 = *(const uint32_t*)&ap[2 * q];
            uint32_t a1 = *(const uint32_t*)&ap[8 * AST2 + 2 * q];
            uint32_t a2 = *(const uint32_t*)&ap[2 * q + 8];
            uint32_t a3 = *(const uint32_t*)&ap[8 * AST2 + 2 * q + 8];
#pragma unroll
            for (int nt = 0; nt < NT; nt++)
                mma_bf16(acc[mt][nt], a0, a1, a2, a3, bb[nt].x, bb[nt].y);
        }
    }
#pragma unroll
    for (int mt = 0; mt < 2; mt++) {
        int r0 = rowbase + mt * 16 + g;
#pragma unroll
        for (int nt = 0; nt < NT; nt++) {
            int col = nt * 8 + cl;
            float a0 = acc[mt][nt][0], a1 = acc[mt][nt][1];
            float a2 = acc[mt][nt][2], a3 = acc[mt][nt][3];
            if (RELU) {
                a0 = fmaxf(a0, 0.f); a1 = fmaxf(a1, 0.f);
                a2 = fmaxf(a2, 0.f); a3 = fmaxf(a3, 0.f);
            }
            *(uint32_t*)&sA[r0 * AST2 + col] = packbf(a0, a1);
            *(uint32_t*)&sA[(r0 + 8) * AST2 + col] = packbf(a2, a3);
        }
    }
}

__global__ __launch_bounds__(256, 2) void decode_kernel(
    const float* __restrict__ coor, const float* __restrict__ spos,
    const float* __restrict__ w0, const float* __restrict__ b0,
    const float* __restrict__ w1, const float* __restrict__ b1,
    const float* __restrict__ dw, const float* __restrict__ db,
    const float* __restrict__ cw0, const float* __restrict__ cb0,
    const float* __restrict__ cw1, const float* __restrict__ cb1,
    float* __restrict__ out) {
    extern __shared__ char smraw[];
    bf16* sA = (bf16*)(smraw + D_SA);
    uint32_t* sB0 = (uint32_t*)(smraw + D_B0);
    uint32_t* sB1 = (uint32_t*)(smraw + D_B1);
    uint32_t* sB2 = (uint32_t*)(smraw + D_B2);
    float* sbi0 = (float*)(smraw + D_BI0);
    float* sbi1 = (float*)(smraw + D_BI1);
    float* sbi2 = (float*)(smraw + D_BI2);
    float* scw1 = (float*)(smraw + D_CW1);
    float* scb1 = (float*)(smraw + D_CB1);
    float4* s_um = (float4*)(smraw + D_UM);

    int tid = threadIdx.x;
    int wid = tid >> 5, lane = tid & 31;

    for (int idx = tid; idx < 96 * 96; idx += 256) {
        int k = idx / 96, n = idx % 96;
        int kb = k >> 4, rr = (k >> 3) & 1, half = k & 1;
        int lane2 = (n & 7) * 4 + ((k & 7) >> 1), nt = n >> 3;
        int hoff = ((kb * 12 + nt) * 64 + lane2 * 2 + rr) * 2 + half;
        ((bf16*)sB0)[hoff] = __float2bfloat16(w0[idx]);
        ((bf16*)sB1)[hoff] = __float2bfloat16(w1[idx]);
    }
    for (int idx = tid; idx < 96 * 32; idx += 256) {
        int k = idx / 32, n = idx % 32;
        float v = (n == 0) ? dw[k] : ((n <= 24) ? cw0[k * 24 + n - 1] : 0.f);
        int kb = k >> 4, rr = (k >> 3) & 1, half = k & 1;
        int lane2 = (n & 7) * 4 + ((k & 7) >> 1), nt = n >> 3;
        int hoff = ((kb * 4 + nt) * 64 + lane2 * 2 + rr) * 2 + half;
        ((bf16*)sB2)[hoff] = __float2bfloat16(v);
    }
    if (tid < 96) { sbi0[tid] = b0[tid]; sbi1[tid] = b1[tid]; }
    if (tid < 32) sbi2[tid] = (tid == 0) ? db[0] : ((tid <= 24) ? cb0[tid - 1] : 0.f);
    if (tid < 72) scw1[tid] = cw1[tid];
    if (tid < 3) scb1[tid] = cb1[tid];
    __syncthreads();

    const int rowbase = wid * 32;
    const int myrow = rowbase + lane;
    const int n = wid;   // slot owned by this warp
    const size_t B1o = (size_t)MPTS * 4;
    const size_t B2o = B1o + (size_t)NS * MPTS * 4;
    const size_t B3o = B2o + (size_t)NS * MPTS * 4;
    float sx = spos[n * 3 + 0], sy = spos[n * 3 + 1], sz = spos[n * 3 + 2];

    for (int t = blockIdx.x; t < DTILES; t += gridDim.x) {
        int m = (t << 5) + lane;

        float rx = coor[((size_t)n * MPTS + m) * 3 + 0] - sx;
        float ry = coor[((size_t)n * MPTS + m) * 3 + 1] - sy;
        float rz = coor[((size_t)n * MPTS + m) * 3 + 2] - sz;
        bool outsider = (fabsf(rx) > 1.f || fabsf(ry) > 1.f || fabsf(rz) > 1.f);

#pragma unroll
        for (int p = 0; p < 3; p++) {
            float cu, cv;
            if (p == 0) { cu = rx; cv = ry; }
            else if (p == 1) { cu = rx; cv = rz; }
            else { cu = rz; cv = rx; }
            float u = (cu + 1.f) * 64.f - 0.5f;
            float v = (cv + 1.f) * 64.f - 0.5f;
            float fx = floorf(u), fy = floorf(v);
            float wx = u - fx, wy = v - fy;
            int ix0 = (int)fx, iy0 = (int)fy;
            float wts[4] = {(1 - wx) * (1 - wy), wx * (1 - wy), (1 - wx) * wy, wx * wy};
            int xs[4] = {ix0, ix0 + 1, ix0, ix0 + 1};
            int ys[4] = {iy0, iy0, iy0 + 1, iy0 + 1};
            bf162 hacc[16];
#pragma unroll
            for (int k = 0; k < 16; k++) hacc[k] = __float2bfloat162_rn(0.f);
            size_t pb = ((size_t)n * 3 + p) * RESO * RESO;
#pragma unroll
            for (int tt = 0; tt < 4; tt++) {
                if (xs[tt] >= 0 && xs[tt] < RESO && ys[tt] >= 0 && ys[tt] < RESO) {
                    const uint4* tq = (const uint4*)&g_tri_h[(pb + (size_t)ys[tt] * RESO + xs[tt]) * TD];
                    bf162 w2 = __float2bfloat162_rn(wts[tt]);
#pragma unroll
                    for (int j = 0; j < 4; j++) {
                        uint4 qv = tq[j];
                        hacc[j * 4 + 0] = __hfma2(*(bf162*)&qv.x, w2, hacc[j * 4 + 0]);
                        hacc[j * 4 + 1] = __hfma2(*(bf162*)&qv.y, w2, hacc[j * 4 + 1]);
                        hacc[j * 4 + 2] = __hfma2(*(bf162*)&qv.z, w2, hacc[j * 4 + 2]);
                        hacc[j * 4 + 3] = __hfma2(*(bf162*)&qv.w, w2, hacc[j * 4 + 3]);
                    }
                }
            }
            uint4* dst = (uint4*)&sA[myrow * AST2 + p * 32];
#pragma unroll
            for (int j = 0; j < 4; j++) {
                uint4 o;
                o.x = *(uint32_t*)&hacc[j * 4 + 0];
                o.y = *(uint32_t*)&hacc[j * 4 + 1];
                o.z = *(uint32_t*)&hacc[j * 4 + 2];
                o.w = *(uint32_t*)&hacc[j * 4 + 3];
                dst[j] = o;
            }
        }
        __syncwarp();

        mlp_layer<12, true>(sA, sB0, sbi0, rowbase, lane);
        __syncwarp();
        mlp_layer<12, true>(sA, sB1, sbi1, rowbase, lane);
        __syncwarp();
        mlp_layer<4, false>(sA, sB2, sbi2, rowbase, lane);
        __syncwarp();

        // ---- unmasked raw for own (slot, point) ----
        float4 um;
        {
            const bf16* vh = &sA[myrow * AST2];
            float vv[26];
#pragma unroll
            for (int i = 0; i < 13; i++) {
                float2 f2 = __bfloat1622float2(*(const bf162*)&vh[2 * i]);
                vv[2 * i] = f2.x;
                vv[2 * i + 1] = f2.y;
            }
            float dens = vv[0];
            float c0 = scb1[0], c1 = scb1[1], c2 = scb1[2];
#pragma unroll
            for (int j = 0; j < 24; j++) {
                float h = fmaxf(vv[1 + j], 0.f);
                c0 += h * scw1[j * 3 + 0];
                c1 += h * scw1[j * 3 + 1];
                c2 += h * scw1[j * 3 + 2];
            }
            float rawmask = outsider ? 0.f : fmaxf(dens, 0.f);
            um = make_float4((tanhf(c0) + 1.f) * 0.5f, (tanhf(c1) + 1.f) * 0.5f,
                             (tanhf(c2) + 1.f) * 0.5f, rawmask);
        }
        s_um[myrow] = um;
        __syncthreads();

        // ---- fused composition ----
        float denom = 1e-8f;
#pragma unroll
        for (int k = 0; k < NS; k++) denom += s_um[k * 32 + lane].w;
        float mk = um.w / denom;
        size_t po = (size_t)n * MPTS + m;
        *(float4*)&out[B2o + po * 4] = um;
        *(float4*)&out[B1o + po * 4] = make_float4(um.x * mk, um.y * mk, um.z * mk, um.w * mk);
        out[B3o + po] = mk;
        if (wid == 0) {
            float4 rr = make_float4(0.f, 0.f, 0.f, 0.f);
#pragma unroll
            for (int k = 0; k < NS; k++) {
                float4 u4 = s_um[k * 32 + lane];
                float mkk = u4.w / denom;
                rr.x += u4.x * mkk; rr.y += u4.y * mkk;
                rr.z += u4.z * mkk; rr.w += u4.w * mkk;
            }
            *(float4*)&out[(size_t)m * 4] = rr;
        }
        __syncthreads();
    }
}

// ---------------- launch ----------------------------------------------------
extern "C" void kernel_launch(void* const* d_in, const int* in_sizes, int n_in,
                              void* d_out, int out_size) {
    const float* coor = (const float*)d_in[0];
    const float* zs   = (const float*)d_in[1];
    const float* sp   = (const float*)d_in[2];
    const float* pos_w = (const float*)d_in[3];
    const float* pos_b = (const float*)d_in[4];
    const float* pe_w  = (const float*)d_in[5];
    const float* pe_b  = (const float*)d_in[6];
    const float* c1w = (const float*)d_in[7];
    const float* c1b = (const float*)d_in[8];
    const float* c2w = (const float*)d_in[9];
    const float* c2b = (const float*)d_in[10];
    const float* c3w = (const float*)d_in[11];
    const float* c3b = (const float*)d_in[12];
    const float* dw0 = (const float*)d_in[13];
    const float* db0 = (const float*)d_in[14];
    const float* dw1 = (const float*)d_in[15];
    const float* db1 = (const float*)d_in[16];
    const float* dnw = (const float*)d_in[17];
    const float* dnb = (const float*)d_in[18];
    const float* cw0 = (const float*)d_in[19];
    const float* cb0 = (const float*)d_in[20];
    const float* cw1 = (const float*)d_in[21];
    const float* cb1 = (const float*)d_in[22];
    float* out = (float*)d_out;

    bf16 *fmap, *tri, *wf2, *wf3;
    cudaGetSymbolAddress((void**)&fmap, g_fmap_h);
    cudaGetSymbolAddress((void**)&tri, g_tri_h);
    cudaGetSymbolAddress((void**)&wf2, g_wf2h);
    cudaGetSymbolAddress((void**)&wf3, g_wf3h);

    prep_kernel<<<1, 64>>>(zs, sp, pos_w, pos_b, pe_w, pe_b);
    prep2_kernel<<<1, 576>>>(c1w, c1b);
    prep3_kernel<<<(9 * 64 * 64 + 9 * 64 * 96 + 255) / 256, 256>>>(c2w, c3w);

    const int smem2 = SIN_H * 2 + 64 * 4;
    const int smem3 = SIN_H * 2 + 96 * 4;
    cudaFuncSetAttribute((const void*)conv_tc_kernel<64, true, false>,
                         cudaFuncAttributeMaxDynamicSharedMemorySize, smem2);
    cudaFuncSetAttribute((const void*)conv_tc_kernel<96, false, true>,
                         cudaFuncAttributeMaxDynamicSharedMemorySize, smem3);

    dim3 cg(4, 32, NS);
    conv_tc_kernel<64, true, false><<<cg, 128, smem2>>>((const uint2*)wf2, c2b, c1b, fmap);
    conv_tc_kernel<96, false, true><<<cg, 128, smem3>>>((const uint2*)wf3, c3b, c1b, tri);

    cudaFuncSetAttribute(decode_kernel, cudaFuncAttributeMaxDynamicSharedMemorySize, DEC_SMEM);
    decode_kernel<<<296, 256, DEC_SMEM>>>(
        coor, sp, dw0, db0, dw1, db1, dnw, dnb, cw0, cb0, cw1, cb1, out);
}